// round 1
// baseline (speedup 1.0000x reference)
#include <cuda_runtime.h>

// Problem constants
#define BATCH 4
#define SEQ   1024
#define NT    4096      // tokens = BATCH*SEQ
#define DM    1024      // d_model
#define NH    16        // heads
#define DK    64        // head dim
#define DFF   4096      // ffn dim

// ---------------- scratch (device globals; no allocations) ----------------
__device__ float g_Q[(size_t)NT * DM];
__device__ float g_K[(size_t)NT * DM];
__device__ float g_V[(size_t)NT * DM];
__device__ float g_scores[(size_t)BATCH * NH * SEQ * SEQ];   // 256 MB
__device__ float g_ctx[(size_t)NT * DM];
__device__ float g_tmp[(size_t)NT * DM];
__device__ float g_h[(size_t)NT * DM];
__device__ float g_ff[(size_t)NT * DFF];

// ---------------- generic batched-stride tiled SGEMM ----------------
// C[M,N] = alpha * A@B (+bias) (optional relu), row-major, exact tiling assumed:
// M % BMv == 0, N % BNv == 0, K % 16 == 0. TRANSB: B is [N,K] (computes A@B^T).
// Batch decomposition: z = zb*nH + zh; per-operand offsets zb*s?b + zh*s?h.
template<int BMv, int BNv, int TMv, int TNv, bool TRANSB, bool RELU>
__global__ __launch_bounds__(256, 2)
void gemm_k(const float* __restrict__ A, const float* __restrict__ B,
            const float* __restrict__ bias, float* __restrict__ C,
            int M, int N, int K, int lda, int ldb, int ldc,
            long long sAb, long long sAh, long long sBb, long long sBh,
            long long sCb, long long sCh, int nH, float alpha)
{
    constexpr int BKK = 16;
    const int z  = blockIdx.z;
    const int zb = z / nH;
    const int zh = z - zb * nH;
    A += zb * sAb + zh * sAh;
    B += zb * sBb + zh * sBh;
    C += zb * sCb + zh * sCh;

    __shared__ __align__(16) float As[BKK][BMv + 4];
    __shared__ __align__(16) float Bs[BKK][BNv + 4];

    const int tid  = threadIdx.x;          // 256 threads
    const int tx   = tid & 15;
    const int ty   = tid >> 4;
    const int row0 = blockIdx.y * BMv;
    const int col0 = blockIdx.x * BNv;

    float acc[TMv][TNv];
#pragma unroll
    for (int i = 0; i < TMv; i++)
#pragma unroll
        for (int j = 0; j < TNv; j++) acc[i][j] = 0.f;

    for (int k0 = 0; k0 < K; k0 += BKK) {
        // ---- load A tile [BMv x 16], store transposed into As[k][m] ----
#pragma unroll
        for (int it = 0; it < BMv / 64; it++) {
            int idx = tid + it * 256;           // float4 index
            int r   = idx >> 2;                 // 0..BMv-1
            int c4  = idx & 3;                  // 0..3
            float4 v = *(const float4*)(A + (long long)(row0 + r) * lda + k0 + c4 * 4);
            As[c4 * 4 + 0][r] = v.x;
            As[c4 * 4 + 1][r] = v.y;
            As[c4 * 4 + 2][r] = v.z;
            As[c4 * 4 + 3][r] = v.w;
        }
        // ---- load B tile ----
        if (TRANSB) {
            // B is [N,K]; tile [BNv x 16] -> Bs[k][n]
#pragma unroll
            for (int it = 0; it < BNv / 64; it++) {
                int idx = tid + it * 256;
                int r   = idx >> 2;
                int c4  = idx & 3;
                float4 v = *(const float4*)(B + (long long)(col0 + r) * ldb + k0 + c4 * 4);
                Bs[c4 * 4 + 0][r] = v.x;
                Bs[c4 * 4 + 1][r] = v.y;
                Bs[c4 * 4 + 2][r] = v.z;
                Bs[c4 * 4 + 3][r] = v.w;
            }
        } else {
            // B is [K,N]; tile [16 x BNv] -> Bs[k][n]
#pragma unroll
            for (int it = 0; it < BNv / 64; it++) {
                int idx = tid + it * 256;
                int r   = idx / (BNv / 4);
                int c4  = idx % (BNv / 4);
                float4 v = *(const float4*)(B + (long long)(k0 + r) * ldb + col0 + c4 * 4);
                *(float4*)&Bs[r][c4 * 4] = v;
            }
        }
        __syncthreads();

#pragma unroll
        for (int k = 0; k < BKK; k++) {
            float a[TMv], b[TNv];
#pragma unroll
            for (int i = 0; i < TMv / 4; i++)
                *(float4*)&a[i * 4] = *(const float4*)&As[k][ty * TMv + i * 4];
#pragma unroll
            for (int j = 0; j < TNv / 4; j++)
                *(float4*)&b[j * 4] = *(const float4*)&Bs[k][tx * TNv + j * 4];
#pragma unroll
            for (int i = 0; i < TMv; i++)
#pragma unroll
                for (int j = 0; j < TNv; j++)
                    acc[i][j] = fmaf(a[i], b[j], acc[i][j]);
        }
        __syncthreads();
    }

    // ---- epilogue ----
#pragma unroll
    for (int i = 0; i < TMv; i++) {
        long long rr = row0 + ty * TMv + i;
#pragma unroll
        for (int j4 = 0; j4 < TNv / 4; j4++) {
            int cc = col0 + tx * TNv + j4 * 4;
            float4 o;
            o.x = acc[i][j4 * 4 + 0] * alpha;
            o.y = acc[i][j4 * 4 + 1] * alpha;
            o.z = acc[i][j4 * 4 + 2] * alpha;
            o.w = acc[i][j4 * 4 + 3] * alpha;
            if (bias) {
                o.x += bias[cc + 0];
                o.y += bias[cc + 1];
                o.z += bias[cc + 2];
                o.w += bias[cc + 3];
            }
            if (RELU) {
                o.x = fmaxf(o.x, 0.f);
                o.y = fmaxf(o.y, 0.f);
                o.z = fmaxf(o.z, 0.f);
                o.w = fmaxf(o.w, 0.f);
            }
            *(float4*)(C + rr * ldc + cc) = o;
        }
    }
}

// ---------------- block reductions ----------------
__device__ __forceinline__ float blockReduceSum(float v, float* red)
{
#pragma unroll
    for (int o = 16; o > 0; o >>= 1) v += __shfl_xor_sync(0xffffffffu, v, o);
    int warp = threadIdx.x >> 5, lane = threadIdx.x & 31;
    if (lane == 0) red[warp] = v;
    __syncthreads();
    if (threadIdx.x < 8) {
        v = red[threadIdx.x];
#pragma unroll
        for (int o = 4; o > 0; o >>= 1) v += __shfl_xor_sync(0xffu, v, o);
        if (threadIdx.x == 0) red[0] = v;
    }
    __syncthreads();
    float r = red[0];
    __syncthreads();
    return r;
}

__device__ __forceinline__ float blockReduceMax(float v, float* red)
{
#pragma unroll
    for (int o = 16; o > 0; o >>= 1) v = fmaxf(v, __shfl_xor_sync(0xffffffffu, v, o));
    int warp = threadIdx.x >> 5, lane = threadIdx.x & 31;
    if (lane == 0) red[warp] = v;
    __syncthreads();
    if (threadIdx.x < 8) {
        v = red[threadIdx.x];
#pragma unroll
        for (int o = 4; o > 0; o >>= 1) v = fmaxf(v, __shfl_xor_sync(0xffu, v, o));
        if (threadIdx.x == 0) red[0] = v;
    }
    __syncthreads();
    float r = red[0];
    __syncthreads();
    return r;
}

// ---------------- masked softmax over score rows (in place) ----------------
// grid: (SEQ, BATCH*NH), block: 256
__global__ void softmax_k(float* __restrict__ scores, const int* __restrict__ mask)
{
    __shared__ float red[32];
    const int row = blockIdx.x;
    const int z   = blockIdx.y;         // b*NH + h
    const int b   = z >> 4;             // NH = 16
    float* p = scores + ((long long)z * SEQ + row) * SEQ;
    const int* m = mask + (long long)b * SEQ;
    const int tid = threadIdx.x;

    float v[4];
    float mx = -1e30f;
#pragma unroll
    for (int j = 0; j < 4; j++) {
        int c = tid + j * 256;
        float val = p[c];
        if (m[c] == 0) val = -1e9f;
        v[j] = val;
        mx = fmaxf(mx, val);
    }
    mx = blockReduceMax(mx, red);

    float s = 0.f;
#pragma unroll
    for (int j = 0; j < 4; j++) {
        v[j] = __expf(v[j] - mx);
        s += v[j];
    }
    s = blockReduceSum(s, red);
    float inv = 1.f / s;
#pragma unroll
    for (int j = 0; j < 4; j++)
        p[tid + j * 256] = v[j] * inv;
}

// ---------------- residual add + LayerNorm ----------------
// out[row] = LN(a[row] + b[row]) * g + be     grid: NT blocks, 256 threads
__global__ void addln_k(const float* __restrict__ a, const float* __restrict__ bres,
                        const float* __restrict__ g, const float* __restrict__ be,
                        float* __restrict__ out)
{
    __shared__ float red[32];
    const long long row = blockIdx.x;
    const float* pa = a    + row * DM;
    const float* pb = bres + row * DM;
    float*       po = out  + row * DM;
    const int tid = threadIdx.x;

    float v[4];
    float s = 0.f, s2 = 0.f;
#pragma unroll
    for (int j = 0; j < 4; j++) {
        int c = tid + j * 256;
        float t = pa[c] + pb[c];
        v[j] = t;
        s  += t;
        s2 += t * t;
    }
    s  = blockReduceSum(s, red);
    s2 = blockReduceSum(s2, red);
    float mu  = s * (1.f / DM);
    float var = s2 * (1.f / DM) - mu * mu;
    float inv = rsqrtf(var + 1e-5f);
#pragma unroll
    for (int j = 0; j < 4; j++) {
        int c = tid + j * 256;
        po[c] = (v[j] - mu) * inv * g[c] + be[c];
    }
}

// ---------------- launch ----------------
extern "C" void kernel_launch(void* const* d_in, const int* in_sizes, int n_in,
                              void* d_out, int out_size)
{
    const float* x    = (const float*)d_in[0];
    const int*   mask = (const int*)  d_in[1];
    const float* Wq   = (const float*)d_in[2];
    const float* bq   = (const float*)d_in[3];
    const float* Wk   = (const float*)d_in[4];
    const float* bk   = (const float*)d_in[5];
    const float* Wv   = (const float*)d_in[6];
    const float* bv   = (const float*)d_in[7];
    const float* Wo   = (const float*)d_in[8];
    const float* bo   = (const float*)d_in[9];
    const float* W1   = (const float*)d_in[10];
    const float* b1   = (const float*)d_in[11];
    const float* W2   = (const float*)d_in[12];
    const float* b2   = (const float*)d_in[13];
    const float* g1   = (const float*)d_in[14];
    const float* be1  = (const float*)d_in[15];
    const float* g2   = (const float*)d_in[16];
    const float* be2  = (const float*)d_in[17];
    float* out = (float*)d_out;

    float *Q, *Kp, *V, *SC, *CT, *TMP, *Hh, *FF;
    cudaGetSymbolAddress((void**)&Q,   g_Q);
    cudaGetSymbolAddress((void**)&Kp,  g_K);
    cudaGetSymbolAddress((void**)&V,   g_V);
    cudaGetSymbolAddress((void**)&SC,  g_scores);
    cudaGetSymbolAddress((void**)&CT,  g_ctx);
    cudaGetSymbolAddress((void**)&TMP, g_tmp);
    cudaGetSymbolAddress((void**)&Hh,  g_h);
    cudaGetSymbolAddress((void**)&FF,  g_ff);

    const dim3 blk(256);
    const long long SD  = (long long)SEQ * DM;       // per-batch token stride
    const long long SS  = (long long)SEQ * SEQ;      // per-head score stride

    // 1) QKV projections: [NT,DM] @ [DM,DM]
    {
        dim3 g(DM / 128, NT / 128, 1);
        gemm_k<128,128,8,8,false,false><<<g, blk>>>(x, Wq, bq, Q,  NT, DM, DM, DM, DM, DM, 0,0,0,0,0,0, 1, 1.f);
        gemm_k<128,128,8,8,false,false><<<g, blk>>>(x, Wk, bk, Kp, NT, DM, DM, DM, DM, DM, 0,0,0,0,0,0, 1, 1.f);
        gemm_k<128,128,8,8,false,false><<<g, blk>>>(x, Wv, bv, V,  NT, DM, DM, DM, DM, DM, 0,0,0,0,0,0, 1, 1.f);
    }

    // 2) scores = (Q @ K^T) / 8 per (b,h):  [SEQ,DK] @ [SEQ,DK]^T
    {
        dim3 g(SEQ / 128, SEQ / 128, BATCH * NH);
        gemm_k<128,128,8,8,true,false><<<g, blk>>>(Q, Kp, nullptr, SC,
            SEQ, SEQ, DK, DM, DM, SEQ,
            SD, DK, SD, DK, (long long)NH * SS, SS, NH, 0.125f);
    }

    // 3) masked softmax
    {
        dim3 g(SEQ, BATCH * NH);
        softmax_k<<<g, 256>>>(SC, mask);
    }

    // 4) ctx = attn @ V per (b,h): [SEQ,SEQ] @ [SEQ,DK]
    {
        dim3 g(DK / 64, SEQ / 64, BATCH * NH);
        gemm_k<64,64,4,4,false,false><<<g, blk>>>(SC, V, nullptr, CT,
            SEQ, DK, SEQ, SEQ, DM, DM,
            (long long)NH * SS, SS, SD, DK, SD, DK, NH, 1.f);
    }

    // 5) attn_out = ctx @ Wo + bo
    {
        dim3 g(DM / 128, NT / 128, 1);
        gemm_k<128,128,8,8,false,false><<<g, blk>>>(CT, Wo, bo, TMP, NT, DM, DM, DM, DM, DM, 0,0,0,0,0,0, 1, 1.f);
    }

    // 6) h = LN1(x + attn_out)
    addln_k<<<NT, 256>>>(x, TMP, g1, be1, Hh);

    // 7) ff = relu(h @ W1 + b1)
    {
        dim3 g(DFF / 128, NT / 128, 1);
        gemm_k<128,128,8,8,false,true><<<g, blk>>>(Hh, W1, b1, FF, NT, DFF, DM, DM, DFF, DFF, 0,0,0,0,0,0, 1, 1.f);
    }

    // 8) tmp = ff @ W2 + b2
    {
        dim3 g(DM / 128, NT / 128, 1);
        gemm_k<128,128,8,8,false,false><<<g, blk>>>(FF, W2, b2, TMP, NT, DM, DFF, DFF, DM, DM, 0,0,0,0,0,0, 1, 1.f);
    }

    // 9) out = LN2(h + tmp)
    addln_k<<<NT, 256>>>(Hh, TMP, g2, be2, out);
}

// round 2
// speedup vs baseline: 1.0023x; 1.0023x over previous
#include <cuda_runtime.h>

// Problem constants
#define BATCH 4
#define SEQ   1024
#define NT    4096      // tokens = BATCH*SEQ
#define DM    1024      // d_model
#define NH    16        // heads
#define DK    64        // head dim
#define DFF   4096      // ffn dim

// ---------------- scratch (device globals; no allocations) ----------------
__device__ float g_Q[(size_t)NT * DM];
__device__ float g_K[(size_t)NT * DM];
__device__ float g_V[(size_t)NT * DM];
__device__ float g_scores[(size_t)BATCH * NH * SEQ * SEQ];   // 256 MB
__device__ float g_ctx[(size_t)NT * DM];
__device__ float g_tmp[(size_t)NT * DM];
__device__ float g_h[(size_t)NT * DM];
__device__ float g_ff[(size_t)NT * DFF];

// ---------------- generic batched-stride tiled SGEMM ----------------
// C[M,N] = alpha * A@B (+bias) (optional relu), row-major, exact tiling assumed:
// M % BMv == 0, N % BNv == 0, K % 16 == 0. TRANSB: B is [N,K] (computes A@B^T).
// Batch decomposition: z = zb*nH + zh; per-operand offsets zb*s?b + zh*s?h.
template<int BMv, int BNv, int TMv, int TNv, bool TRANSB, bool RELU>
__global__ __launch_bounds__(256, 2)
void gemm_k(const float* __restrict__ A, const float* __restrict__ B,
            const float* __restrict__ bias, float* __restrict__ C,
            int M, int N, int K, int lda, int ldb, int ldc,
            long long sAb, long long sAh, long long sBb, long long sBh,
            long long sCb, long long sCh, int nH, float alpha)
{
    constexpr int BKK = 16;
    const int z  = blockIdx.z;
    const int zb = z / nH;
    const int zh = z - zb * nH;
    A += zb * sAb + zh * sAh;
    B += zb * sBb + zh * sBh;
    C += zb * sCb + zh * sCh;

    __shared__ __align__(16) float As[BKK][BMv + 4];
    __shared__ __align__(16) float Bs[BKK][BNv + 4];

    const int tid  = threadIdx.x;          // 256 threads
    const int tx   = tid & 15;
    const int ty   = tid >> 4;
    const int row0 = blockIdx.y * BMv;
    const int col0 = blockIdx.x * BNv;

    float acc[TMv][TNv];
#pragma unroll
    for (int i = 0; i < TMv; i++)
#pragma unroll
        for (int j = 0; j < TNv; j++) acc[i][j] = 0.f;

    for (int k0 = 0; k0 < K; k0 += BKK) {
        // ---- load A tile [BMv x 16], store transposed into As[k][m] ----
#pragma unroll
        for (int it = 0; it < BMv / 64; it++) {
            int idx = tid + it * 256;           // float4 index
            int r   = idx >> 2;                 // 0..BMv-1
            int c4  = idx & 3;                  // 0..3
            float4 v = *(const float4*)(A + (long long)(row0 + r) * lda + k0 + c4 * 4);
            As[c4 * 4 + 0][r] = v.x;
            As[c4 * 4 + 1][r] = v.y;
            As[c4 * 4 + 2][r] = v.z;
            As[c4 * 4 + 3][r] = v.w;
        }
        // ---- load B tile ----
        if (TRANSB) {
            // B is [N,K]; tile [BNv x 16] -> Bs[k][n]
#pragma unroll
            for (int it = 0; it < BNv / 64; it++) {
                int idx = tid + it * 256;
                int r   = idx >> 2;
                int c4  = idx & 3;
                float4 v = *(const float4*)(B + (long long)(col0 + r) * ldb + k0 + c4 * 4);
                Bs[c4 * 4 + 0][r] = v.x;
                Bs[c4 * 4 + 1][r] = v.y;
                Bs[c4 * 4 + 2][r] = v.z;
                Bs[c4 * 4 + 3][r] = v.w;
            }
        } else {
            // B is [K,N]; tile [16 x BNv] -> Bs[k][n]
#pragma unroll
            for (int it = 0; it < BNv / 64; it++) {
                int idx = tid + it * 256;
                int r   = idx / (BNv / 4);
                int c4  = idx % (BNv / 4);
                float4 v = *(const float4*)(B + (long long)(k0 + r) * ldb + col0 + c4 * 4);
                *(float4*)&Bs[r][c4 * 4] = v;
            }
        }
        __syncthreads();

#pragma unroll
        for (int k = 0; k < BKK; k++) {
            float a[TMv], b[TNv];
#pragma unroll
            for (int i = 0; i < TMv / 4; i++)
                *(float4*)&a[i * 4] = *(const float4*)&As[k][ty * TMv + i * 4];
#pragma unroll
            for (int j = 0; j < TNv / 4; j++)
                *(float4*)&b[j * 4] = *(const float4*)&Bs[k][tx * TNv + j * 4];
#pragma unroll
            for (int i = 0; i < TMv; i++)
#pragma unroll
                for (int j = 0; j < TNv; j++)
                    acc[i][j] = fmaf(a[i], b[j], acc[i][j]);
        }
        __syncthreads();
    }

    // ---- epilogue ----
#pragma unroll
    for (int i = 0; i < TMv; i++) {
        long long rr = row0 + ty * TMv + i;
#pragma unroll
        for (int j4 = 0; j4 < TNv / 4; j4++) {
            int cc = col0 + tx * TNv + j4 * 4;
            float4 o;
            o.x = acc[i][j4 * 4 + 0] * alpha;
            o.y = acc[i][j4 * 4 + 1] * alpha;
            o.z = acc[i][j4 * 4 + 2] * alpha;
            o.w = acc[i][j4 * 4 + 3] * alpha;
            if (bias) {
                o.x += bias[cc + 0];
                o.y += bias[cc + 1];
                o.z += bias[cc + 2];
                o.w += bias[cc + 3];
            }
            if (RELU) {
                o.x = fmaxf(o.x, 0.f);
                o.y = fmaxf(o.y, 0.f);
                o.z = fmaxf(o.z, 0.f);
                o.w = fmaxf(o.w, 0.f);
            }
            *(float4*)(C + rr * ldc + cc) = o;
        }
    }
}

// ---------------- block reductions ----------------
__device__ __forceinline__ float blockReduceSum(float v, float* red)
{
#pragma unroll
    for (int o = 16; o > 0; o >>= 1) v += __shfl_xor_sync(0xffffffffu, v, o);
    int warp = threadIdx.x >> 5, lane = threadIdx.x & 31;
    if (lane == 0) red[warp] = v;
    __syncthreads();
    if (threadIdx.x < 8) {
        v = red[threadIdx.x];
#pragma unroll
        for (int o = 4; o > 0; o >>= 1) v += __shfl_xor_sync(0xffu, v, o);
        if (threadIdx.x == 0) red[0] = v;
    }
    __syncthreads();
    float r = red[0];
    __syncthreads();
    return r;
}

__device__ __forceinline__ float blockReduceMax(float v, float* red)
{
#pragma unroll
    for (int o = 16; o > 0; o >>= 1) v = fmaxf(v, __shfl_xor_sync(0xffffffffu, v, o));
    int warp = threadIdx.x >> 5, lane = threadIdx.x & 31;
    if (lane == 0) red[warp] = v;
    __syncthreads();
    if (threadIdx.x < 8) {
        v = red[threadIdx.x];
#pragma unroll
        for (int o = 4; o > 0; o >>= 1) v = fmaxf(v, __shfl_xor_sync(0xffu, v, o));
        if (threadIdx.x == 0) red[0] = v;
    }
    __syncthreads();
    float r = red[0];
    __syncthreads();
    return r;
}

// ---------------- masked softmax over score rows (in place) ----------------
// grid: (SEQ, BATCH*NH), block: 256
__global__ void softmax_k(float* __restrict__ scores, const int* __restrict__ mask)
{
    __shared__ float red[32];
    const int row = blockIdx.x;
    const int z   = blockIdx.y;         // b*NH + h
    const int b   = z >> 4;             // NH = 16
    float* p = scores + ((long long)z * SEQ + row) * SEQ;
    const int* m = mask + (long long)b * SEQ;
    const int tid = threadIdx.x;

    float v[4];
    float mx = -1e30f;
#pragma unroll
    for (int j = 0; j < 4; j++) {
        int c = tid + j * 256;
        float val = p[c];
        if (m[c] == 0) val = -1e9f;
        v[j] = val;
        mx = fmaxf(mx, val);
    }
    mx = blockReduceMax(mx, red);

    float s = 0.f;
#pragma unroll
    for (int j = 0; j < 4; j++) {
        v[j] = __expf(v[j] - mx);
        s += v[j];
    }
    s = blockReduceSum(s, red);
    float inv = 1.f / s;
#pragma unroll
    for (int j = 0; j < 4; j++)
        p[tid + j * 256] = v[j] * inv;
}

// ---------------- residual add + LayerNorm ----------------
// out[row] = LN(a[row] + b[row]) * g + be     grid: NT blocks, 256 threads
__global__ void addln_k(const float* __restrict__ a, const float* __restrict__ bres,
                        const float* __restrict__ g, const float* __restrict__ be,
                        float* __restrict__ out)
{
    __shared__ float red[32];
    const long long row = blockIdx.x;
    const float* pa = a    + row * DM;
    const float* pb = bres + row * DM;
    float*       po = out  + row * DM;
    const int tid = threadIdx.x;

    float v[4];
    float s = 0.f, s2 = 0.f;
#pragma unroll
    for (int j = 0; j < 4; j++) {
        int c = tid + j * 256;
        float t = pa[c] + pb[c];
        v[j] = t;
        s  += t;
        s2 += t * t;
    }
    s  = blockReduceSum(s, red);
    s2 = blockReduceSum(s2, red);
    float mu  = s * (1.f / DM);
    float var = s2 * (1.f / DM) - mu * mu;
    float inv = rsqrtf(var + 1e-5f);
#pragma unroll
    for (int j = 0; j < 4; j++) {
        int c = tid + j * 256;
        po[c] = (v[j] - mu) * inv * g[c] + be[c];
    }
}

// ---------------- launch ----------------
extern "C" void kernel_launch(void* const* d_in, const int* in_sizes, int n_in,
                              void* d_out, int out_size)
{
    const float* x    = (const float*)d_in[0];
    const int*   mask = (const int*)  d_in[1];
    const float* Wq   = (const float*)d_in[2];
    const float* bq   = (const float*)d_in[3];
    const float* Wk   = (const float*)d_in[4];
    const float* bk   = (const float*)d_in[5];
    const float* Wv   = (const float*)d_in[6];
    const float* bv   = (const float*)d_in[7];
    const float* Wo   = (const float*)d_in[8];
    const float* bo   = (const float*)d_in[9];
    const float* W1   = (const float*)d_in[10];
    const float* b1   = (const float*)d_in[11];
    const float* W2   = (const float*)d_in[12];
    const float* b2   = (const float*)d_in[13];
    const float* g1   = (const float*)d_in[14];
    const float* be1  = (const float*)d_in[15];
    const float* g2   = (const float*)d_in[16];
    const float* be2  = (const float*)d_in[17];
    float* out = (float*)d_out;

    float *Q, *Kp, *V, *SC, *CT, *TMP, *Hh, *FF;
    cudaGetSymbolAddress((void**)&Q,   g_Q);
    cudaGetSymbolAddress((void**)&Kp,  g_K);
    cudaGetSymbolAddress((void**)&V,   g_V);
    cudaGetSymbolAddress((void**)&SC,  g_scores);
    cudaGetSymbolAddress((void**)&CT,  g_ctx);
    cudaGetSymbolAddress((void**)&TMP, g_tmp);
    cudaGetSymbolAddress((void**)&Hh,  g_h);
    cudaGetSymbolAddress((void**)&FF,  g_ff);

    const dim3 blk(256);
    const long long SD  = (long long)SEQ * DM;       // per-batch token stride
    const long long SS  = (long long)SEQ * SEQ;      // per-head score stride

    // 1) QKV projections: [NT,DM] @ [DM,DM]
    {
        dim3 g(DM / 128, NT / 128, 1);
        gemm_k<128,128,8,8,false,false><<<g, blk>>>(x, Wq, bq, Q,  NT, DM, DM, DM, DM, DM, 0,0,0,0,0,0, 1, 1.f);
        gemm_k<128,128,8,8,false,false><<<g, blk>>>(x, Wk, bk, Kp, NT, DM, DM, DM, DM, DM, 0,0,0,0,0,0, 1, 1.f);
        gemm_k<128,128,8,8,false,false><<<g, blk>>>(x, Wv, bv, V,  NT, DM, DM, DM, DM, DM, 0,0,0,0,0,0, 1, 1.f);
    }

    // 2) scores = (Q @ K^T) / 8 per (b,h):  [SEQ,DK] @ [SEQ,DK]^T
    {
        dim3 g(SEQ / 128, SEQ / 128, BATCH * NH);
        gemm_k<128,128,8,8,true,false><<<g, blk>>>(Q, Kp, nullptr, SC,
            SEQ, SEQ, DK, DM, DM, SEQ,
            SD, DK, SD, DK, (long long)NH * SS, SS, NH, 0.125f);
    }

    // 3) masked softmax
    {
        dim3 g(SEQ, BATCH * NH);
        softmax_k<<<g, 256>>>(SC, mask);
    }

    // 4) ctx = attn @ V per (b,h): [SEQ,SEQ] @ [SEQ,DK]
    {
        dim3 g(DK / 64, SEQ / 64, BATCH * NH);
        gemm_k<64,64,4,4,false,false><<<g, blk>>>(SC, V, nullptr, CT,
            SEQ, DK, SEQ, SEQ, DM, DM,
            (long long)NH * SS, SS, SD, DK, SD, DK, NH, 1.f);
    }

    // 5) attn_out = ctx @ Wo + bo
    {
        dim3 g(DM / 128, NT / 128, 1);
        gemm_k<128,128,8,8,false,false><<<g, blk>>>(CT, Wo, bo, TMP, NT, DM, DM, DM, DM, DM, 0,0,0,0,0,0, 1, 1.f);
    }

    // 6) h = LN1(x + attn_out)
    addln_k<<<NT, 256>>>(x, TMP, g1, be1, Hh);

    // 7) ff = relu(h @ W1 + b1)
    {
        dim3 g(DFF / 128, NT / 128, 1);
        gemm_k<128,128,8,8,false,true><<<g, blk>>>(Hh, W1, b1, FF, NT, DFF, DM, DM, DFF, DFF, 0,0,0,0,0,0, 1, 1.f);
    }

    // 8) tmp = ff @ W2 + b2
    {
        dim3 g(DM / 128, NT / 128, 1);
        gemm_k<128,128,8,8,false,false><<<g, blk>>>(FF, W2, b2, TMP, NT, DM, DFF, DFF, DM, DM, 0,0,0,0,0,0, 1, 1.f);
    }

    // 9) out = LN2(h + tmp)
    addln_k<<<NT, 256>>>(Hh, TMP, g2, be2, out);
}

// round 4
// speedup vs baseline: 2.9806x; 2.9736x over previous
#include <cuda_runtime.h>
#include <cuda_bf16.h>
#include <cstdint>

#define BATCH 4
#define SEQ   1024
#define NT    4096
#define DM    1024
#define NH    16
#define DKH   64
#define DFF   4096

// ======================= device scratch =======================
__device__ __align__(16) float g_scores[(size_t)64 * SEQ * SEQ];
__device__ __align__(16) float g_tmp[(size_t)NT * DM];
__device__ __align__(16) float g_h[(size_t)NT * DM];
__device__ __align__(16) __nv_bfloat16 g_xb [(size_t)NT * DM];
__device__ __align__(16) __nv_bfloat16 g_Qb [(size_t)NT * DM];
__device__ __align__(16) __nv_bfloat16 g_Kb [(size_t)NT * DM];
__device__ __align__(16) __nv_bfloat16 g_Vb [(size_t)NT * DM];
__device__ __align__(16) __nv_bfloat16 g_VT [(size_t)NT * DM];
__device__ __align__(16) __nv_bfloat16 g_probs[(size_t)64 * SEQ * SEQ];
__device__ __align__(16) __nv_bfloat16 g_ctxb[(size_t)NT * DM];
__device__ __align__(16) __nv_bfloat16 g_WqT[(size_t)DM * DM];
__device__ __align__(16) __nv_bfloat16 g_WkT[(size_t)DM * DM];
__device__ __align__(16) __nv_bfloat16 g_WvT[(size_t)DM * DM];
__device__ __align__(16) __nv_bfloat16 g_WoT[(size_t)DM * DM];
__device__ __align__(16) __nv_bfloat16 g_W1T3[(size_t)DFF * 3 * DM];
__device__ __align__(16) __nv_bfloat16 g_W2T3[(size_t)DM * 3 * DFF];
__device__ __align__(16) __nv_bfloat16 g_h3 [(size_t)NT * 3 * DM];
__device__ __align__(16) __nv_bfloat16 g_ff3[(size_t)NT * 3 * DFF];

// ======================= asm helpers (compute_80-level only) =======================
__device__ __forceinline__ uint32_t smem_u32(const void* p) {
    uint32_t a;
    asm("{ .reg .u64 t; cvta.to.shared.u64 t, %1; cvt.u32.u64 %0, t; }" : "=r"(a) : "l"(p));
    return a;
}
#define CP_ASYNC(s, g) \
    asm volatile("cp.async.cg.shared.global [%0], [%1], 16;" :: "r"(s), "l"(g) : "memory")
#define CP_COMMIT() asm volatile("cp.async.commit_group;" ::: "memory")
#define CP_WAIT(n)  asm volatile("cp.async.wait_group %0;" :: "n"(n) : "memory")

#define LDSM_X4(r0, r1, r2, r3, a) \
    asm volatile("ldmatrix.sync.aligned.m8n8.x4.shared.b16 {%0,%1,%2,%3}, [%4];" \
        : "=r"(r0), "=r"(r1), "=r"(r2), "=r"(r3) : "r"(a))

#define MMA_BF16(d, a, b) \
    asm volatile("mma.sync.aligned.m16n8k16.row.col.f32.bf16.bf16.f32 " \
        "{%0,%1,%2,%3}, {%4,%5,%6,%7}, {%8,%9}, {%0,%1,%2,%3};" \
        : "+f"((d)[0]), "+f"((d)[1]), "+f"((d)[2]), "+f"((d)[3]) \
        : "r"((a)[0]), "r"((a)[1]), "r"((a)[2]), "r"((a)[3]), "r"((b)[0]), "r"((b)[1]))

// swizzled smem layout: BK=32 bf16 rows (64B); 128B bank-row holds 2 tile rows.
// phys(r, c16): chunk index xor'ed over 3 bits -> conflict-free ldmatrix phases.
__device__ __forceinline__ uint32_t phys(uint32_t r, uint32_t c) {
    return (r >> 1) * 128 + ((((r & 1) << 2) | c) ^ ((r >> 1) & 7)) * 16;
}
__device__ __forceinline__ unsigned short bfu(float v) {
    return __bfloat16_as_ushort(__float2bfloat16_rn(v));
}

// ======================= mma.sync batched GEMM =======================
// C[M,N] = alpha*(A @ B^T) + bias. A:[M,K] bf16, B:[N,K] bf16 row-major.
// M%128==0, N%BN==0, K%32==0. OUT: 0=f32, 1=bf16, 2=relu+split3 bf16 (Npart).
template<int BN, int OUT>
__global__ __launch_bounds__(256, 2)
void mma_gemm(const __nv_bfloat16* __restrict__ A, const __nv_bfloat16* __restrict__ B,
              const float* __restrict__ bias, char* __restrict__ Cptr,
              int K, int lda, int ldb, int ldc,
              long long sAb, long long sAh, long long sBb, long long sBh,
              long long sCb, long long sCh, int nH, float alpha, int Npart)
{
    constexpr int DEPTH  = 4;
    constexpr int ABYTES = 128 * 64;
    constexpr int BBYTES = BN * 64;
    constexpr int STAGE  = ABYTES + BBYTES;
    constexpr int WN     = BN / 2;       // warp cols
    constexpr int NTL    = WN / 8;       // n-tiles per warp
    constexpr int NPAIR  = NTL / 2;
    constexpr int AIT    = 2;            // (128 rows * 4 chunks)/256
    constexpr int BIT    = (BN * 4) / 256;

    extern __shared__ char sm[];
    const uint32_t smb = smem_u32(sm);

    const int tid = threadIdx.x;
    const int wid = tid >> 5, lane = tid & 31;
    const int wRow = (wid & 3) * 32;
    const int wCol = (wid >> 2) * WN;
    const int z = blockIdx.z, zb = z / nH, zh = z - zb * nH;
    A += zb * sAb + zh * sAh;
    B += zb * sBb + zh * sBh;
    const long long coff = zb * sCb + zh * sCh;
    const int row0 = blockIdx.y * 128;
    const int col0 = blockIdx.x * BN;

    // ---- per-thread cp.async source/dest precompute ----
    const __nv_bfloat16* Ag[AIT]; uint32_t Asm[AIT];
#pragma unroll
    for (int i = 0; i < AIT; i++) {
        int r = (tid >> 2) + i * 64, c = tid & 3;
        Ag[i]  = A + (size_t)(row0 + r) * lda + c * 8;
        Asm[i] = phys(r, c);
    }
    const __nv_bfloat16* Bg[BIT]; uint32_t Bsm[BIT];
#pragma unroll
    for (int i = 0; i < BIT; i++) {
        int r = (tid >> 2) + i * 64, c = tid & 3;
        Bg[i]  = B + (size_t)(col0 + r) * ldb + c * 8;
        Bsm[i] = ABYTES + phys(r, c);
    }
    // ---- ldmatrix address precompute (constant across stages) ----
    uint32_t ldAo[2][2], ldBo[NPAIR][2];
#pragma unroll
    for (int mt = 0; mt < 2; mt++)
#pragma unroll
        for (int kk = 0; kk < 2; kk++)
            ldAo[mt][kk] = phys(wRow + mt * 16 + (lane & 15), kk * 2 + (lane >> 4));
#pragma unroll
    for (int np = 0; np < NPAIR; np++)
#pragma unroll
        for (int kk = 0; kk < 2; kk++)
            ldBo[np][kk] = ABYTES + phys(wCol + np * 16 + ((lane >> 4) << 3) + (lane & 7),
                                         kk * 2 + ((lane >> 3) & 1));

    float acc[2][NTL][4];
#pragma unroll
    for (int i = 0; i < 2; i++)
#pragma unroll
        for (int j = 0; j < NTL; j++)
#pragma unroll
            for (int k = 0; k < 4; k++) acc[i][j][k] = 0.f;

    const int NC = K / 32;
    const int PRE = NC < (DEPTH - 1) ? NC : (DEPTH - 1);
    for (int s = 0; s < PRE; s++) {
#pragma unroll
        for (int i = 0; i < AIT; i++) CP_ASYNC(smb + s * STAGE + Asm[i], Ag[i] + s * 32);
#pragma unroll
        for (int i = 0; i < BIT; i++) CP_ASYNC(smb + s * STAGE + Bsm[i], Bg[i] + s * 32);
        CP_COMMIT();
    }
    int idx = PRE;
    for (int cch = 0; cch < NC; cch++) {
        const int rem = NC - 1 - cch;
        if (rem >= 2) { CP_WAIT(2); } else if (rem == 1) { CP_WAIT(1); } else { CP_WAIT(0); }
        __syncthreads();
        if (idx < NC) {
            const int s = idx & (DEPTH - 1);
#pragma unroll
            for (int i = 0; i < AIT; i++) CP_ASYNC(smb + s * STAGE + Asm[i], Ag[i] + idx * 32);
#pragma unroll
            for (int i = 0; i < BIT; i++) CP_ASYNC(smb + s * STAGE + Bsm[i], Bg[i] + idx * 32);
            CP_COMMIT();
            idx++;
        }
        const uint32_t sb = smb + (cch & (DEPTH - 1)) * STAGE;
#pragma unroll
        for (int kk = 0; kk < 2; kk++) {
            uint32_t a[2][4], b[NTL][2];
#pragma unroll
            for (int mt = 0; mt < 2; mt++)
                LDSM_X4(a[mt][0], a[mt][1], a[mt][2], a[mt][3], sb + ldAo[mt][kk]);
#pragma unroll
            for (int np = 0; np < NPAIR; np++)
                LDSM_X4(b[2 * np][0], b[2 * np][1], b[2 * np + 1][0], b[2 * np + 1][1],
                        sb + ldBo[np][kk]);
#pragma unroll
            for (int mt = 0; mt < 2; mt++)
#pragma unroll
                for (int nt = 0; nt < NTL; nt++)
                    MMA_BF16(acc[mt][nt], a[mt], b[nt]);
        }
    }

    // ---- epilogue: register fragments -> global ----
    const int gid = lane >> 2, t4 = lane & 3;
#pragma unroll
    for (int mt = 0; mt < 2; mt++) {
        const int r1 = row0 + wRow + mt * 16 + gid;
        const long long ro1 = coff + (long long)r1 * ldc;
        const long long ro2 = ro1 + 8LL * ldc;
#pragma unroll
        for (int nt = 0; nt < NTL; nt++) {
            const int cc = col0 + wCol + nt * 8 + t4 * 2;
            const float b0 = bias ? bias[cc] : 0.f;
            const float b1 = bias ? bias[cc + 1] : 0.f;
            float v0 = acc[mt][nt][0] * alpha + b0;
            float v1 = acc[mt][nt][1] * alpha + b1;
            float v2 = acc[mt][nt][2] * alpha + b0;
            float v3 = acc[mt][nt][3] * alpha + b1;
            if constexpr (OUT == 0) {
                float* C = (float*)Cptr;
                *(float2*)(C + ro1 + cc) = make_float2(v0, v1);
                *(float2*)(C + ro2 + cc) = make_float2(v2, v3);
            } else if constexpr (OUT == 1) {
                __nv_bfloat16* C = (__nv_bfloat16*)Cptr;
                ushort2 o1, o2;
                o1.x = bfu(v0); o1.y = bfu(v1);
                o2.x = bfu(v2); o2.y = bfu(v3);
                *(ushort2*)(C + ro1 + cc) = o1;
                *(ushort2*)(C + ro2 + cc) = o2;
            } else {
                __nv_bfloat16* C = (__nv_bfloat16*)Cptr;
                v0 = fmaxf(v0, 0.f); v1 = fmaxf(v1, 0.f);
                v2 = fmaxf(v2, 0.f); v3 = fmaxf(v3, 0.f);
                __nv_bfloat16 h0 = __float2bfloat16_rn(v0), h1 = __float2bfloat16_rn(v1);
                __nv_bfloat16 h2 = __float2bfloat16_rn(v2), h3 = __float2bfloat16_rn(v3);
                ushort2 hi1, hi2, lo1, lo2;
                hi1.x = __bfloat16_as_ushort(h0); hi1.y = __bfloat16_as_ushort(h1);
                hi2.x = __bfloat16_as_ushort(h2); hi2.y = __bfloat16_as_ushort(h3);
                lo1.x = bfu(v0 - __bfloat162float(h0)); lo1.y = bfu(v1 - __bfloat162float(h1));
                lo2.x = bfu(v2 - __bfloat162float(h2)); lo2.y = bfu(v3 - __bfloat162float(h3));
                *(ushort2*)(C + ro1 + cc) = hi1;
                *(ushort2*)(C + ro2 + cc) = hi2;
                *(ushort2*)(C + ro1 + Npart + cc) = hi1;
                *(ushort2*)(C + ro2 + Npart + cc) = hi2;
                *(ushort2*)(C + ro1 + 2 * Npart + cc) = lo1;
                *(ushort2*)(C + ro2 + 2 * Npart + cc) = lo2;
            }
        }
    }
}

// ======================= conversion kernels =======================
__global__ void f32_to_bf16_k(const float* __restrict__ in, __nv_bfloat16* __restrict__ out, int n4)
{
    int i = blockIdx.x * 256 + threadIdx.x;
    if (i < n4) {
        float4 v = *(const float4*)(in + (size_t)i * 4);
        ushort4 o;
        o.x = bfu(v.x); o.y = bfu(v.y); o.z = bfu(v.z); o.w = bfu(v.w);
        *(ushort4*)(out + (size_t)i * 4) = o;
    }
}
// W[K,N] f32 -> WT[N,K] bf16
__global__ void transpose_bf16_k(const float* __restrict__ in, __nv_bfloat16* __restrict__ out, int K, int N)
{
    __shared__ float t[32][33];
    int n0 = blockIdx.x * 32, k0 = blockIdx.y * 32;
    int tx = threadIdx.x, ty = threadIdx.y;
    for (int j = ty; j < 32; j += 8) t[j][tx] = in[(size_t)(k0 + j) * N + n0 + tx];
    __syncthreads();
    for (int j = ty; j < 32; j += 8)
        out[(size_t)(n0 + j) * K + k0 + tx] = __float2bfloat16_rn(t[tx][j]);
}
// W[K,N] f32 -> W'[N,3K] bf16: hi | lo | hi (B-operand split3 layout)
__global__ void transpose_split3_k(const float* __restrict__ in, __nv_bfloat16* __restrict__ out, int K, int N)
{
    __shared__ float t[32][33];
    int n0 = blockIdx.x * 32, k0 = blockIdx.y * 32;
    int tx = threadIdx.x, ty = threadIdx.y;
    for (int j = ty; j < 32; j += 8) t[j][tx] = in[(size_t)(k0 + j) * N + n0 + tx];
    __syncthreads();
    for (int j = ty; j < 32; j += 8) {
        float v = t[tx][j];
        __nv_bfloat16 hi = __float2bfloat16_rn(v);
        size_t o = (size_t)(n0 + j) * 3 * K + k0 + tx;
        out[o] = hi;
        out[o + K] = __float2bfloat16_rn(v - __bfloat162float(hi));
        out[o + 2 * K] = hi;
    }
}
// V bf16 [NT,DM] -> VT [z][d][s]
__global__ void vt_k(const __nv_bfloat16* __restrict__ V, __nv_bfloat16* __restrict__ VT)
{
    __shared__ __nv_bfloat16 t[32][33];
    int z = blockIdx.z, b = z >> 4, h = z & 15;
    int s0 = blockIdx.x * 32, d0 = blockIdx.y * 32;
    int tx = threadIdx.x, ty = threadIdx.y;
    for (int j = ty; j < 32; j += 8)
        t[j][tx] = V[(size_t)(b * SEQ + s0 + j) * DM + h * DKH + d0 + tx];
    __syncthreads();
    for (int j = ty; j < 32; j += 8)
        VT[((size_t)z * DKH + d0 + j) * SEQ + s0 + tx] = t[tx][j];
}

// ======================= reductions / softmax / LN =======================
__device__ __forceinline__ float blkSum(float v, float* red)
{
#pragma unroll
    for (int o = 16; o > 0; o >>= 1) v += __shfl_xor_sync(0xffffffffu, v, o);
    int w = threadIdx.x >> 5, l = threadIdx.x & 31;
    if (l == 0) red[w] = v;
    __syncthreads();
    if (threadIdx.x < 8) {
        v = red[threadIdx.x];
#pragma unroll
        for (int o = 4; o > 0; o >>= 1) v += __shfl_xor_sync(0xffu, v, o);
        if (threadIdx.x == 0) red[0] = v;
    }
    __syncthreads();
    float r = red[0];
    __syncthreads();
    return r;
}
__device__ __forceinline__ float blkMax(float v, float* red)
{
#pragma unroll
    for (int o = 16; o > 0; o >>= 1) v = fmaxf(v, __shfl_xor_sync(0xffffffffu, v, o));
    int w = threadIdx.x >> 5, l = threadIdx.x & 31;
    if (l == 0) red[w] = v;
    __syncthreads();
    if (threadIdx.x < 8) {
        v = red[threadIdx.x];
#pragma unroll
        for (int o = 4; o > 0; o >>= 1) v = fmaxf(v, __shfl_xor_sync(0xffu, v, o));
        if (threadIdx.x == 0) red[0] = v;
    }
    __syncthreads();
    float r = red[0];
    __syncthreads();
    return r;
}

__global__ void softmax_k(const float* __restrict__ scores, const int* __restrict__ mask,
                          __nv_bfloat16* __restrict__ probs)
{
    __shared__ float red[32];
    const int row = blockIdx.x, z = blockIdx.y, b = z >> 4;
    const float* p = scores + ((long long)z * SEQ + row) * SEQ;
    __nv_bfloat16* q = probs + ((long long)z * SEQ + row) * SEQ;
    const int* m = mask + (long long)b * SEQ;
    const int tid = threadIdx.x;
    float v[4], mx = -1e30f;
#pragma unroll
    for (int j = 0; j < 4; j++) {
        int c = tid + j * 256;
        float val = p[c];
        if (m[c] == 0) val = -1e9f;
        v[j] = val;
        mx = fmaxf(mx, val);
    }
    mx = blkMax(mx, red);
    float s = 0.f;
#pragma unroll
    for (int j = 0; j < 4; j++) { v[j] = __expf(v[j] - mx); s += v[j]; }
    s = blkSum(s, red);
    float inv = 1.f / s;
#pragma unroll
    for (int j = 0; j < 4; j++)
        q[tid + j * 256] = __float2bfloat16_rn(v[j] * inv);
}

// out = LN(a+b)*g+be; if SPLIT also emit split3 bf16 rows (hi|hi|lo)
template<bool SPLIT>
__global__ void addln_k(const float* __restrict__ a, const float* __restrict__ bres,
                        const float* __restrict__ g, const float* __restrict__ be,
                        float* __restrict__ out, __nv_bfloat16* __restrict__ out3)
{
    __shared__ float red[32];
    const long long row = blockIdx.x;
    const float* pa = a + row * DM;
    const float* pb = bres + row * DM;
    const int tid = threadIdx.x;
    float v[4], s = 0.f, s2 = 0.f;
#pragma unroll
    for (int j = 0; j < 4; j++) {
        int c = tid + j * 256;
        float t = pa[c] + pb[c];
        v[j] = t; s += t; s2 += t * t;
    }
    s = blkSum(s, red);
    s2 = blkSum(s2, red);
    float mu = s * (1.f / DM);
    float var = s2 * (1.f / DM) - mu * mu;
    float inv = rsqrtf(var + 1e-5f);
#pragma unroll
    for (int j = 0; j < 4; j++) {
        int c = tid + j * 256;
        float o = (v[j] - mu) * inv * g[c] + be[c];
        out[row * DM + c] = o;
        if (SPLIT) {
            __nv_bfloat16 hi = __float2bfloat16_rn(o);
            size_t p = row * 3 * DM + c;
            out3[p] = hi;
            out3[p + DM] = hi;
            out3[p + 2 * DM] = __float2bfloat16_rn(o - __bfloat162float(hi));
        }
    }
}

// ======================= launch =======================
extern "C" void kernel_launch(void* const* d_in, const int* in_sizes, int n_in,
                              void* d_out, int out_size)
{
    const float* x    = (const float*)d_in[0];
    const int*   mask = (const int*)  d_in[1];
    const float* Wq = (const float*)d_in[2];  const float* bq = (const float*)d_in[3];
    const float* Wk = (const float*)d_in[4];  const float* bk = (const float*)d_in[5];
    const float* Wv = (const float*)d_in[6];  const float* bv = (const float*)d_in[7];
    const float* Wo = (const float*)d_in[8];  const float* bo = (const float*)d_in[9];
    const float* W1 = (const float*)d_in[10]; const float* b1 = (const float*)d_in[11];
    const float* W2 = (const float*)d_in[12]; const float* b2 = (const float*)d_in[13];
    const float* g1 = (const float*)d_in[14]; const float* be1 = (const float*)d_in[15];
    const float* g2 = (const float*)d_in[16]; const float* be2 = (const float*)d_in[17];
    float* out = (float*)d_out;

    float *SC, *TMP, *H;
    __nv_bfloat16 *XB, *QB, *KB, *VB, *VT, *PR, *CTX, *WQT, *WKT, *WVT, *WOT, *W1T, *W2T, *H3, *FF3;
    cudaGetSymbolAddress((void**)&SC, g_scores);
    cudaGetSymbolAddress((void**)&TMP, g_tmp);
    cudaGetSymbolAddress((void**)&H, g_h);
    cudaGetSymbolAddress((void**)&XB, g_xb);
    cudaGetSymbolAddress((void**)&QB, g_Qb);
    cudaGetSymbolAddress((void**)&KB, g_Kb);
    cudaGetSymbolAddress((void**)&VB, g_Vb);
    cudaGetSymbolAddress((void**)&VT, g_VT);
    cudaGetSymbolAddress((void**)&PR, g_probs);
    cudaGetSymbolAddress((void**)&CTX, g_ctxb);
    cudaGetSymbolAddress((void**)&WQT, g_WqT);
    cudaGetSymbolAddress((void**)&WKT, g_WkT);
    cudaGetSymbolAddress((void**)&WVT, g_WvT);
    cudaGetSymbolAddress((void**)&WOT, g_WoT);
    cudaGetSymbolAddress((void**)&W1T, g_W1T3);
    cudaGetSymbolAddress((void**)&W2T, g_W2T3);
    cudaGetSymbolAddress((void**)&H3, g_h3);
    cudaGetSymbolAddress((void**)&FF3, g_ff3);

    const int SM128 = 4 * (128 + 128) * 64;   // 65536
    const int SM64  = 4 * (128 + 64) * 64;    // 49152
    cudaFuncSetAttribute(mma_gemm<128, 0>, cudaFuncAttributeMaxDynamicSharedMemorySize, SM128);
    cudaFuncSetAttribute(mma_gemm<128, 1>, cudaFuncAttributeMaxDynamicSharedMemorySize, SM128);
    cudaFuncSetAttribute(mma_gemm<128, 2>, cudaFuncAttributeMaxDynamicSharedMemorySize, SM128);
    cudaFuncSetAttribute(mma_gemm<64, 1>,  cudaFuncAttributeMaxDynamicSharedMemorySize, SM64);

    const long long SS = (long long)SEQ * SEQ;
    const long long SD = (long long)SEQ * DM;
    const dim3 t32(32, 8);

    // ---- input conversions ----
    f32_to_bf16_k<<<(NT * DM / 4 + 255) / 256, 256>>>(x, XB, NT * DM / 4);
    transpose_bf16_k<<<dim3(DM / 32, DM / 32), t32>>>(Wq, WQT, DM, DM);
    transpose_bf16_k<<<dim3(DM / 32, DM / 32), t32>>>(Wk, WKT, DM, DM);
    transpose_bf16_k<<<dim3(DM / 32, DM / 32), t32>>>(Wv, WVT, DM, DM);
    transpose_bf16_k<<<dim3(DM / 32, DM / 32), t32>>>(Wo, WOT, DM, DM);
    transpose_split3_k<<<dim3(DFF / 32, DM / 32), t32>>>(W1, W1T, DM, DFF);
    transpose_split3_k<<<dim3(DM / 32, DFF / 32), t32>>>(W2, W2T, DFF, DM);

    // ---- QKV projections (single-pass bf16) ----
    {
        dim3 g(DM / 128, NT / 128, 1);
        mma_gemm<128, 1><<<g, 256, SM128>>>(XB, WQT, bq, (char*)QB, DM, DM, DM, DM,
                                            0, 0, 0, 0, 0, 0, 1, 1.f, 0);
        mma_gemm<128, 1><<<g, 256, SM128>>>(XB, WKT, bk, (char*)KB, DM, DM, DM, DM,
                                            0, 0, 0, 0, 0, 0, 1, 1.f, 0);
        mma_gemm<128, 1><<<g, 256, SM128>>>(XB, WVT, bv, (char*)VB, DM, DM, DM, DM,
                                            0, 0, 0, 0, 0, 0, 1, 1.f, 0);
    }
    vt_k<<<dim3(SEQ / 32, DKH / 32, 64), t32>>>(VB, VT);

    // ---- scores = (Q @ K^T) / 8 -> f32 ----
    {
        dim3 g(SEQ / 128, SEQ / 128, 64);
        mma_gemm<128, 0><<<g, 256, SM128>>>(QB, KB, nullptr, (char*)SC, DKH, DM, DM, SEQ,
            SD, DKH, SD, DKH, (long long)NH * SS, SS, NH, 0.125f, 0);
    }
    // ---- masked softmax -> bf16 probs ----
    softmax_k<<<dim3(SEQ, 64), 256>>>(SC, mask, PR);

    // ---- ctx = probs @ V -> bf16 [NT,DM] ----
    {
        dim3 g(1, SEQ / 128, 64);
        mma_gemm<64, 1><<<g, 256, SM64>>>(PR, VT, nullptr, (char*)CTX, SEQ, SEQ, SEQ, DM,
            (long long)NH * SS, SS, (long long)NH * DKH * SEQ, (long long)DKH * SEQ,
            SD, DKH, NH, 1.f, 0);
    }
    // ---- attn_out = ctx @ Wo + bo -> f32 ----
    {
        dim3 g(DM / 128, NT / 128, 1);
        mma_gemm<128, 0><<<g, 256, SM128>>>(CTX, WOT, bo, (char*)TMP, DM, DM, DM, DM,
                                            0, 0, 0, 0, 0, 0, 1, 1.f, 0);
    }
    // ---- h = LN1(x + attn_out), also split3 ----
    addln_k<true><<<NT, 256>>>(x, TMP, g1, be1, H, H3);

    // ---- ff = relu(h @ W1 + b1) -> split3 bf16 (K' = 3*DM) ----
    {
        dim3 g(DFF / 128, NT / 128, 1);
        mma_gemm<128, 2><<<g, 256, SM128>>>(H3, W1T, b1, (char*)FF3, 3 * DM, 3 * DM, 3 * DM, 3 * DFF,
                                            0, 0, 0, 0, 0, 0, 1, 1.f, DFF);
    }
    // ---- tmp = ff @ W2 + b2 -> f32 (K' = 3*DFF) ----
    {
        dim3 g(DM / 128, NT / 128, 1);
        mma_gemm<128, 0><<<g, 256, SM128>>>(FF3, W2T, b2, (char*)TMP, 3 * DFF, 3 * DFF, 3 * DFF, DM,
                                            0, 0, 0, 0, 0, 0, 1, 1.f, 0);
    }
    // ---- out = LN2(h + tmp) ----
    addln_k<false><<<NT, 256>>>(H, TMP, g2, be2, out, nullptr);
}

// round 5
// speedup vs baseline: 3.4122x; 1.1448x over previous
#include <cuda_runtime.h>
#include <cuda_bf16.h>
#include <cstdint>

#define BATCH 4
#define SEQ   1024
#define NT    4096
#define DM    1024
#define NH    16
#define DKH   64
#define DFF   4096

// ======================= device scratch =======================
__device__ __align__(16) float g_tmp[(size_t)NT * DM];
__device__ __align__(16) float g_h[(size_t)NT * DM];
__device__ __align__(16) __nv_bfloat16 g_xb [(size_t)NT * DM];
__device__ __align__(16) __nv_bfloat16 g_Qb [(size_t)NT * DM];
__device__ __align__(16) __nv_bfloat16 g_Kb [(size_t)NT * DM];
__device__ __align__(16) __nv_bfloat16 g_Vb [(size_t)NT * DM];
__device__ __align__(16) __nv_bfloat16 g_VT [(size_t)NT * DM];
__device__ __align__(16) __nv_bfloat16 g_ctxb[(size_t)NT * DM];
__device__ __align__(16) __nv_bfloat16 g_WqT[(size_t)DM * DM];
__device__ __align__(16) __nv_bfloat16 g_WkT[(size_t)DM * DM];
__device__ __align__(16) __nv_bfloat16 g_WvT[(size_t)DM * DM];
__device__ __align__(16) __nv_bfloat16 g_WoT[(size_t)DM * DM];
__device__ __align__(16) __nv_bfloat16 g_W1T3[(size_t)DFF * 3 * DM];
__device__ __align__(16) __nv_bfloat16 g_W2T3[(size_t)DM * 3 * DFF];
__device__ __align__(16) __nv_bfloat16 g_h3 [(size_t)NT * 3 * DM];
__device__ __align__(16) __nv_bfloat16 g_ff3[(size_t)NT * 3 * DFF];

// ======================= asm helpers (compute_80-level only) =======================
__device__ __forceinline__ uint32_t smem_u32(const void* p) {
    uint32_t a;
    asm("{ .reg .u64 t; cvta.to.shared.u64 t, %1; cvt.u32.u64 %0, t; }" : "=r"(a) : "l"(p));
    return a;
}
#define CP_ASYNC(s, g) \
    asm volatile("cp.async.cg.shared.global [%0], [%1], 16;" :: "r"(s), "l"(g) : "memory")
#define CP_COMMIT() asm volatile("cp.async.commit_group;" ::: "memory")
#define CP_WAIT(n)  asm volatile("cp.async.wait_group %0;" :: "n"(n) : "memory")

#define LDSM_X4(r0, r1, r2, r3, a) \
    asm volatile("ldmatrix.sync.aligned.m8n8.x4.shared.b16 {%0,%1,%2,%3}, [%4];" \
        : "=r"(r0), "=r"(r1), "=r"(r2), "=r"(r3) : "r"(a))

#define MMA_BF16(d, a, b) \
    asm volatile("mma.sync.aligned.m16n8k16.row.col.f32.bf16.bf16.f32 " \
        "{%0,%1,%2,%3}, {%4,%5,%6,%7}, {%8,%9}, {%0,%1,%2,%3};" \
        : "+f"((d)[0]), "+f"((d)[1]), "+f"((d)[2]), "+f"((d)[3]) \
        : "r"((a)[0]), "r"((a)[1]), "r"((a)[2]), "r"((a)[3]), "r"((b)[0]), "r"((b)[1]))

// pack two f32 -> bf16x2 (lo = first arg, hi = second)
#define PACK_BF16X2(r, flo, fhi) \
    asm("cvt.rn.bf16x2.f32 %0, %1, %2;" : "=r"(r) : "f"(fhi), "f"(flo))

// swizzled smem layout for 32-element (64B) k-chunks.
// Property used below: phys(r+16, c) == phys(r, c) + 1024.
__device__ __forceinline__ uint32_t phys(uint32_t r, uint32_t c) {
    return (r >> 1) * 128 + ((((r & 1) << 2) | c) ^ ((r >> 1) & 7)) * 16;
}
__device__ __forceinline__ unsigned short bfu(float v) {
    return __bfloat16_as_ushort(__float2bfloat16_rn(v));
}

// ======================= mma.sync batched GEMM =======================
// C[M,N] = alpha*(A @ B^T) + bias. A:[M,K] bf16, B:[N,K] bf16 row-major.
// OUT: 0=f32, 1=bf16, 2=relu+split3 bf16 (Npart).
template<int BN, int OUT>
__global__ __launch_bounds__(256, 2)
void mma_gemm(const __nv_bfloat16* __restrict__ A, const __nv_bfloat16* __restrict__ B,
              const float* __restrict__ bias, char* __restrict__ Cptr,
              int K, int lda, int ldb, int ldc,
              long long sAb, long long sAh, long long sBb, long long sBh,
              long long sCb, long long sCh, int nH, float alpha, int Npart)
{
    constexpr int DEPTH  = 4;
    constexpr int ABYTES = 128 * 64;
    constexpr int BBYTES = BN * 64;
    constexpr int STAGE  = ABYTES + BBYTES;
    constexpr int WN     = BN / 2;
    constexpr int NTL    = WN / 8;
    constexpr int NPAIR  = NTL / 2;
    constexpr int AIT    = 2;
    constexpr int BIT    = (BN * 4) / 256;

    extern __shared__ char sm[];
    const uint32_t smb = smem_u32(sm);

    const int tid = threadIdx.x;
    const int wid = tid >> 5, lane = tid & 31;
    const int wRow = (wid & 3) * 32;
    const int wCol = (wid >> 2) * WN;
    const int z = blockIdx.z, zb = z / nH, zh = z - zb * nH;
    A += zb * sAb + zh * sAh;
    B += zb * sBb + zh * sBh;
    const long long coff = zb * sCb + zh * sCh;
    const int row0 = blockIdx.y * 128;
    const int col0 = blockIdx.x * BN;

    const __nv_bfloat16* Ag[AIT]; uint32_t Asm[AIT];
#pragma unroll
    for (int i = 0; i < AIT; i++) {
        int r = (tid >> 2) + i * 64, c = tid & 3;
        Ag[i]  = A + (size_t)(row0 + r) * lda + c * 8;
        Asm[i] = phys(r, c);
    }
    const __nv_bfloat16* Bg[BIT]; uint32_t Bsm[BIT];
#pragma unroll
    for (int i = 0; i < BIT; i++) {
        int r = (tid >> 2) + i * 64, c = tid & 3;
        Bg[i]  = B + (size_t)(col0 + r) * ldb + c * 8;
        Bsm[i] = ABYTES + phys(r, c);
    }
    uint32_t ldAo[2][2], ldBo[NPAIR][2];
#pragma unroll
    for (int mt = 0; mt < 2; mt++)
#pragma unroll
        for (int kk = 0; kk < 2; kk++)
            ldAo[mt][kk] = phys(wRow + mt * 16 + (lane & 15), kk * 2 + (lane >> 4));
#pragma unroll
    for (int np = 0; np < NPAIR; np++)
#pragma unroll
        for (int kk = 0; kk < 2; kk++)
            ldBo[np][kk] = ABYTES + phys(wCol + np * 16 + ((lane >> 4) << 3) + (lane & 7),
                                         kk * 2 + ((lane >> 3) & 1));

    float acc[2][NTL][4];
#pragma unroll
    for (int i = 0; i < 2; i++)
#pragma unroll
        for (int j = 0; j < NTL; j++)
#pragma unroll
            for (int k = 0; k < 4; k++) acc[i][j][k] = 0.f;

    const int NC = K / 32;
    const int PRE = NC < (DEPTH - 1) ? NC : (DEPTH - 1);
    for (int s = 0; s < PRE; s++) {
#pragma unroll
        for (int i = 0; i < AIT; i++) CP_ASYNC(smb + s * STAGE + Asm[i], Ag[i] + s * 32);
#pragma unroll
        for (int i = 0; i < BIT; i++) CP_ASYNC(smb + s * STAGE + Bsm[i], Bg[i] + s * 32);
        CP_COMMIT();
    }
    int idx = PRE;
    for (int cch = 0; cch < NC; cch++) {
        const int rem = NC - 1 - cch;
        if (rem >= 2) { CP_WAIT(2); } else if (rem == 1) { CP_WAIT(1); } else { CP_WAIT(0); }
        __syncthreads();
        if (idx < NC) {
            const int s = idx & (DEPTH - 1);
#pragma unroll
            for (int i = 0; i < AIT; i++) CP_ASYNC(smb + s * STAGE + Asm[i], Ag[i] + idx * 32);
#pragma unroll
            for (int i = 0; i < BIT; i++) CP_ASYNC(smb + s * STAGE + Bsm[i], Bg[i] + idx * 32);
            CP_COMMIT();
            idx++;
        }
        const uint32_t sb = smb + (cch & (DEPTH - 1)) * STAGE;
#pragma unroll
        for (int kk = 0; kk < 2; kk++) {
            uint32_t a[2][4], b[NTL][2];
#pragma unroll
            for (int mt = 0; mt < 2; mt++)
                LDSM_X4(a[mt][0], a[mt][1], a[mt][2], a[mt][3], sb + ldAo[mt][kk]);
#pragma unroll
            for (int np = 0; np < NPAIR; np++)
                LDSM_X4(b[2 * np][0], b[2 * np][1], b[2 * np + 1][0], b[2 * np + 1][1],
                        sb + ldBo[np][kk]);
#pragma unroll
            for (int mt = 0; mt < 2; mt++)
#pragma unroll
                for (int nt = 0; nt < NTL; nt++)
                    MMA_BF16(acc[mt][nt], a[mt], b[nt]);
        }
    }

    const int gid = lane >> 2, t4 = lane & 3;
#pragma unroll
    for (int mt = 0; mt < 2; mt++) {
        const int r1 = row0 + wRow + mt * 16 + gid;
        const long long ro1 = coff + (long long)r1 * ldc;
        const long long ro2 = ro1 + 8LL * ldc;
#pragma unroll
        for (int nt = 0; nt < NTL; nt++) {
            const int cc = col0 + wCol + nt * 8 + t4 * 2;
            const float b0 = bias ? bias[cc] : 0.f;
            const float b1 = bias ? bias[cc + 1] : 0.f;
            float v0 = acc[mt][nt][0] * alpha + b0;
            float v1 = acc[mt][nt][1] * alpha + b1;
            float v2 = acc[mt][nt][2] * alpha + b0;
            float v3 = acc[mt][nt][3] * alpha + b1;
            if constexpr (OUT == 0) {
                float* C = (float*)Cptr;
                *(float2*)(C + ro1 + cc) = make_float2(v0, v1);
                *(float2*)(C + ro2 + cc) = make_float2(v2, v3);
            } else if constexpr (OUT == 1) {
                __nv_bfloat16* C = (__nv_bfloat16*)Cptr;
                ushort2 o1, o2;
                o1.x = bfu(v0); o1.y = bfu(v1);
                o2.x = bfu(v2); o2.y = bfu(v3);
                *(ushort2*)(C + ro1 + cc) = o1;
                *(ushort2*)(C + ro2 + cc) = o2;
            } else {
                __nv_bfloat16* C = (__nv_bfloat16*)Cptr;
                v0 = fmaxf(v0, 0.f); v1 = fmaxf(v1, 0.f);
                v2 = fmaxf(v2, 0.f); v3 = fmaxf(v3, 0.f);
                __nv_bfloat16 h0 = __float2bfloat16_rn(v0), h1 = __float2bfloat16_rn(v1);
                __nv_bfloat16 h2 = __float2bfloat16_rn(v2), h3 = __float2bfloat16_rn(v3);
                ushort2 hi1, hi2, lo1, lo2;
                hi1.x = __bfloat16_as_ushort(h0); hi1.y = __bfloat16_as_ushort(h1);
                hi2.x = __bfloat16_as_ushort(h2); hi2.y = __bfloat16_as_ushort(h3);
                lo1.x = bfu(v0 - __bfloat162float(h0)); lo1.y = bfu(v1 - __bfloat162float(h1));
                lo2.x = bfu(v2 - __bfloat162float(h2)); lo2.y = bfu(v3 - __bfloat162float(h3));
                *(ushort2*)(C + ro1 + cc) = hi1;
                *(ushort2*)(C + ro2 + cc) = hi2;
                *(ushort2*)(C + ro1 + Npart + cc) = hi1;
                *(ushort2*)(C + ro2 + Npart + cc) = hi2;
                *(ushort2*)(C + ro1 + 2 * Npart + cc) = lo1;
                *(ushort2*)(C + ro2 + 2 * Npart + cc) = lo2;
            }
        }
    }
}

// ======================= flash attention =======================
// grid (SEQ/128, BATCH*NH), 256 threads (8 warps x 16 q-rows).
// Q,K: [NT, DM] bf16 (head-sliced). VT: [z][64][SEQ] bf16. CTX out: [NT, DM] bf16.
__global__ __launch_bounds__(256, 1)
void flash_k(const __nv_bfloat16* __restrict__ Q, const __nv_bfloat16* __restrict__ Kc,
             const __nv_bfloat16* __restrict__ VT, const int* __restrict__ mask,
             __nv_bfloat16* __restrict__ CTX)
{
    constexpr int CH128 = 8192;            // 128-row x 32-col bf16 chunk bytes
    constexpr int CH64  = 4096;
    constexpr int QOFF  = 0;               // Q: 2 chunks = 16 KB
    constexpr int ST0   = 16384;
    constexpr int STSZ  = 33280;           // K 16K + VT 16K + mask 512 + pad
    constexpr int VOFF  = 16384;
    constexpr int MOFF  = 32768;
    constexpr float SCL = 0.125f;
    constexpr float L2E = 1.44269504f;

    extern __shared__ char sm[];
    const uint32_t smb = smem_u32(sm);

    const int tid = threadIdx.x;
    const int wid = tid >> 5, lane = tid & 31;
    const int gid = lane >> 2, t4 = lane & 3;
    const int qb = blockIdx.x, z = blockIdx.y;
    const int b = z >> 4, h = z & 15;

    const int rr = tid >> 2, cc4 = tid & 3;          // loader row/col
    const size_t qrow0 = (size_t)(b * SEQ + qb * 128);
    const __nv_bfloat16* Qg = Q + (qrow0 + rr) * DM + h * DKH + cc4 * 8;
    const __nv_bfloat16* Kg0 = Kc + ((size_t)b * SEQ + rr) * DM + h * DKH + cc4 * 8;
    const __nv_bfloat16* Vg0 = VT + ((size_t)z * DKH + rr) * SEQ + cc4 * 8;
    const uint32_t physrc = phys(rr, cc4);

    auto issue_stage = [&](int jb, int st) {
        const uint32_t sb = smb + ST0 + st * STSZ;
        const __nv_bfloat16* kgb = Kg0 + (size_t)jb * 128 * DM;
#pragma unroll
        for (int kc = 0; kc < 2; kc++)
#pragma unroll
            for (int it = 0; it < 2; it++)
                CP_ASYNC(sb + kc * CH128 + physrc + it * 32 * 128,
                         kgb + (size_t)it * 64 * DM + kc * 32);
        const __nv_bfloat16* vgb = Vg0 + jb * 128;
#pragma unroll
        for (int kc = 0; kc < 4; kc++)
            CP_ASYNC(sb + VOFF + kc * CH64 + physrc, vgb + kc * 32);
        if (tid < 32)
            CP_ASYNC(sb + MOFF + tid * 16, mask + (size_t)b * SEQ + jb * 128 + tid * 4);
    };

    // prologue: Q + stage0, stage1
#pragma unroll
    for (int kc = 0; kc < 2; kc++)
#pragma unroll
        for (int it = 0; it < 2; it++)
            CP_ASYNC(smb + QOFF + kc * CH128 + physrc + it * 32 * 128,
                     Qg + (size_t)it * 64 * DM + kc * 32);
    issue_stage(0, 0);
    CP_COMMIT();
    issue_stage(1, 1);
    CP_COMMIT();
    CP_WAIT(1);
    __syncthreads();

    // Q fragments (warp's 16 rows x 64 d)
    uint32_t qa[4][4];
    {
        const uint32_t qbase0 = phys(lane & 15, (lane >> 4)) + wid * 1024;
        const uint32_t qbase1 = phys(lane & 15, 2 + (lane >> 4)) + wid * 1024;
#pragma unroll
        for (int kc = 0; kc < 2; kc++) {
            LDSM_X4(qa[kc * 2][0], qa[kc * 2][1], qa[kc * 2][2], qa[kc * 2][3],
                    smb + QOFF + kc * CH128 + qbase0);
            LDSM_X4(qa[kc * 2 + 1][0], qa[kc * 2 + 1][1], qa[kc * 2 + 1][2], qa[kc * 2 + 1][3],
                    smb + QOFF + kc * CH128 + qbase1);
        }
    }

    // ldmatrix B base offsets (np advances by +1024)
    const uint32_t bb0 = phys(((lane >> 4) << 3) + (lane & 7), ((lane >> 3) & 1));
    const uint32_t bb1 = phys(((lane >> 4) << 3) + (lane & 7), 2 + ((lane >> 3) & 1));

    float O[8][4];
#pragma unroll
    for (int i = 0; i < 8; i++)
#pragma unroll
        for (int j = 0; j < 4; j++) O[i][j] = 0.f;
    float m0 = -1e30f, m1 = -1e30f, l0 = 0.f, l1 = 0.f;

    for (int j = 0; j < 8; j++) {
        const uint32_t sb = smb + ST0 + (j & 1) * STSZ;
        const int* msm = (const int*)(sm + ST0 + (j & 1) * STSZ + MOFF);

        // ---- S = Q @ K^T ----
        float s[16][4];
#pragma unroll
        for (int i = 0; i < 16; i++)
#pragma unroll
            for (int k = 0; k < 4; k++) s[i][k] = 0.f;
#pragma unroll
        for (int kidx = 0; kidx < 4; kidx++) {
            const uint32_t cb = sb + (kidx >> 1) * CH128 + ((kidx & 1) ? bb1 : bb0);
#pragma unroll
            for (int np = 0; np < 8; np++) {
                uint32_t r0, r1, r2, r3;
                LDSM_X4(r0, r1, r2, r3, cb + np * 1024);
                uint32_t p0[2] = {r0, r1}, p1[2] = {r2, r3};
                MMA_BF16(s[2 * np], qa[kidx], p0);
                MMA_BF16(s[2 * np + 1], qa[kidx], p1);
            }
        }

        // ---- mask + scale, row max ----
        float mx0 = -1e30f, mx1 = -1e30f;
#pragma unroll
        for (int nt = 0; nt < 16; nt++) {
            const int c0 = nt * 8 + t4 * 2;
            const float a0 = msm[c0] ? 0.f : -1e9f;
            const float a1 = msm[c0 + 1] ? 0.f : -1e9f;
            s[nt][0] = s[nt][0] * SCL + a0;
            s[nt][1] = s[nt][1] * SCL + a1;
            s[nt][2] = s[nt][2] * SCL + a0;
            s[nt][3] = s[nt][3] * SCL + a1;
            mx0 = fmaxf(mx0, fmaxf(s[nt][0], s[nt][1]));
            mx1 = fmaxf(mx1, fmaxf(s[nt][2], s[nt][3]));
        }
        mx0 = fmaxf(mx0, __shfl_xor_sync(0xffffffffu, mx0, 1));
        mx0 = fmaxf(mx0, __shfl_xor_sync(0xffffffffu, mx0, 2));
        mx1 = fmaxf(mx1, __shfl_xor_sync(0xffffffffu, mx1, 1));
        mx1 = fmaxf(mx1, __shfl_xor_sync(0xffffffffu, mx1, 2));

        const float nm0 = fmaxf(m0, mx0), nm1 = fmaxf(m1, mx1);
        const float al0 = exp2f((m0 - nm0) * L2E), al1 = exp2f((m1 - nm1) * L2E);
        m0 = nm0; m1 = nm1;

        // ---- P = exp, rowsum, rescale O ----
        float sum0 = 0.f, sum1 = 0.f;
#pragma unroll
        for (int nt = 0; nt < 16; nt++) {
            s[nt][0] = exp2f((s[nt][0] - nm0) * L2E);
            s[nt][1] = exp2f((s[nt][1] - nm0) * L2E);
            s[nt][2] = exp2f((s[nt][2] - nm1) * L2E);
            s[nt][3] = exp2f((s[nt][3] - nm1) * L2E);
            sum0 += s[nt][0] + s[nt][1];
            sum1 += s[nt][2] + s[nt][3];
        }
        sum0 += __shfl_xor_sync(0xffffffffu, sum0, 1);
        sum0 += __shfl_xor_sync(0xffffffffu, sum0, 2);
        sum1 += __shfl_xor_sync(0xffffffffu, sum1, 1);
        sum1 += __shfl_xor_sync(0xffffffffu, sum1, 2);
        l0 = l0 * al0 + sum0;
        l1 = l1 * al1 + sum1;
#pragma unroll
        for (int i = 0; i < 8; i++) {
            O[i][0] *= al0; O[i][1] *= al0;
            O[i][2] *= al1; O[i][3] *= al1;
        }

        // ---- O += P @ V^T ----
#pragma unroll
        for (int kt = 0; kt < 8; kt++) {
            uint32_t pa[4];
            PACK_BF16X2(pa[0], s[2 * kt][0], s[2 * kt][1]);
            PACK_BF16X2(pa[1], s[2 * kt][2], s[2 * kt][3]);
            PACK_BF16X2(pa[2], s[2 * kt + 1][0], s[2 * kt + 1][1]);
            PACK_BF16X2(pa[3], s[2 * kt + 1][2], s[2 * kt + 1][3]);
            const uint32_t vb = sb + VOFF + (kt >> 1) * CH64 + ((kt & 1) ? bb1 : bb0);
#pragma unroll
            for (int np = 0; np < 4; np++) {
                uint32_t r0, r1, r2, r3;
                LDSM_X4(r0, r1, r2, r3, vb + np * 1024);
                uint32_t p0[2] = {r0, r1}, p1[2] = {r2, r3};
                MMA_BF16(O[2 * np], pa, p0);
                MMA_BF16(O[2 * np + 1], pa, p1);
            }
        }

        __syncthreads();
        if (j + 2 < 8) { issue_stage(j + 2, j & 1); CP_COMMIT(); CP_WAIT(1); }
        else if (j + 1 < 8) { CP_WAIT(0); }
        __syncthreads();
    }

    // ---- normalize + store ----
    const float inv0 = 1.f / l0, inv1 = 1.f / l1;
    const int q0 = qb * 128 + wid * 16 + gid;
    __nv_bfloat16* C1 = CTX + ((size_t)(b * SEQ + q0)) * DM + h * DKH;
    __nv_bfloat16* C2 = C1 + 8 * DM;
#pragma unroll
    for (int nt = 0; nt < 8; nt++) {
        const int cc = nt * 8 + t4 * 2;
        ushort2 o1, o2;
        o1.x = bfu(O[nt][0] * inv0); o1.y = bfu(O[nt][1] * inv0);
        o2.x = bfu(O[nt][2] * inv1); o2.y = bfu(O[nt][3] * inv1);
        *(ushort2*)(C1 + cc) = o1;
        *(ushort2*)(C2 + cc) = o2;
    }
}

// ======================= conversion kernels =======================
__global__ void f32_to_bf16_k(const float* __restrict__ in, __nv_bfloat16* __restrict__ out, int n4)
{
    int i = blockIdx.x * 256 + threadIdx.x;
    if (i < n4) {
        float4 v = *(const float4*)(in + (size_t)i * 4);
        ushort4 o;
        o.x = bfu(v.x); o.y = bfu(v.y); o.z = bfu(v.z); o.w = bfu(v.w);
        *(ushort4*)(out + (size_t)i * 4) = o;
    }
}
__global__ void transpose_bf16_k(const float* __restrict__ in, __nv_bfloat16* __restrict__ out, int K, int N)
{
    __shared__ float t[32][33];
    int n0 = blockIdx.x * 32, k0 = blockIdx.y * 32;
    int tx = threadIdx.x, ty = threadIdx.y;
    for (int j = ty; j < 32; j += 8) t[j][tx] = in[(size_t)(k0 + j) * N + n0 + tx];
    __syncthreads();
    for (int j = ty; j < 32; j += 8)
        out[(size_t)(n0 + j) * K + k0 + tx] = __float2bfloat16_rn(t[tx][j]);
}
__global__ void transpose_split3_k(const float* __restrict__ in, __nv_bfloat16* __restrict__ out, int K, int N)
{
    __shared__ float t[32][33];
    int n0 = blockIdx.x * 32, k0 = blockIdx.y * 32;
    int tx = threadIdx.x, ty = threadIdx.y;
    for (int j = ty; j < 32; j += 8) t[j][tx] = in[(size_t)(k0 + j) * N + n0 + tx];
    __syncthreads();
    for (int j = ty; j < 32; j += 8) {
        float v = t[tx][j];
        __nv_bfloat16 hi = __float2bfloat16_rn(v);
        size_t o = (size_t)(n0 + j) * 3 * K + k0 + tx;
        out[o] = hi;
        out[o + K] = __float2bfloat16_rn(v - __bfloat162float(hi));
        out[o + 2 * K] = hi;
    }
}
__global__ void vt_k(const __nv_bfloat16* __restrict__ V, __nv_bfloat16* __restrict__ VT)
{
    __shared__ __nv_bfloat16 t[32][33];
    int z = blockIdx.z, b = z >> 4, h = z & 15;
    int s0 = blockIdx.x * 32, d0 = blockIdx.y * 32;
    int tx = threadIdx.x, ty = threadIdx.y;
    for (int j = ty; j < 32; j += 8)
        t[j][tx] = V[(size_t)(b * SEQ + s0 + j) * DM + h * DKH + d0 + tx];
    __syncthreads();
    for (int j = ty; j < 32; j += 8)
        VT[((size_t)z * DKH + d0 + j) * SEQ + s0 + tx] = t[tx][j];
}

// ======================= reductions / LN =======================
__device__ __forceinline__ float blkSum(float v, float* red)
{
#pragma unroll
    for (int o = 16; o > 0; o >>= 1) v += __shfl_xor_sync(0xffffffffu, v, o);
    int w = threadIdx.x >> 5, l = threadIdx.x & 31;
    if (l == 0) red[w] = v;
    __syncthreads();
    if (threadIdx.x < 8) {
        v = red[threadIdx.x];
#pragma unroll
        for (int o = 4; o > 0; o >>= 1) v += __shfl_xor_sync(0xffu, v, o);
        if (threadIdx.x == 0) red[0] = v;
    }
    __syncthreads();
    float r = red[0];
    __syncthreads();
    return r;
}

template<bool SPLIT>
__global__ void addln_k(const float* __restrict__ a, const float* __restrict__ bres,
                        const float* __restrict__ g, const float* __restrict__ be,
                        float* __restrict__ out, __nv_bfloat16* __restrict__ out3)
{
    __shared__ float red[32];
    const long long row = blockIdx.x;
    const float* pa = a + row * DM;
    const float* pb = bres + row * DM;
    const int tid = threadIdx.x;
    float v[4], s = 0.f, s2 = 0.f;
#pragma unroll
    for (int j = 0; j < 4; j++) {
        int c = tid + j * 256;
        float t = pa[c] + pb[c];
        v[j] = t; s += t; s2 += t * t;
    }
    s = blkSum(s, red);
    s2 = blkSum(s2, red);
    float mu = s * (1.f / DM);
    float var = s2 * (1.f / DM) - mu * mu;
    float inv = rsqrtf(var + 1e-5f);
#pragma unroll
    for (int j = 0; j < 4; j++) {
        int c = tid + j * 256;
        float o = (v[j] - mu) * inv * g[c] + be[c];
        out[row * DM + c] = o;
        if (SPLIT) {
            __nv_bfloat16 hi = __float2bfloat16_rn(o);
            size_t p = row * 3 * DM + c;
            out3[p] = hi;
            out3[p + DM] = hi;
            out3[p + 2 * DM] = __float2bfloat16_rn(o - __bfloat162float(hi));
        }
    }
}

// ======================= launch =======================
extern "C" void kernel_launch(void* const* d_in, const int* in_sizes, int n_in,
                              void* d_out, int out_size)
{
    const float* x    = (const float*)d_in[0];
    const int*   mask = (const int*)  d_in[1];
    const float* Wq = (const float*)d_in[2];  const float* bq = (const float*)d_in[3];
    const float* Wk = (const float*)d_in[4];  const float* bk = (const float*)d_in[5];
    const float* Wv = (const float*)d_in[6];  const float* bv = (const float*)d_in[7];
    const float* Wo = (const float*)d_in[8];  const float* bo = (const float*)d_in[9];
    const float* W1 = (const float*)d_in[10]; const float* b1 = (const float*)d_in[11];
    const float* W2 = (const float*)d_in[12]; const float* b2 = (const float*)d_in[13];
    const float* g1 = (const float*)d_in[14]; const float* be1 = (const float*)d_in[15];
    const float* g2 = (const float*)d_in[16]; const float* be2 = (const float*)d_in[17];
    float* out = (float*)d_out;

    float *TMP, *H;
    __nv_bfloat16 *XB, *QB, *KB, *VB, *VT, *CTX, *WQT, *WKT, *WVT, *WOT, *W1T, *W2T, *H3, *FF3;
    cudaGetSymbolAddress((void**)&TMP, g_tmp);
    cudaGetSymbolAddress((void**)&H, g_h);
    cudaGetSymbolAddress((void**)&XB, g_xb);
    cudaGetSymbolAddress((void**)&QB, g_Qb);
    cudaGetSymbolAddress((void**)&KB, g_Kb);
    cudaGetSymbolAddress((void**)&VB, g_Vb);
    cudaGetSymbolAddress((void**)&VT, g_VT);
    cudaGetSymbolAddress((void**)&CTX, g_ctxb);
    cudaGetSymbolAddress((void**)&WQT, g_WqT);
    cudaGetSymbolAddress((void**)&WKT, g_WkT);
    cudaGetSymbolAddress((void**)&WVT, g_WvT);
    cudaGetSymbolAddress((void**)&WOT, g_WoT);
    cudaGetSymbolAddress((void**)&W1T, g_W1T3);
    cudaGetSymbolAddress((void**)&W2T, g_W2T3);
    cudaGetSymbolAddress((void**)&H3, g_h3);
    cudaGetSymbolAddress((void**)&FF3, g_ff3);

    const int SM128 = 4 * (128 + 128) * 64;   // 65536
    const int SMFL  = 16384 + 2 * 33280;      // 82944
    cudaFuncSetAttribute(mma_gemm<128, 0>, cudaFuncAttributeMaxDynamicSharedMemorySize, SM128);
    cudaFuncSetAttribute(mma_gemm<128, 1>, cudaFuncAttributeMaxDynamicSharedMemorySize, SM128);
    cudaFuncSetAttribute(mma_gemm<128, 2>, cudaFuncAttributeMaxDynamicSharedMemorySize, SM128);
    cudaFuncSetAttribute(flash_k, cudaFuncAttributeMaxDynamicSharedMemorySize, SMFL);

    const dim3 t32(32, 8);

    // ---- input conversions ----
    f32_to_bf16_k<<<(NT * DM / 4 + 255) / 256, 256>>>(x, XB, NT * DM / 4);
    transpose_bf16_k<<<dim3(DM / 32, DM / 32), t32>>>(Wq, WQT, DM, DM);
    transpose_bf16_k<<<dim3(DM / 32, DM / 32), t32>>>(Wk, WKT, DM, DM);
    transpose_bf16_k<<<dim3(DM / 32, DM / 32), t32>>>(Wv, WVT, DM, DM);
    transpose_bf16_k<<<dim3(DM / 32, DM / 32), t32>>>(Wo, WOT, DM, DM);
    transpose_split3_k<<<dim3(DFF / 32, DM / 32), t32>>>(W1, W1T, DM, DFF);
    transpose_split3_k<<<dim3(DM / 32, DFF / 32), t32>>>(W2, W2T, DFF, DM);

    // ---- QKV projections (single-pass bf16) ----
    {
        dim3 g(DM / 128, NT / 128, 1);
        mma_gemm<128, 1><<<g, 256, SM128>>>(XB, WQT, bq, (char*)QB, DM, DM, DM, DM,
                                            0, 0, 0, 0, 0, 0, 1, 1.f, 0);
        mma_gemm<128, 1><<<g, 256, SM128>>>(XB, WKT, bk, (char*)KB, DM, DM, DM, DM,
                                            0, 0, 0, 0, 0, 0, 1, 1.f, 0);
        mma_gemm<128, 1><<<g, 256, SM128>>>(XB, WVT, bv, (char*)VB, DM, DM, DM, DM,
                                            0, 0, 0, 0, 0, 0, 1, 1.f, 0);
    }
    vt_k<<<dim3(SEQ / 32, DKH / 32, 64), t32>>>(VB, VT);

    // ---- fused flash attention -> CTX bf16 ----
    flash_k<<<dim3(SEQ / 128, 64), 256, SMFL>>>(QB, KB, VT, mask, CTX);

    // ---- attn_out = ctx @ Wo + bo -> f32 ----
    {
        dim3 g(DM / 128, NT / 128, 1);
        mma_gemm<128, 0><<<g, 256, SM128>>>(CTX, WOT, bo, (char*)TMP, DM, DM, DM, DM,
                                            0, 0, 0, 0, 0, 0, 1, 1.f, 0);
    }
    // ---- h = LN1(x + attn_out), also split3 ----
    addln_k<true><<<NT, 256>>>(x, TMP, g1, be1, H, H3);

    // ---- ff = relu(h @ W1 + b1) -> split3 bf16 (K' = 3*DM) ----
    {
        dim3 g(DFF / 128, NT / 128, 1);
        mma_gemm<128, 2><<<g, 256, SM128>>>(H3, W1T, b1, (char*)FF3, 3 * DM, 3 * DM, 3 * DM, 3 * DFF,
                                            0, 0, 0, 0, 0, 0, 1, 1.f, DFF);
    }
    // ---- tmp = ff @ W2 + b2 -> f32 (K' = 3*DFF) ----
    {
        dim3 g(DM / 128, NT / 128, 1);
        mma_gemm<128, 0><<<g, 256, SM128>>>(FF3, W2T, b2, (char*)TMP, 3 * DFF, 3 * DFF, 3 * DFF, DM,
                                            0, 0, 0, 0, 0, 0, 1, 1.f, 0);
    }
    // ---- out = LN2(h + tmp) ----
    addln_k<false><<<NT, 256>>>(H, TMP, g2, be2, out, nullptr);
}

// round 6
// speedup vs baseline: 6.2853x; 1.8420x over previous
#include <cuda_runtime.h>
#include <cuda_fp16.h>
#include <cstdint>

#define BATCH 4
#define SEQ   1024
#define NT    4096
#define DM    1024
#define NH    16
#define DKH   64
#define DFF   4096

// ======================= device scratch =======================
__device__ __align__(16) float g_tmp[(size_t)NT * DM];
__device__ __align__(16) float g_h[(size_t)NT * DM];
__device__ __align__(16) __half g_xh [(size_t)NT * DM];
__device__ __align__(16) __half g_qkv[(size_t)NT * 3 * DM];
__device__ __align__(16) __half g_VT [(size_t)NT * DM];
__device__ __align__(16) __half g_ctx[(size_t)NT * DM];
__device__ __align__(16) __half g_WqkvT[(size_t)3 * DM * DM];
__device__ __align__(16) __half g_WoT[(size_t)DM * DM];
__device__ __align__(16) __half g_W1T[(size_t)DFF * DM];
__device__ __align__(16) __half g_W2T[(size_t)DM * DFF];
__device__ __align__(16) __half g_hh [(size_t)NT * DM];
__device__ __align__(16) __half g_ff [(size_t)NT * DFF];
__device__ __align__(16) float  g_bqkv[3 * DM];

// ======================= asm helpers (compute_80-level only) =======================
__device__ __forceinline__ uint32_t smem_u32(const void* p) {
    uint32_t a;
    asm("{ .reg .u64 t; cvta.to.shared.u64 t, %1; cvt.u32.u64 %0, t; }" : "=r"(a) : "l"(p));
    return a;
}
#define CP_ASYNC(s, g) \
    asm volatile("cp.async.cg.shared.global [%0], [%1], 16;" :: "r"(s), "l"(g) : "memory")
#define CP_COMMIT() asm volatile("cp.async.commit_group;" ::: "memory")
#define CP_WAIT(n)  asm volatile("cp.async.wait_group %0;" :: "n"(n) : "memory")

#define LDSM_X4(r0, r1, r2, r3, a) \
    asm volatile("ldmatrix.sync.aligned.m8n8.x4.shared.b16 {%0,%1,%2,%3}, [%4];" \
        : "=r"(r0), "=r"(r1), "=r"(r2), "=r"(r3) : "r"(a))

#define MMA_F16(d, a, b) \
    asm volatile("mma.sync.aligned.m16n8k16.row.col.f32.f16.f16.f32 " \
        "{%0,%1,%2,%3}, {%4,%5,%6,%7}, {%8,%9}, {%0,%1,%2,%3};" \
        : "+f"((d)[0]), "+f"((d)[1]), "+f"((d)[2]), "+f"((d)[3]) \
        : "r"((a)[0]), "r"((a)[1]), "r"((a)[2]), "r"((a)[3]), "r"((b)[0]), "r"((b)[1]))

// pack two f32 -> f16x2 (first arg -> low half)
#define PACK_F16X2(r, flo, fhi) \
    asm("cvt.rn.f16x2.f32 %0, %1, %2;" : "=r"(r) : "f"(fhi), "f"(flo))

// swizzled smem layout for 32-element (64B) k-chunks.
// Property: phys(r+16, c) == phys(r, c) + 1024.
__device__ __forceinline__ uint32_t phys(uint32_t r, uint32_t c) {
    return (r >> 1) * 128 + ((((r & 1) << 2) | c) ^ ((r >> 1) & 7)) * 16;
}
__device__ __forceinline__ unsigned short hfu(float v) {
    return __half_as_ushort(__float2half_rn(v));
}

// ======================= mma.sync batched GEMM (fp16 in, f32 acc) =======================
// C[M,N] = alpha*(A @ B^T) + bias. A:[M,K] half, B:[N,K] half row-major.
// OUT: 0=f32, 1=half, 2=relu half.
template<int BN, int OUT>
__global__ __launch_bounds__(256, 2)
void mma_gemm(const __half* __restrict__ A, const __half* __restrict__ B,
              const float* __restrict__ bias, char* __restrict__ Cptr,
              int K, int lda, int ldb, int ldc,
              long long sAb, long long sAh, long long sBb, long long sBh,
              long long sCb, long long sCh, int nH, float alpha)
{
    constexpr int DEPTH  = 4;
    constexpr int ABYTES = 128 * 64;
    constexpr int BBYTES = BN * 64;
    constexpr int STAGE  = ABYTES + BBYTES;
    constexpr int WN     = BN / 2;
    constexpr int NTL    = WN / 8;
    constexpr int NPAIR  = NTL / 2;
    constexpr int AIT    = 2;
    constexpr int BIT    = (BN * 4) / 256;

    extern __shared__ char sm[];
    const uint32_t smb = smem_u32(sm);

    const int tid = threadIdx.x;
    const int wid = tid >> 5, lane = tid & 31;
    const int wRow = (wid & 3) * 32;
    const int wCol = (wid >> 2) * WN;
    const int z = blockIdx.z, zb = z / nH, zh = z - zb * nH;
    A += zb * sAb + zh * sAh;
    B += zb * sBb + zh * sBh;
    const long long coff = zb * sCb + zh * sCh;
    const int row0 = blockIdx.y * 128;
    const int col0 = blockIdx.x * BN;

    const __half* Ag[AIT]; uint32_t Asm[AIT];
#pragma unroll
    for (int i = 0; i < AIT; i++) {
        int r = (tid >> 2) + i * 64, c = tid & 3;
        Ag[i]  = A + (size_t)(row0 + r) * lda + c * 8;
        Asm[i] = phys(r, c);
    }
    const __half* Bg[BIT]; uint32_t Bsm[BIT];
#pragma unroll
    for (int i = 0; i < BIT; i++) {
        int r = (tid >> 2) + i * 64, c = tid & 3;
        Bg[i]  = B + (size_t)(col0 + r) * ldb + c * 8;
        Bsm[i] = ABYTES + phys(r, c);
    }
    uint32_t ldAo[2][2], ldBo[NPAIR][2];
#pragma unroll
    for (int mt = 0; mt < 2; mt++)
#pragma unroll
        for (int kk = 0; kk < 2; kk++)
            ldAo[mt][kk] = phys(wRow + mt * 16 + (lane & 15), kk * 2 + (lane >> 4));
#pragma unroll
    for (int np = 0; np < NPAIR; np++)
#pragma unroll
        for (int kk = 0; kk < 2; kk++)
            ldBo[np][kk] = ABYTES + phys(wCol + np * 16 + ((lane >> 4) << 3) + (lane & 7),
                                         kk * 2 + ((lane >> 3) & 1));

    float acc[2][NTL][4];
#pragma unroll
    for (int i = 0; i < 2; i++)
#pragma unroll
        for (int j = 0; j < NTL; j++)
#pragma unroll
            for (int k = 0; k < 4; k++) acc[i][j][k] = 0.f;

    const int NC = K / 32;
    const int PRE = NC < (DEPTH - 1) ? NC : (DEPTH - 1);
    for (int s = 0; s < PRE; s++) {
#pragma unroll
        for (int i = 0; i < AIT; i++) CP_ASYNC(smb + s * STAGE + Asm[i], Ag[i] + s * 32);
#pragma unroll
        for (int i = 0; i < BIT; i++) CP_ASYNC(smb + s * STAGE + Bsm[i], Bg[i] + s * 32);
        CP_COMMIT();
    }
    int idx = PRE;
    for (int cch = 0; cch < NC; cch++) {
        const int rem = NC - 1 - cch;
        if (rem >= 2) { CP_WAIT(2); } else if (rem == 1) { CP_WAIT(1); } else { CP_WAIT(0); }
        __syncthreads();
        if (idx < NC) {
            const int s = idx & (DEPTH - 1);
#pragma unroll
            for (int i = 0; i < AIT; i++) CP_ASYNC(smb + s * STAGE + Asm[i], Ag[i] + idx * 32);
#pragma unroll
            for (int i = 0; i < BIT; i++) CP_ASYNC(smb + s * STAGE + Bsm[i], Bg[i] + idx * 32);
            CP_COMMIT();
            idx++;
        }
        const uint32_t sb = smb + (cch & (DEPTH - 1)) * STAGE;
#pragma unroll
        for (int kk = 0; kk < 2; kk++) {
            uint32_t a[2][4], b[NTL][2];
#pragma unroll
            for (int mt = 0; mt < 2; mt++)
                LDSM_X4(a[mt][0], a[mt][1], a[mt][2], a[mt][3], sb + ldAo[mt][kk]);
#pragma unroll
            for (int np = 0; np < NPAIR; np++)
                LDSM_X4(b[2 * np][0], b[2 * np][1], b[2 * np + 1][0], b[2 * np + 1][1],
                        sb + ldBo[np][kk]);
#pragma unroll
            for (int mt = 0; mt < 2; mt++)
#pragma unroll
                for (int nt = 0; nt < NTL; nt++)
                    MMA_F16(acc[mt][nt], a[mt], b[nt]);
        }
    }

    const int gid = lane >> 2, t4 = lane & 3;
#pragma unroll
    for (int mt = 0; mt < 2; mt++) {
        const int r1 = row0 + wRow + mt * 16 + gid;
        const long long ro1 = coff + (long long)r1 * ldc;
        const long long ro2 = ro1 + 8LL * ldc;
#pragma unroll
        for (int nt = 0; nt < NTL; nt++) {
            const int cc = col0 + wCol + nt * 8 + t4 * 2;
            const float b0 = bias ? bias[cc] : 0.f;
            const float b1 = bias ? bias[cc + 1] : 0.f;
            float v0 = acc[mt][nt][0] * alpha + b0;
            float v1 = acc[mt][nt][1] * alpha + b1;
            float v2 = acc[mt][nt][2] * alpha + b0;
            float v3 = acc[mt][nt][3] * alpha + b1;
            if constexpr (OUT == 0) {
                float* C = (float*)Cptr;
                *(float2*)(C + ro1 + cc) = make_float2(v0, v1);
                *(float2*)(C + ro2 + cc) = make_float2(v2, v3);
            } else {
                if constexpr (OUT == 2) {
                    v0 = fmaxf(v0, 0.f); v1 = fmaxf(v1, 0.f);
                    v2 = fmaxf(v2, 0.f); v3 = fmaxf(v3, 0.f);
                }
                __half* C = (__half*)Cptr;
                ushort2 o1, o2;
                o1.x = hfu(v0); o1.y = hfu(v1);
                o2.x = hfu(v2); o2.y = hfu(v3);
                *(ushort2*)(C + ro1 + cc) = o1;
                *(ushort2*)(C + ro2 + cc) = o2;
            }
        }
    }
}

// ======================= flash attention (fp16) =======================
// grid (SEQ/128, BATCH*NH), 256 threads. Q,K head-sliced from fused QKV (ld 3*DM).
__global__ __launch_bounds__(256, 1)
void flash_k(const __half* __restrict__ QKV, const __half* __restrict__ VT,
             const int* __restrict__ mask, __half* __restrict__ CTX)
{
    constexpr int QLD   = 3 * DM;
    constexpr int CH128 = 8192;
    constexpr int CH64  = 4096;
    constexpr int QOFF  = 0;
    constexpr int ST0   = 16384;
    constexpr int STSZ  = 33280;
    constexpr int VOFF  = 16384;
    constexpr int MOFF  = 32768;
    constexpr float SCL = 0.125f;
    constexpr float L2E = 1.44269504f;

    extern __shared__ char sm[];
    const uint32_t smb = smem_u32(sm);

    const int tid = threadIdx.x;
    const int wid = tid >> 5, lane = tid & 31;
    const int gid = lane >> 2, t4 = lane & 3;
    const int qb = blockIdx.x, z = blockIdx.y;
    const int b = z >> 4, h = z & 15;

    const int rr = tid >> 2, cc4 = tid & 3;
    const size_t qrow0 = (size_t)(b * SEQ + qb * 128);
    const __half* Qg  = QKV + (qrow0 + rr) * QLD + h * DKH + cc4 * 8;
    const __half* Kg0 = QKV + ((size_t)b * SEQ + rr) * QLD + DM + h * DKH + cc4 * 8;
    const __half* Vg0 = VT + ((size_t)z * DKH + rr) * SEQ + cc4 * 8;
    const uint32_t physrc = phys(rr, cc4);

    auto issue_stage = [&](int jb, int st) {
        const uint32_t sb = smb + ST0 + st * STSZ;
        const __half* kgb = Kg0 + (size_t)jb * 128 * QLD;
#pragma unroll
        for (int kc = 0; kc < 2; kc++)
#pragma unroll
            for (int it = 0; it < 2; it++)
                CP_ASYNC(sb + kc * CH128 + physrc + it * 32 * 128,
                         kgb + (size_t)it * 64 * QLD + kc * 32);
        const __half* vgb = Vg0 + jb * 128;
#pragma unroll
        for (int kc = 0; kc < 4; kc++)
            CP_ASYNC(sb + VOFF + kc * CH64 + physrc, vgb + kc * 32);
        if (tid < 32)
            CP_ASYNC(sb + MOFF + tid * 16, mask + (size_t)b * SEQ + jb * 128 + tid * 4);
    };

#pragma unroll
    for (int kc = 0; kc < 2; kc++)
#pragma unroll
        for (int it = 0; it < 2; it++)
            CP_ASYNC(smb + QOFF + kc * CH128 + physrc + it * 32 * 128,
                     Qg + (size_t)it * 64 * QLD + kc * 32);
    issue_stage(0, 0);
    CP_COMMIT();
    issue_stage(1, 1);
    CP_COMMIT();
    CP_WAIT(1);
    __syncthreads();

    uint32_t qa[4][4];
    {
        const uint32_t qbase0 = phys(lane & 15, (lane >> 4)) + wid * 1024;
        const uint32_t qbase1 = phys(lane & 15, 2 + (lane >> 4)) + wid * 1024;
#pragma unroll
        for (int kc = 0; kc < 2; kc++) {
            LDSM_X4(qa[kc * 2][0], qa[kc * 2][1], qa[kc * 2][2], qa[kc * 2][3],
                    smb + QOFF + kc * CH128 + qbase0);
            LDSM_X4(qa[kc * 2 + 1][0], qa[kc * 2 + 1][1], qa[kc * 2 + 1][2], qa[kc * 2 + 1][3],
                    smb + QOFF + kc * CH128 + qbase1);
        }
    }

    const uint32_t bb0 = phys(((lane >> 4) << 3) + (lane & 7), ((lane >> 3) & 1));
    const uint32_t bb1 = phys(((lane >> 4) << 3) + (lane & 7), 2 + ((lane >> 3) & 1));

    float O[8][4];
#pragma unroll
    for (int i = 0; i < 8; i++)
#pragma unroll
        for (int j = 0; j < 4; j++) O[i][j] = 0.f;
    float m0 = -1e30f, m1 = -1e30f, l0 = 0.f, l1 = 0.f;

    for (int j = 0; j < 8; j++) {
        const uint32_t sb = smb + ST0 + (j & 1) * STSZ;
        const int* msm = (const int*)(sm + ST0 + (j & 1) * STSZ + MOFF);

        float s[16][4];
#pragma unroll
        for (int i = 0; i < 16; i++)
#pragma unroll
            for (int k = 0; k < 4; k++) s[i][k] = 0.f;
#pragma unroll
        for (int kidx = 0; kidx < 4; kidx++) {
            const uint32_t cb = sb + (kidx >> 1) * CH128 + ((kidx & 1) ? bb1 : bb0);
#pragma unroll
            for (int np = 0; np < 8; np++) {
                uint32_t r0, r1, r2, r3;
                LDSM_X4(r0, r1, r2, r3, cb + np * 1024);
                uint32_t p0[2] = {r0, r1}, p1[2] = {r2, r3};
                MMA_F16(s[2 * np], qa[kidx], p0);
                MMA_F16(s[2 * np + 1], qa[kidx], p1);
            }
        }

        float mx0 = -1e30f, mx1 = -1e30f;
#pragma unroll
        for (int nt = 0; nt < 16; nt++) {
            const int c0 = nt * 8 + t4 * 2;
            const float a0 = msm[c0] ? 0.f : -1e9f;
            const float a1 = msm[c0 + 1] ? 0.f : -1e9f;
            s[nt][0] = s[nt][0] * SCL + a0;
            s[nt][1] = s[nt][1] * SCL + a1;
            s[nt][2] = s[nt][2] * SCL + a0;
            s[nt][3] = s[nt][3] * SCL + a1;
            mx0 = fmaxf(mx0, fmaxf(s[nt][0], s[nt][1]));
            mx1 = fmaxf(mx1, fmaxf(s[nt][2], s[nt][3]));
        }
        mx0 = fmaxf(mx0, __shfl_xor_sync(0xffffffffu, mx0, 1));
        mx0 = fmaxf(mx0, __shfl_xor_sync(0xffffffffu, mx0, 2));
        mx1 = fmaxf(mx1, __shfl_xor_sync(0xffffffffu, mx1, 1));
        mx1 = fmaxf(mx1, __shfl_xor_sync(0xffffffffu, mx1, 2));

        const float nm0 = fmaxf(m0, mx0), nm1 = fmaxf(m1, mx1);
        const float al0 = exp2f((m0 - nm0) * L2E), al1 = exp2f((m1 - nm1) * L2E);
        m0 = nm0; m1 = nm1;

        float sum0 = 0.f, sum1 = 0.f;
#pragma unroll
        for (int nt = 0; nt < 16; nt++) {
            s[nt][0] = exp2f((s[nt][0] - nm0) * L2E);
            s[nt][1] = exp2f((s[nt][1] - nm0) * L2E);
            s[nt][2] = exp2f((s[nt][2] - nm1) * L2E);
            s[nt][3] = exp2f((s[nt][3] - nm1) * L2E);
            sum0 += s[nt][0] + s[nt][1];
            sum1 += s[nt][2] + s[nt][3];
        }
        sum0 += __shfl_xor_sync(0xffffffffu, sum0, 1);
        sum0 += __shfl_xor_sync(0xffffffffu, sum0, 2);
        sum1 += __shfl_xor_sync(0xffffffffu, sum1, 1);
        sum1 += __shfl_xor_sync(0xffffffffu, sum1, 2);
        l0 = l0 * al0 + sum0;
        l1 = l1 * al1 + sum1;
#pragma unroll
        for (int i = 0; i < 8; i++) {
            O[i][0] *= al0; O[i][1] *= al0;
            O[i][2] *= al1; O[i][3] *= al1;
        }

#pragma unroll
        for (int kt = 0; kt < 8; kt++) {
            uint32_t pa[4];
            PACK_F16X2(pa[0], s[2 * kt][0], s[2 * kt][1]);
            PACK_F16X2(pa[1], s[2 * kt][2], s[2 * kt][3]);
            PACK_F16X2(pa[2], s[2 * kt + 1][0], s[2 * kt + 1][1]);
            PACK_F16X2(pa[3], s[2 * kt + 1][2], s[2 * kt + 1][3]);
            const uint32_t vb = sb + VOFF + (kt >> 1) * CH64 + ((kt & 1) ? bb1 : bb0);
#pragma unroll
            for (int np = 0; np < 4; np++) {
                uint32_t r0, r1, r2, r3;
                LDSM_X4(r0, r1, r2, r3, vb + np * 1024);
                uint32_t p0[2] = {r0, r1}, p1[2] = {r2, r3};
                MMA_F16(O[2 * np], pa, p0);
                MMA_F16(O[2 * np + 1], pa, p1);
            }
        }

        __syncthreads();
        if (j + 2 < 8) { issue_stage(j + 2, j & 1); CP_COMMIT(); CP_WAIT(1); }
        else if (j + 1 < 8) { CP_WAIT(0); }
        __syncthreads();
    }

    const float inv0 = 1.f / l0, inv1 = 1.f / l1;
    const int q0 = qb * 128 + wid * 16 + gid;
    __half* C1 = CTX + ((size_t)(b * SEQ + q0)) * DM + h * DKH;
    __half* C2 = C1 + 8 * DM;
#pragma unroll
    for (int nt = 0; nt < 8; nt++) {
        const int cc = nt * 8 + t4 * 2;
        ushort2 o1, o2;
        o1.x = hfu(O[nt][0] * inv0); o1.y = hfu(O[nt][1] * inv0);
        o2.x = hfu(O[nt][2] * inv1); o2.y = hfu(O[nt][3] * inv1);
        *(ushort2*)(C1 + cc) = o1;
        *(ushort2*)(C2 + cc) = o2;
    }
}

// ======================= conversion kernels =======================
__global__ void f32_to_half_k(const float* __restrict__ in, __half* __restrict__ out, int n4)
{
    int i = blockIdx.x * 256 + threadIdx.x;
    if (i < n4) {
        float4 v = *(const float4*)(in + (size_t)i * 4);
        ushort4 o;
        o.x = hfu(v.x); o.y = hfu(v.y); o.z = hfu(v.z); o.w = hfu(v.w);
        *(ushort4*)(out + (size_t)i * 4) = o;
    }
}
__global__ void transpose_half_k(const float* __restrict__ in, __half* __restrict__ out, int K, int N)
{
    __shared__ float t[32][33];
    int n0 = blockIdx.x * 32, k0 = blockIdx.y * 32;
    int tx = threadIdx.x, ty = threadIdx.y;
    for (int j = ty; j < 32; j += 8) t[j][tx] = in[(size_t)(k0 + j) * N + n0 + tx];
    __syncthreads();
    for (int j = ty; j < 32; j += 8)
        out[(size_t)(n0 + j) * K + k0 + tx] = __float2half_rn(t[tx][j]);
}
__global__ void concat_bias_k(const float* __restrict__ a, const float* __restrict__ b,
                              const float* __restrict__ c, float* __restrict__ o)
{
    int i = blockIdx.x * 256 + threadIdx.x;
    if (i < DM) { o[i] = a[i]; o[i + DM] = b[i]; o[i + 2 * DM] = c[i]; }
}
// V (from fused QKV, ld 3*DM) -> VT [z][d][s]
__global__ void vt_k(const __half* __restrict__ QKV, __half* __restrict__ VT)
{
    __shared__ __half t[32][33];
    int z = blockIdx.z, b = z >> 4, h = z & 15;
    int s0 = blockIdx.x * 32, d0 = blockIdx.y * 32;
    int tx = threadIdx.x, ty = threadIdx.y;
    for (int j = ty; j < 32; j += 8)
        t[j][tx] = QKV[(size_t)(b * SEQ + s0 + j) * (3 * DM) + 2 * DM + h * DKH + d0 + tx];
    __syncthreads();
    for (int j = ty; j < 32; j += 8)
        VT[((size_t)z * DKH + d0 + j) * SEQ + s0 + tx] = t[tx][j];
}

// ======================= reductions / LN =======================
__device__ __forceinline__ float blkSum(float v, float* red)
{
#pragma unroll
    for (int o = 16; o > 0; o >>= 1) v += __shfl_xor_sync(0xffffffffu, v, o);
    int w = threadIdx.x >> 5, l = threadIdx.x & 31;
    if (l == 0) red[w] = v;
    __syncthreads();
    if (threadIdx.x < 8) {
        v = red[threadIdx.x];
#pragma unroll
        for (int o = 4; o > 0; o >>= 1) v += __shfl_xor_sync(0xffu, v, o);
        if (threadIdx.x == 0) red[0] = v;
    }
    __syncthreads();
    float r = red[0];
    __syncthreads();
    return r;
}

// out = LN(a+b)*g+be (f32); if EMIT_H also write half copy
template<bool EMIT_H>
__global__ void addln_k(const float* __restrict__ a, const float* __restrict__ bres,
                        const float* __restrict__ g, const float* __restrict__ be,
                        float* __restrict__ out, __half* __restrict__ outh)
{
    __shared__ float red[32];
    const long long row = blockIdx.x;
    const float* pa = a + row * DM;
    const float* pb = bres + row * DM;
    const int tid = threadIdx.x;
    float v[4], s = 0.f, s2 = 0.f;
#pragma unroll
    for (int j = 0; j < 4; j++) {
        int c = tid + j * 256;
        float t = pa[c] + pb[c];
        v[j] = t; s += t; s2 += t * t;
    }
    s = blkSum(s, red);
    s2 = blkSum(s2, red);
    float mu = s * (1.f / DM);
    float var = s2 * (1.f / DM) - mu * mu;
    float inv = rsqrtf(var + 1e-5f);
#pragma unroll
    for (int j = 0; j < 4; j++) {
        int c = tid + j * 256;
        float o = (v[j] - mu) * inv * g[c] + be[c];
        out[row * DM + c] = o;
        if (EMIT_H) outh[row * DM + c] = __float2half_rn(o);
    }
}

// ======================= launch =======================
extern "C" void kernel_launch(void* const* d_in, const int* in_sizes, int n_in,
                              void* d_out, int out_size)
{
    const float* x    = (const float*)d_in[0];
    const int*   mask = (const int*)  d_in[1];
    const float* Wq = (const float*)d_in[2];  const float* bq = (const float*)d_in[3];
    const float* Wk = (const float*)d_in[4];  const float* bk = (const float*)d_in[5];
    const float* Wv = (const float*)d_in[6];  const float* bv = (const float*)d_in[7];
    const float* Wo = (const float*)d_in[8];  const float* bo = (const float*)d_in[9];
    const float* W1 = (const float*)d_in[10]; const float* b1 = (const float*)d_in[11];
    const float* W2 = (const float*)d_in[12]; const float* b2 = (const float*)d_in[13];
    const float* g1 = (const float*)d_in[14]; const float* be1 = (const float*)d_in[15];
    const float* g2 = (const float*)d_in[16]; const float* be2 = (const float*)d_in[17];
    float* out = (float*)d_out;

    float *TMP, *H, *BQKV;
    __half *XH, *QKV, *VT, *CTX, *WQKVT, *WOT, *W1T, *W2T, *HH, *FF;
    cudaGetSymbolAddress((void**)&TMP, g_tmp);
    cudaGetSymbolAddress((void**)&H, g_h);
    cudaGetSymbolAddress((void**)&XH, g_xh);
    cudaGetSymbolAddress((void**)&QKV, g_qkv);
    cudaGetSymbolAddress((void**)&VT, g_VT);
    cudaGetSymbolAddress((void**)&CTX, g_ctx);
    cudaGetSymbolAddress((void**)&WQKVT, g_WqkvT);
    cudaGetSymbolAddress((void**)&WOT, g_WoT);
    cudaGetSymbolAddress((void**)&W1T, g_W1T);
    cudaGetSymbolAddress((void**)&W2T, g_W2T);
    cudaGetSymbolAddress((void**)&HH, g_hh);
    cudaGetSymbolAddress((void**)&FF, g_ff);
    cudaGetSymbolAddress((void**)&BQKV, g_bqkv);

    const int SM128 = 4 * (128 + 128) * 64;   // 65536
    const int SMFL  = 16384 + 2 * 33280;      // 82944
    cudaFuncSetAttribute(mma_gemm<128, 0>, cudaFuncAttributeMaxDynamicSharedMemorySize, SM128);
    cudaFuncSetAttribute(mma_gemm<128, 1>, cudaFuncAttributeMaxDynamicSharedMemorySize, SM128);
    cudaFuncSetAttribute(mma_gemm<128, 2>, cudaFuncAttributeMaxDynamicSharedMemorySize, SM128);
    cudaFuncSetAttribute(flash_k, cudaFuncAttributeMaxDynamicSharedMemorySize, SMFL);

    const dim3 t32(32, 8);

    // ---- input conversions ----
    f32_to_half_k<<<(NT * DM / 4 + 255) / 256, 256>>>(x, XH, NT * DM / 4);
    transpose_half_k<<<dim3(DM / 32, DM / 32), t32>>>(Wq, WQKVT, DM, DM);
    transpose_half_k<<<dim3(DM / 32, DM / 32), t32>>>(Wk, WQKVT + (size_t)DM * DM, DM, DM);
    transpose_half_k<<<dim3(DM / 32, DM / 32), t32>>>(Wv, WQKVT + (size_t)2 * DM * DM, DM, DM);
    transpose_half_k<<<dim3(DM / 32, DM / 32), t32>>>(Wo, WOT, DM, DM);
    transpose_half_k<<<dim3(DFF / 32, DM / 32), t32>>>(W1, W1T, DM, DFF);
    transpose_half_k<<<dim3(DM / 32, DFF / 32), t32>>>(W2, W2T, DFF, DM);
    concat_bias_k<<<(DM + 255) / 256, 256>>>(bq, bk, bv, BQKV);

    // ---- fused QKV projection: [NT,1024] @ [3072,1024]^T -> [NT,3072] half ----
    {
        dim3 g(3 * DM / 128, NT / 128, 1);
        mma_gemm<128, 1><<<g, 256, SM128>>>(XH, WQKVT, BQKV, (char*)QKV, DM, DM, DM, 3 * DM,
                                            0, 0, 0, 0, 0, 0, 1, 1.f);
    }
    vt_k<<<dim3(SEQ / 32, DKH / 32, 64), t32>>>(QKV, VT);

    // ---- fused flash attention -> CTX half ----
    flash_k<<<dim3(SEQ / 128, 64), 256, SMFL>>>(QKV, VT, mask, CTX);

    // ---- attn_out = ctx @ Wo + bo -> f32 ----
    {
        dim3 g(DM / 128, NT / 128, 1);
        mma_gemm<128, 0><<<g, 256, SM128>>>(CTX, WOT, bo, (char*)TMP, DM, DM, DM, DM,
                                            0, 0, 0, 0, 0, 0, 1, 1.f);
    }
    // ---- h = LN1(x + attn_out) -> f32 + half ----
    addln_k<true><<<NT, 256>>>(x, TMP, g1, be1, H, HH);

    // ---- ff = relu(h @ W1 + b1) -> half ----
    {
        dim3 g(DFF / 128, NT / 128, 1);
        mma_gemm<128, 2><<<g, 256, SM128>>>(HH, W1T, b1, (char*)FF, DM, DM, DM, DFF,
                                            0, 0, 0, 0, 0, 0, 1, 1.f);
    }
    // ---- tmp = ff @ W2 + b2 -> f32 ----
    {
        dim3 g(DM / 128, NT / 128, 1);
        mma_gemm<128, 0><<<g, 256, SM128>>>(FF, W2T, b2, (char*)TMP, DFF, DFF, DFF, DM,
                                            0, 0, 0, 0, 0, 0, 1, 1.f);
    }
    // ---- out = LN2(h + tmp) ----
    addln_k<false><<<NT, 256>>>(H, TMP, g2, be2, out, nullptr);
}

// round 7
// speedup vs baseline: 6.4303x; 1.0231x over previous
#include <cuda_runtime.h>
#include <cuda_fp16.h>
#include <cstdint>

#define BATCH 4
#define SEQ   1024
#define NT    4096
#define DM    1024
#define NH    16
#define DKH   64
#define DFF   4096

// ======================= device scratch =======================
__device__ __align__(16) float g_tmp[(size_t)NT * DM];
__device__ __align__(16) float g_h[(size_t)NT * DM];
__device__ __align__(16) __half g_xh [(size_t)NT * DM];
__device__ __align__(16) __half g_qkv[(size_t)NT * 3 * DM];
__device__ __align__(16) __half g_VT [(size_t)NT * DM];
__device__ __align__(16) __half g_ctx[(size_t)NT * DM];
__device__ __align__(16) __half g_WqkvT[(size_t)3 * DM * DM];
__device__ __align__(16) __half g_WoT[(size_t)DM * DM];
__device__ __align__(16) __half g_W1T[(size_t)DFF * DM];
__device__ __align__(16) __half g_W2T[(size_t)DM * DFF];
__device__ __align__(16) __half g_hh [(size_t)NT * DM];
__device__ __align__(16) __half g_ff [(size_t)NT * DFF];
__device__ __align__(16) float  g_bqkv[3 * DM];

// ======================= asm helpers (compute_80-level only) =======================
__device__ __forceinline__ uint32_t smem_u32(const void* p) {
    uint32_t a;
    asm("{ .reg .u64 t; cvta.to.shared.u64 t, %1; cvt.u32.u64 %0, t; }" : "=r"(a) : "l"(p));
    return a;
}
#define CP_ASYNC(s, g) \
    asm volatile("cp.async.cg.shared.global [%0], [%1], 16;" :: "r"(s), "l"(g) : "memory")
#define CP_COMMIT() asm volatile("cp.async.commit_group;" ::: "memory")
#define CP_WAIT(n)  asm volatile("cp.async.wait_group %0;" :: "n"(n) : "memory")

#define LDSM_X4(r0, r1, r2, r3, a) \
    asm volatile("ldmatrix.sync.aligned.m8n8.x4.shared.b16 {%0,%1,%2,%3}, [%4];" \
        : "=r"(r0), "=r"(r1), "=r"(r2), "=r"(r3) : "r"(a))

#define MMA_F16(d, a, b) \
    asm volatile("mma.sync.aligned.m16n8k16.row.col.f32.f16.f16.f32 " \
        "{%0,%1,%2,%3}, {%4,%5,%6,%7}, {%8,%9}, {%0,%1,%2,%3};" \
        : "+f"((d)[0]), "+f"((d)[1]), "+f"((d)[2]), "+f"((d)[3]) \
        : "r"((a)[0]), "r"((a)[1]), "r"((a)[2]), "r"((a)[3]), "r"((b)[0]), "r"((b)[1]))

#define PACK_F16X2(r, flo, fhi) \
    asm("cvt.rn.f16x2.f32 %0, %1, %2;" : "=r"(r) : "f"(fhi), "f"(flo))

// swizzled smem layout for 32-element (64B) k-chunks. phys(r+16,c)==phys(r,c)+1024.
__device__ __forceinline__ uint32_t phys(uint32_t r, uint32_t c) {
    return (r >> 1) * 128 + ((((r & 1) << 2) | c) ^ ((r >> 1) & 7)) * 16;
}
__device__ __forceinline__ unsigned short hfu(float v) {
    return __half_as_ushort(__float2half_rn(v));
}

// ======================= mma.sync batched GEMM (fp16 in, f32 acc) =======================
template<int BN, int OUT>
__global__ __launch_bounds__(256, 2)
void mma_gemm(const __half* __restrict__ A, const __half* __restrict__ B,
              const float* __restrict__ bias, char* __restrict__ Cptr,
              int K, int lda, int ldb, int ldc,
              long long sAb, long long sAh, long long sBb, long long sBh,
              long long sCb, long long sCh, int nH, float alpha)
{
    constexpr int DEPTH  = 4;
    constexpr int ABYTES = 128 * 64;
    constexpr int BBYTES = BN * 64;
    constexpr int STAGE  = ABYTES + BBYTES;
    constexpr int WN     = BN / 2;
    constexpr int NTL    = WN / 8;
    constexpr int NPAIR  = NTL / 2;
    constexpr int AIT    = 2;
    constexpr int BIT    = (BN * 4) / 256;

    extern __shared__ char sm[];
    const uint32_t smb = smem_u32(sm);

    const int tid = threadIdx.x;
    const int wid = tid >> 5, lane = tid & 31;
    const int wRow = (wid & 3) * 32;
    const int wCol = (wid >> 2) * WN;
    const int z = blockIdx.z, zb = z / nH, zh = z - zb * nH;
    A += zb * sAb + zh * sAh;
    B += zb * sBb + zh * sBh;
    const long long coff = zb * sCb + zh * sCh;
    const int row0 = blockIdx.y * 128;
    const int col0 = blockIdx.x * BN;

    const __half* Ag[AIT]; uint32_t Asm[AIT];
#pragma unroll
    for (int i = 0; i < AIT; i++) {
        int r = (tid >> 2) + i * 64, c = tid & 3;
        Ag[i]  = A + (size_t)(row0 + r) * lda + c * 8;
        Asm[i] = phys(r, c);
    }
    const __half* Bg[BIT]; uint32_t Bsm[BIT];
#pragma unroll
    for (int i = 0; i < BIT; i++) {
        int r = (tid >> 2) + i * 64, c = tid & 3;
        Bg[i]  = B + (size_t)(col0 + r) * ldb + c * 8;
        Bsm[i] = ABYTES + phys(r, c);
    }
    uint32_t ldAo[2][2], ldBo[NPAIR][2];
#pragma unroll
    for (int mt = 0; mt < 2; mt++)
#pragma unroll
        for (int kk = 0; kk < 2; kk++)
            ldAo[mt][kk] = phys(wRow + mt * 16 + (lane & 15), kk * 2 + (lane >> 4));
#pragma unroll
    for (int np = 0; np < NPAIR; np++)
#pragma unroll
        for (int kk = 0; kk < 2; kk++)
            ldBo[np][kk] = ABYTES + phys(wCol + np * 16 + ((lane >> 4) << 3) + (lane & 7),
                                         kk * 2 + ((lane >> 3) & 1));

    float acc[2][NTL][4];
#pragma unroll
    for (int i = 0; i < 2; i++)
#pragma unroll
        for (int j = 0; j < NTL; j++)
#pragma unroll
            for (int k = 0; k < 4; k++) acc[i][j][k] = 0.f;

    const int NC = K / 32;
    const int PRE = NC < (DEPTH - 1) ? NC : (DEPTH - 1);
    for (int s = 0; s < PRE; s++) {
#pragma unroll
        for (int i = 0; i < AIT; i++) CP_ASYNC(smb + s * STAGE + Asm[i], Ag[i] + s * 32);
#pragma unroll
        for (int i = 0; i < BIT; i++) CP_ASYNC(smb + s * STAGE + Bsm[i], Bg[i] + s * 32);
        CP_COMMIT();
    }
    int idx = PRE;
    for (int cch = 0; cch < NC; cch++) {
        const int rem = NC - 1 - cch;
        if (rem >= 2) { CP_WAIT(2); } else if (rem == 1) { CP_WAIT(1); } else { CP_WAIT(0); }
        __syncthreads();
        if (idx < NC) {
            const int s = idx & (DEPTH - 1);
#pragma unroll
            for (int i = 0; i < AIT; i++) CP_ASYNC(smb + s * STAGE + Asm[i], Ag[i] + idx * 32);
#pragma unroll
            for (int i = 0; i < BIT; i++) CP_ASYNC(smb + s * STAGE + Bsm[i], Bg[i] + idx * 32);
            CP_COMMIT();
            idx++;
        }
        const uint32_t sb = smb + (cch & (DEPTH - 1)) * STAGE;
#pragma unroll
        for (int kk = 0; kk < 2; kk++) {
            uint32_t a[2][4], b[NTL][2];
#pragma unroll
            for (int mt = 0; mt < 2; mt++)
                LDSM_X4(a[mt][0], a[mt][1], a[mt][2], a[mt][3], sb + ldAo[mt][kk]);
#pragma unroll
            for (int np = 0; np < NPAIR; np++)
                LDSM_X4(b[2 * np][0], b[2 * np][1], b[2 * np + 1][0], b[2 * np + 1][1],
                        sb + ldBo[np][kk]);
#pragma unroll
            for (int mt = 0; mt < 2; mt++)
#pragma unroll
                for (int nt = 0; nt < NTL; nt++)
                    MMA_F16(acc[mt][nt], a[mt], b[nt]);
        }
    }

    const int gid = lane >> 2, t4 = lane & 3;
#pragma unroll
    for (int mt = 0; mt < 2; mt++) {
        const int r1 = row0 + wRow + mt * 16 + gid;
        const long long ro1 = coff + (long long)r1 * ldc;
        const long long ro2 = ro1 + 8LL * ldc;
#pragma unroll
        for (int nt = 0; nt < NTL; nt++) {
            const int cc = col0 + wCol + nt * 8 + t4 * 2;
            const float b0 = bias ? bias[cc] : 0.f;
            const float b1 = bias ? bias[cc + 1] : 0.f;
            float v0 = acc[mt][nt][0] * alpha + b0;
            float v1 = acc[mt][nt][1] * alpha + b1;
            float v2 = acc[mt][nt][2] * alpha + b0;
            float v3 = acc[mt][nt][3] * alpha + b1;
            if constexpr (OUT == 0) {
                float* C = (float*)Cptr;
                *(float2*)(C + ro1 + cc) = make_float2(v0, v1);
                *(float2*)(C + ro2 + cc) = make_float2(v2, v3);
            } else {
                if constexpr (OUT == 2) {
                    v0 = fmaxf(v0, 0.f); v1 = fmaxf(v1, 0.f);
                    v2 = fmaxf(v2, 0.f); v3 = fmaxf(v3, 0.f);
                }
                __half* C = (__half*)Cptr;
                ushort2 o1, o2;
                o1.x = hfu(v0); o1.y = hfu(v1);
                o2.x = hfu(v2); o2.y = hfu(v3);
                *(ushort2*)(C + ro1 + cc) = o1;
                *(ushort2*)(C + ro2 + cc) = o2;
            }
        }
    }
}

// ======================= flash attention v2: KV-block 64, occupancy 2 =======================
// grid (SEQ/128, BATCH*NH), 256 threads (8 warps x 16 q-rows).
__global__ __launch_bounds__(256, 2)
void flash_k(const __half* __restrict__ QKV, const __half* __restrict__ VT,
             const int* __restrict__ mask, __half* __restrict__ CTX)
{
    constexpr int QLD   = 3 * DM;
    constexpr int CH128 = 8192;       // [128][32] half chunk
    constexpr int CH64  = 4096;       // [64][32] half chunk
    constexpr int QOFF  = 0;          // Q: 2x CH128 = 16 KB
    constexpr int ST0   = 16384;
    constexpr int VOFF  = 8192;       // within stage: K 8K, V 8K, mask 256
    constexpr int MOFF  = 16384;
    constexpr int STSZ  = 16640;
    constexpr int NJ    = SEQ / 64;   // 16
    constexpr float SCL = 0.125f;
    constexpr float L2E = 1.44269504f;

    extern __shared__ char sm[];
    const uint32_t smb = smem_u32(sm);

    const int tid = threadIdx.x;
    const int wid = tid >> 5, lane = tid & 31;
    const int gid = lane >> 2, t4 = lane & 3;
    const int qb = blockIdx.x, z = blockIdx.y;
    const int b = z >> 4, h = z & 15;

    const int rr = tid >> 2, cc4 = tid & 3;     // 64 rows x 4 col-chunks
    const int rq = tid >> 2;                    // for Q (two iterations of 64)
    const size_t qrow0 = (size_t)(b * SEQ + qb * 128);
    const __half* Qg  = QKV + (qrow0 + rq) * QLD + h * DKH + cc4 * 8;
    const __half* Kg0 = QKV + ((size_t)b * SEQ + rr) * QLD + DM + h * DKH + cc4 * 8;
    const __half* Vg0 = VT + ((size_t)z * DKH + rr) * SEQ + cc4 * 8;
    const uint32_t physrc = phys(rr, cc4);

    auto issue_stage = [&](int jb, int st) {
        const uint32_t sb = smb + ST0 + st * STSZ;
        const __half* kgb = Kg0 + (size_t)jb * 64 * QLD;
#pragma unroll
        for (int kc = 0; kc < 2; kc++)
            CP_ASYNC(sb + kc * CH64 + physrc, kgb + kc * 32);
        const __half* vgb = Vg0 + jb * 64;
#pragma unroll
        for (int kc = 0; kc < 2; kc++)
            CP_ASYNC(sb + VOFF + kc * CH64 + physrc, vgb + kc * 32);
        if (tid < 16)
            CP_ASYNC(sb + MOFF + tid * 16, mask + (size_t)b * SEQ + jb * 64 + tid * 4);
    };

    // prologue: Q + 2 stages
#pragma unroll
    for (int kc = 0; kc < 2; kc++)
#pragma unroll
        for (int it = 0; it < 2; it++)
            CP_ASYNC(smb + QOFF + kc * CH128 + physrc + it * 32 * 128,
                     Qg + (size_t)it * 64 * QLD + kc * 32);
    issue_stage(0, 0);
    CP_COMMIT();
    issue_stage(1, 1);
    CP_COMMIT();
    CP_WAIT(1);
    __syncthreads();

    uint32_t qa[4][4];
    {
        const uint32_t qbase0 = phys(lane & 15, (lane >> 4)) + wid * 1024;
        const uint32_t qbase1 = phys(lane & 15, 2 + (lane >> 4)) + wid * 1024;
#pragma unroll
        for (int kc = 0; kc < 2; kc++) {
            LDSM_X4(qa[kc * 2][0], qa[kc * 2][1], qa[kc * 2][2], qa[kc * 2][3],
                    smb + QOFF + kc * CH128 + qbase0);
            LDSM_X4(qa[kc * 2 + 1][0], qa[kc * 2 + 1][1], qa[kc * 2 + 1][2], qa[kc * 2 + 1][3],
                    smb + QOFF + kc * CH128 + qbase1);
        }
    }

    const uint32_t bb0 = phys(((lane >> 4) << 3) + (lane & 7), ((lane >> 3) & 1));
    const uint32_t bb1 = phys(((lane >> 4) << 3) + (lane & 7), 2 + ((lane >> 3) & 1));

    float O[8][4];
#pragma unroll
    for (int i = 0; i < 8; i++)
#pragma unroll
        for (int j = 0; j < 4; j++) O[i][j] = 0.f;
    float m0 = -1e30f, m1 = -1e30f, l0 = 0.f, l1 = 0.f;

    for (int j = 0; j < NJ; j++) {
        const uint32_t sb = smb + ST0 + (j & 1) * STSZ;
        const int* msm = (const int*)(sm + ST0 + (j & 1) * STSZ + MOFF);

        // ---- S = Q @ K^T  (128 x 64 block) ----
        float s[8][4];
#pragma unroll
        for (int i = 0; i < 8; i++)
#pragma unroll
            for (int k = 0; k < 4; k++) s[i][k] = 0.f;
#pragma unroll
        for (int kidx = 0; kidx < 4; kidx++) {
            const uint32_t cb = sb + (kidx >> 1) * CH64 + ((kidx & 1) ? bb1 : bb0);
#pragma unroll
            for (int np = 0; np < 4; np++) {
                uint32_t r0, r1, r2, r3;
                LDSM_X4(r0, r1, r2, r3, cb + np * 1024);
                uint32_t p0[2] = {r0, r1}, p1[2] = {r2, r3};
                MMA_F16(s[2 * np], qa[kidx], p0);
                MMA_F16(s[2 * np + 1], qa[kidx], p1);
            }
        }

        // ---- mask + scale, row max ----
        float mx0 = -1e30f, mx1 = -1e30f;
#pragma unroll
        for (int nt = 0; nt < 8; nt++) {
            const int c0 = nt * 8 + t4 * 2;
            const float a0 = msm[c0] ? 0.f : -1e9f;
            const float a1 = msm[c0 + 1] ? 0.f : -1e9f;
            s[nt][0] = s[nt][0] * SCL + a0;
            s[nt][1] = s[nt][1] * SCL + a1;
            s[nt][2] = s[nt][2] * SCL + a0;
            s[nt][3] = s[nt][3] * SCL + a1;
            mx0 = fmaxf(mx0, fmaxf(s[nt][0], s[nt][1]));
            mx1 = fmaxf(mx1, fmaxf(s[nt][2], s[nt][3]));
        }
        mx0 = fmaxf(mx0, __shfl_xor_sync(0xffffffffu, mx0, 1));
        mx0 = fmaxf(mx0, __shfl_xor_sync(0xffffffffu, mx0, 2));
        mx1 = fmaxf(mx1, __shfl_xor_sync(0xffffffffu, mx1, 1));
        mx1 = fmaxf(mx1, __shfl_xor_sync(0xffffffffu, mx1, 2));

        const float nm0 = fmaxf(m0, mx0), nm1 = fmaxf(m1, mx1);
        const float al0 = exp2f((m0 - nm0) * L2E), al1 = exp2f((m1 - nm1) * L2E);
        m0 = nm0; m1 = nm1;

        float sum0 = 0.f, sum1 = 0.f;
#pragma unroll
        for (int nt = 0; nt < 8; nt++) {
            s[nt][0] = exp2f((s[nt][0] - nm0) * L2E);
            s[nt][1] = exp2f((s[nt][1] - nm0) * L2E);
            s[nt][2] = exp2f((s[nt][2] - nm1) * L2E);
            s[nt][3] = exp2f((s[nt][3] - nm1) * L2E);
            sum0 += s[nt][0] + s[nt][1];
            sum1 += s[nt][2] + s[nt][3];
        }
        sum0 += __shfl_xor_sync(0xffffffffu, sum0, 1);
        sum0 += __shfl_xor_sync(0xffffffffu, sum0, 2);
        sum1 += __shfl_xor_sync(0xffffffffu, sum1, 1);
        sum1 += __shfl_xor_sync(0xffffffffu, sum1, 2);
        l0 = l0 * al0 + sum0;
        l1 = l1 * al1 + sum1;
#pragma unroll
        for (int i = 0; i < 8; i++) {
            O[i][0] *= al0; O[i][1] *= al0;
            O[i][2] *= al1; O[i][3] *= al1;
        }

        // ---- O += P @ V^T ----
#pragma unroll
        for (int kt = 0; kt < 4; kt++) {
            uint32_t pa[4];
            PACK_F16X2(pa[0], s[2 * kt][0], s[2 * kt][1]);
            PACK_F16X2(pa[1], s[2 * kt][2], s[2 * kt][3]);
            PACK_F16X2(pa[2], s[2 * kt + 1][0], s[2 * kt + 1][1]);
            PACK_F16X2(pa[3], s[2 * kt + 1][2], s[2 * kt + 1][3]);
            const uint32_t vb = sb + VOFF + (kt >> 1) * CH64 + ((kt & 1) ? bb1 : bb0);
#pragma unroll
            for (int np = 0; np < 4; np++) {
                uint32_t r0, r1, r2, r3;
                LDSM_X4(r0, r1, r2, r3, vb + np * 1024);
                uint32_t p0[2] = {r0, r1}, p1[2] = {r2, r3};
                MMA_F16(O[2 * np], pa, p0);
                MMA_F16(O[2 * np + 1], pa, p1);
            }
        }

        __syncthreads();
        if (j + 2 < NJ) { issue_stage(j + 2, j & 1); CP_COMMIT(); CP_WAIT(1); }
        else if (j + 1 < NJ) { CP_WAIT(0); }
        __syncthreads();
    }

    const float inv0 = 1.f / l0, inv1 = 1.f / l1;
    const int q0 = qb * 128 + wid * 16 + gid;
    __half* C1 = CTX + ((size_t)(b * SEQ + q0)) * DM + h * DKH;
    __half* C2 = C1 + 8 * DM;
#pragma unroll
    for (int nt = 0; nt < 8; nt++) {
        const int cc = nt * 8 + t4 * 2;
        ushort2 o1, o2;
        o1.x = hfu(O[nt][0] * inv0); o1.y = hfu(O[nt][1] * inv0);
        o2.x = hfu(O[nt][2] * inv1); o2.y = hfu(O[nt][3] * inv1);
        *(ushort2*)(C1 + cc) = o1;
        *(ushort2*)(C2 + cc) = o2;
    }
}

// ======================= conversion kernels =======================
__global__ void f32_to_half_k(const float* __restrict__ in, __half* __restrict__ out, int n4)
{
    int i = blockIdx.x * 256 + threadIdx.x;
    if (i < n4) {
        float4 v = *(const float4*)(in + (size_t)i * 4);
        ushort4 o;
        o.x = hfu(v.x); o.y = hfu(v.y); o.z = hfu(v.z); o.w = hfu(v.w);
        *(ushort4*)(out + (size_t)i * 4) = o;
    }
}
// 4x [DM,DM] transposes in one launch: z selects (src, dst)
__global__ void transpose4_k(const float* __restrict__ s0, const float* __restrict__ s1,
                             const float* __restrict__ s2, const float* __restrict__ s3,
                             __half* __restrict__ d0, __half* __restrict__ d3)
{
    __shared__ float t[32][33];
    const int zi = blockIdx.z;
    const float* in = (zi == 0) ? s0 : (zi == 1) ? s1 : (zi == 2) ? s2 : s3;
    __half* out = (zi == 3) ? d3 : d0 + (size_t)zi * DM * DM;
    int n0 = blockIdx.x * 32, k0 = blockIdx.y * 32;
    int tx = threadIdx.x, ty = threadIdx.y;
    for (int j = ty; j < 32; j += 8) t[j][tx] = in[(size_t)(k0 + j) * DM + n0 + tx];
    __syncthreads();
    for (int j = ty; j < 32; j += 8)
        out[(size_t)(n0 + j) * DM + k0 + tx] = __float2half_rn(t[tx][j]);
}
__global__ void transpose_half_k(const float* __restrict__ in, __half* __restrict__ out, int K, int N)
{
    __shared__ float t[32][33];
    int n0 = blockIdx.x * 32, k0 = blockIdx.y * 32;
    int tx = threadIdx.x, ty = threadIdx.y;
    for (int j = ty; j < 32; j += 8) t[j][tx] = in[(size_t)(k0 + j) * N + n0 + tx];
    __syncthreads();
    for (int j = ty; j < 32; j += 8)
        out[(size_t)(n0 + j) * K + k0 + tx] = __float2half_rn(t[tx][j]);
}
__global__ void concat_bias_k(const float* __restrict__ a, const float* __restrict__ b,
                              const float* __restrict__ c, float* __restrict__ o)
{
    int i = blockIdx.x * 256 + threadIdx.x;
    if (i < DM) { o[i] = a[i]; o[i + DM] = b[i]; o[i + 2 * DM] = c[i]; }
}
__global__ void vt_k(const __half* __restrict__ QKV, __half* __restrict__ VT)
{
    __shared__ __half t[32][33];
    int z = blockIdx.z, b = z >> 4, h = z & 15;
    int s0 = blockIdx.x * 32, d0 = blockIdx.y * 32;
    int tx = threadIdx.x, ty = threadIdx.y;
    for (int j = ty; j < 32; j += 8)
        t[j][tx] = QKV[(size_t)(b * SEQ + s0 + j) * (3 * DM) + 2 * DM + h * DKH + d0 + tx];
    __syncthreads();
    for (int j = ty; j < 32; j += 8)
        VT[((size_t)z * DKH + d0 + j) * SEQ + s0 + tx] = t[tx][j];
}

// ======================= reductions / LN =======================
__device__ __forceinline__ float blkSum(float v, float* red)
{
#pragma unroll
    for (int o = 16; o > 0; o >>= 1) v += __shfl_xor_sync(0xffffffffu, v, o);
    int w = threadIdx.x >> 5, l = threadIdx.x & 31;
    if (l == 0) red[w] = v;
    __syncthreads();
    if (threadIdx.x < 8) {
        v = red[threadIdx.x];
#pragma unroll
        for (int o = 4; o > 0; o >>= 1) v += __shfl_xor_sync(0xffu, v, o);
        if (threadIdx.x == 0) red[0] = v;
    }
    __syncthreads();
    float r = red[0];
    __syncthreads();
    return r;
}

template<bool EMIT_H>
__global__ void addln_k(const float* __restrict__ a, const float* __restrict__ bres,
                        const float* __restrict__ g, const float* __restrict__ be,
                        float* __restrict__ out, __half* __restrict__ outh)
{
    __shared__ float red[32];
    const long long row = blockIdx.x;
    const float* pa = a + row * DM;
    const float* pb = bres + row * DM;
    const int tid = threadIdx.x;
    float v[4], s = 0.f, s2 = 0.f;
#pragma unroll
    for (int j = 0; j < 4; j++) {
        int c = tid + j * 256;
        float t = pa[c] + pb[c];
        v[j] = t; s += t; s2 += t * t;
    }
    s = blkSum(s, red);
    s2 = blkSum(s2, red);
    float mu = s * (1.f / DM);
    float var = s2 * (1.f / DM) - mu * mu;
    float inv = rsqrtf(var + 1e-5f);
#pragma unroll
    for (int j = 0; j < 4; j++) {
        int c = tid + j * 256;
        float o = (v[j] - mu) * inv * g[c] + be[c];
        out[row * DM + c] = o;
        if (EMIT_H) outh[row * DM + c] = __float2half_rn(o);
    }
}

// ======================= launch =======================
extern "C" void kernel_launch(void* const* d_in, const int* in_sizes, int n_in,
                              void* d_out, int out_size)
{
    const float* x    = (const float*)d_in[0];
    const int*   mask = (const int*)  d_in[1];
    const float* Wq = (const float*)d_in[2];  const float* bq = (const float*)d_in[3];
    const float* Wk = (const float*)d_in[4];  const float* bk = (const float*)d_in[5];
    const float* Wv = (const float*)d_in[6];  const float* bv = (const float*)d_in[7];
    const float* Wo = (const float*)d_in[8];  const float* bo = (const float*)d_in[9];
    const float* W1 = (const float*)d_in[10]; const float* b1 = (const float*)d_in[11];
    const float* W2 = (const float*)d_in[12]; const float* b2 = (const float*)d_in[13];
    const float* g1 = (const float*)d_in[14]; const float* be1 = (const float*)d_in[15];
    const float* g2 = (const float*)d_in[16]; const float* be2 = (const float*)d_in[17];
    float* out = (float*)d_out;

    float *TMP, *H, *BQKV;
    __half *XH, *QKV, *VT, *CTX, *WQKVT, *WOT, *W1T, *W2T, *HH, *FF;
    cudaGetSymbolAddress((void**)&TMP, g_tmp);
    cudaGetSymbolAddress((void**)&H, g_h);
    cudaGetSymbolAddress((void**)&XH, g_xh);
    cudaGetSymbolAddress((void**)&QKV, g_qkv);
    cudaGetSymbolAddress((void**)&VT, g_VT);
    cudaGetSymbolAddress((void**)&CTX, g_ctx);
    cudaGetSymbolAddress((void**)&WQKVT, g_WqkvT);
    cudaGetSymbolAddress((void**)&WOT, g_WoT);
    cudaGetSymbolAddress((void**)&W1T, g_W1T);
    cudaGetSymbolAddress((void**)&W2T, g_W2T);
    cudaGetSymbolAddress((void**)&HH, g_hh);
    cudaGetSymbolAddress((void**)&FF, g_ff);
    cudaGetSymbolAddress((void**)&BQKV, g_bqkv);

    const int SM128 = 4 * (128 + 128) * 64;   // 65536
    const int SMFL  = 16384 + 2 * 16640;      // 49664
    cudaFuncSetAttribute(mma_gemm<128, 0>, cudaFuncAttributeMaxDynamicSharedMemorySize, SM128);
    cudaFuncSetAttribute(mma_gemm<128, 1>, cudaFuncAttributeMaxDynamicSharedMemorySize, SM128);
    cudaFuncSetAttribute(mma_gemm<128, 2>, cudaFuncAttributeMaxDynamicSharedMemorySize, SM128);
    cudaFuncSetAttribute(flash_k, cudaFuncAttributeMaxDynamicSharedMemorySize, SMFL);

    const dim3 t32(32, 8);

    // ---- prologue conversions (5 launches; #6 is the QKV GEMM for ncu -s 5) ----
    f32_to_half_k<<<(NT * DM / 4 + 255) / 256, 256>>>(x, XH, NT * DM / 4);
    transpose4_k<<<dim3(DM / 32, DM / 32, 4), t32>>>(Wq, Wk, Wv, Wo, WQKVT, WOT);
    transpose_half_k<<<dim3(DFF / 32, DM / 32), t32>>>(W1, W1T, DM, DFF);
    transpose_half_k<<<dim3(DM / 32, DFF / 32), t32>>>(W2, W2T, DFF, DM);
    concat_bias_k<<<(DM + 255) / 256, 256>>>(bq, bk, bv, BQKV);

    // ---- fused QKV projection ----
    {
        dim3 g(3 * DM / 128, NT / 128, 1);
        mma_gemm<128, 1><<<g, 256, SM128>>>(XH, WQKVT, BQKV, (char*)QKV, DM, DM, DM, 3 * DM,
                                            0, 0, 0, 0, 0, 0, 1, 1.f);
    }
    vt_k<<<dim3(SEQ / 32, DKH / 32, 64), t32>>>(QKV, VT);

    // ---- flash attention -> CTX half ----
    flash_k<<<dim3(SEQ / 128, 64), 256, SMFL>>>(QKV, VT, mask, CTX);

    // ---- attn_out = ctx @ Wo + bo -> f32 ----
    {
        dim3 g(DM / 128, NT / 128, 1);
        mma_gemm<128, 0><<<g, 256, SM128>>>(CTX, WOT, bo, (char*)TMP, DM, DM, DM, DM,
                                            0, 0, 0, 0, 0, 0, 1, 1.f);
    }
    // ---- h = LN1(x + attn_out) ----
    addln_k<true><<<NT, 256>>>(x, TMP, g1, be1, H, HH);

    // ---- ff = relu(h @ W1 + b1) ----
    {
        dim3 g(DFF / 128, NT / 128, 1);
        mma_gemm<128, 2><<<g, 256, SM128>>>(HH, W1T, b1, (char*)FF, DM, DM, DM, DFF,
                                            0, 0, 0, 0, 0, 0, 1, 1.f);
    }
    // ---- tmp = ff @ W2 + b2 ----
    {
        dim3 g(DM / 128, NT / 128, 1);
        mma_gemm<128, 0><<<g, 256, SM128>>>(FF, W2T, b2, (char*)TMP, DFF, DFF, DFF, DM,
                                            0, 0, 0, 0, 0, 0, 1, 1.f);
    }
    // ---- out = LN2(h + tmp) ----
    addln_k<false><<<NT, 256>>>(H, TMP, g2, be2, out, nullptr);
}

// round 8
// speedup vs baseline: 6.5189x; 1.0138x over previous
#include <cuda_runtime.h>
#include <cuda_fp16.h>
#include <cstdint>

#define BATCH 4
#define SEQ   1024
#define NT    4096
#define DM    1024
#define NH    16
#define DKH   64
#define DFF   4096

// ======================= device scratch =======================
__device__ __align__(16) float g_tmp[(size_t)NT * DM];
__device__ __align__(16) float g_h[(size_t)NT * DM];
__device__ __align__(16) __half g_xh [(size_t)NT * DM];
__device__ __align__(16) __half g_qkv[(size_t)NT * 3 * DM];
__device__ __align__(16) __half g_VT [(size_t)NT * DM];
__device__ __align__(16) __half g_ctx[(size_t)NT * DM];
__device__ __align__(16) __half g_WqkvT[(size_t)3 * DM * DM];
__device__ __align__(16) __half g_WoT[(size_t)DM * DM];
__device__ __align__(16) __half g_W1T[(size_t)DFF * DM];
__device__ __align__(16) __half g_W2T[(size_t)DM * DFF];
__device__ __align__(16) __half g_hh [(size_t)NT * DM];
__device__ __align__(16) __half g_ff [(size_t)NT * DFF];
__device__ __align__(16) float  g_bqkv[3 * DM];

// ======================= asm helpers (compute_80-level only) =======================
__device__ __forceinline__ uint32_t smem_u32(const void* p) {
    uint32_t a;
    asm("{ .reg .u64 t; cvta.to.shared.u64 t, %1; cvt.u32.u64 %0, t; }" : "=r"(a) : "l"(p));
    return a;
}
#define CP_ASYNC(s, g) \
    asm volatile("cp.async.cg.shared.global [%0], [%1], 16;" :: "r"(s), "l"(g) : "memory")
#define CP_COMMIT() asm volatile("cp.async.commit_group;" ::: "memory")
#define CP_WAIT(n)  asm volatile("cp.async.wait_group %0;" :: "n"(n) : "memory")

#define LDSM_X4(r0, r1, r2, r3, a) \
    asm volatile("ldmatrix.sync.aligned.m8n8.x4.shared.b16 {%0,%1,%2,%3}, [%4];" \
        : "=r"(r0), "=r"(r1), "=r"(r2), "=r"(r3) : "r"(a))

#define MMA_F16(d, a, b) \
    asm volatile("mma.sync.aligned.m16n8k16.row.col.f32.f16.f16.f32 " \
        "{%0,%1,%2,%3}, {%4,%5,%6,%7}, {%8,%9}, {%0,%1,%2,%3};" \
        : "+f"((d)[0]), "+f"((d)[1]), "+f"((d)[2]), "+f"((d)[3]) \
        : "r"((a)[0]), "r"((a)[1]), "r"((a)[2]), "r"((a)[3]), "r"((b)[0]), "r"((b)[1]))

#define PACK_F16X2(r, flo, fhi) \
    asm("cvt.rn.f16x2.f32 %0, %1, %2;" : "=r"(r) : "f"(fhi), "f"(flo))

// swizzled smem layout for 32-element (64B) k-chunks. phys(r+16,c)==phys(r,c)+1024.
__device__ __forceinline__ uint32_t phys(uint32_t r, uint32_t c) {
    return (r >> 1) * 128 + ((((r & 1) << 2) | c) ^ ((r >> 1) & 7)) * 16;
}
__device__ __forceinline__ unsigned short hfu(float v) {
    return __half_as_ushort(__float2half_rn(v));
}

// ======================= mma.sync batched GEMM (fp16 in, f32 acc) =======================
template<int BN, int OUT>
__global__ __launch_bounds__(256, 2)
void mma_gemm(const __half* __restrict__ A, const __half* __restrict__ B,
              const float* __restrict__ bias, char* __restrict__ Cptr,
              int K, int lda, int ldb, int ldc,
              long long sAb, long long sAh, long long sBb, long long sBh,
              long long sCb, long long sCh, int nH, float alpha)
{
    constexpr int DEPTH  = 4;
    constexpr int ABYTES = 128 * 64;
    constexpr int BBYTES = BN * 64;
    constexpr int STAGE  = ABYTES + BBYTES;
    constexpr int WN     = BN / 2;
    constexpr int NTL    = WN / 8;
    constexpr int NPAIR  = NTL / 2;
    constexpr int AIT    = 2;
    constexpr int BIT    = (BN * 4) / 256;

    extern __shared__ char sm[];
    const uint32_t smb = smem_u32(sm);

    const int tid = threadIdx.x;
    const int wid = tid >> 5, lane = tid & 31;
    const int wRow = (wid & 3) * 32;
    const int wCol = (wid >> 2) * WN;
    const int z = blockIdx.z, zb = z / nH, zh = z - zb * nH;
    A += zb * sAb + zh * sAh;
    B += zb * sBb + zh * sBh;
    const long long coff = zb * sCb + zh * sCh;
    const int row0 = blockIdx.y * 128;
    const int col0 = blockIdx.x * BN;

    const __half* Ag[AIT]; uint32_t Asm[AIT];
#pragma unroll
    for (int i = 0; i < AIT; i++) {
        int r = (tid >> 2) + i * 64, c = tid & 3;
        Ag[i]  = A + (size_t)(row0 + r) * lda + c * 8;
        Asm[i] = phys(r, c);
    }
    const __half* Bg[BIT]; uint32_t Bsm[BIT];
#pragma unroll
    for (int i = 0; i < BIT; i++) {
        int r = (tid >> 2) + i * 64, c = tid & 3;
        Bg[i]  = B + (size_t)(col0 + r) * ldb + c * 8;
        Bsm[i] = ABYTES + phys(r, c);
    }
    uint32_t ldAo[2][2], ldBo[NPAIR][2];
#pragma unroll
    for (int mt = 0; mt < 2; mt++)
#pragma unroll
        for (int kk = 0; kk < 2; kk++)
            ldAo[mt][kk] = phys(wRow + mt * 16 + (lane & 15), kk * 2 + (lane >> 4));
#pragma unroll
    for (int np = 0; np < NPAIR; np++)
#pragma unroll
        for (int kk = 0; kk < 2; kk++)
            ldBo[np][kk] = ABYTES + phys(wCol + np * 16 + ((lane >> 4) << 3) + (lane & 7),
                                         kk * 2 + ((lane >> 3) & 1));

    float acc[2][NTL][4];
#pragma unroll
    for (int i = 0; i < 2; i++)
#pragma unroll
        for (int j = 0; j < NTL; j++)
#pragma unroll
            for (int k = 0; k < 4; k++) acc[i][j][k] = 0.f;

    const int NC = K / 32;
    const int PRE = NC < (DEPTH - 1) ? NC : (DEPTH - 1);
    for (int s = 0; s < PRE; s++) {
#pragma unroll
        for (int i = 0; i < AIT; i++) CP_ASYNC(smb + s * STAGE + Asm[i], Ag[i] + s * 32);
#pragma unroll
        for (int i = 0; i < BIT; i++) CP_ASYNC(smb + s * STAGE + Bsm[i], Bg[i] + s * 32);
        CP_COMMIT();
    }
    int idx = PRE;
    for (int cch = 0; cch < NC; cch++) {
        const int rem = NC - 1 - cch;
        if (rem >= 2) { CP_WAIT(2); } else if (rem == 1) { CP_WAIT(1); } else { CP_WAIT(0); }
        __syncthreads();
        if (idx < NC) {
            const int s = idx & (DEPTH - 1);
#pragma unroll
            for (int i = 0; i < AIT; i++) CP_ASYNC(smb + s * STAGE + Asm[i], Ag[i] + idx * 32);
#pragma unroll
            for (int i = 0; i < BIT; i++) CP_ASYNC(smb + s * STAGE + Bsm[i], Bg[i] + idx * 32);
            CP_COMMIT();
            idx++;
        }
        const uint32_t sb = smb + (cch & (DEPTH - 1)) * STAGE;
#pragma unroll
        for (int kk = 0; kk < 2; kk++) {
            uint32_t a[2][4], b[NTL][2];
#pragma unroll
            for (int mt = 0; mt < 2; mt++)
                LDSM_X4(a[mt][0], a[mt][1], a[mt][2], a[mt][3], sb + ldAo[mt][kk]);
#pragma unroll
            for (int np = 0; np < NPAIR; np++)
                LDSM_X4(b[2 * np][0], b[2 * np][1], b[2 * np + 1][0], b[2 * np + 1][1],
                        sb + ldBo[np][kk]);
#pragma unroll
            for (int mt = 0; mt < 2; mt++)
#pragma unroll
                for (int nt = 0; nt < NTL; nt++)
                    MMA_F16(acc[mt][nt], a[mt], b[nt]);
        }
    }

    const int gid = lane >> 2, t4 = lane & 3;
#pragma unroll
    for (int mt = 0; mt < 2; mt++) {
        const int r1 = row0 + wRow + mt * 16 + gid;
        const long long ro1 = coff + (long long)r1 * ldc;
        const long long ro2 = ro1 + 8LL * ldc;
#pragma unroll
        for (int nt = 0; nt < NTL; nt++) {
            const int cc = col0 + wCol + nt * 8 + t4 * 2;
            const float b0 = bias ? bias[cc] : 0.f;
            const float b1 = bias ? bias[cc + 1] : 0.f;
            float v0 = acc[mt][nt][0] * alpha + b0;
            float v1 = acc[mt][nt][1] * alpha + b1;
            float v2 = acc[mt][nt][2] * alpha + b0;
            float v3 = acc[mt][nt][3] * alpha + b1;
            if constexpr (OUT == 0) {
                float* C = (float*)Cptr;
                *(float2*)(C + ro1 + cc) = make_float2(v0, v1);
                *(float2*)(C + ro2 + cc) = make_float2(v2, v3);
            } else {
                if constexpr (OUT == 2) {
                    v0 = fmaxf(v0, 0.f); v1 = fmaxf(v1, 0.f);
                    v2 = fmaxf(v2, 0.f); v3 = fmaxf(v3, 0.f);
                }
                __half* C = (__half*)Cptr;
                ushort2 o1, o2;
                o1.x = hfu(v0); o1.y = hfu(v1);
                o2.x = hfu(v2); o2.y = hfu(v3);
                *(ushort2*)(C + ro1 + cc) = o1;
                *(ushort2*)(C + ro2 + cc) = o2;
            }
        }
    }
}

// ======================= flash attention: KV-block 64, occupancy 2 =======================
__global__ __launch_bounds__(256, 2)
void flash_k(const __half* __restrict__ QKV, const __half* __restrict__ VT,
             const int* __restrict__ mask, __half* __restrict__ CTX)
{
    constexpr int QLD   = 3 * DM;
    constexpr int CH128 = 8192;
    constexpr int CH64  = 4096;
    constexpr int QOFF  = 0;
    constexpr int ST0   = 16384;
    constexpr int VOFF  = 8192;
    constexpr int MOFF  = 16384;
    constexpr int STSZ  = 16640;
    constexpr int NJ    = SEQ / 64;
    constexpr float SCL = 0.125f;
    constexpr float L2E = 1.44269504f;

    extern __shared__ char sm[];
    const uint32_t smb = smem_u32(sm);

    const int tid = threadIdx.x;
    const int wid = tid >> 5, lane = tid & 31;
    const int gid = lane >> 2, t4 = lane & 3;
    const int qb = blockIdx.x, z = blockIdx.y;
    const int b = z >> 4, h = z & 15;

    const int rr = tid >> 2, cc4 = tid & 3;
    const size_t qrow0 = (size_t)(b * SEQ + qb * 128);
    const __half* Qg  = QKV + (qrow0 + rr) * QLD + h * DKH + cc4 * 8;
    const __half* Kg0 = QKV + ((size_t)b * SEQ + rr) * QLD + DM + h * DKH + cc4 * 8;
    const __half* Vg0 = VT + ((size_t)z * DKH + rr) * SEQ + cc4 * 8;
    const uint32_t physrc = phys(rr, cc4);

    auto issue_stage = [&](int jb, int st) {
        const uint32_t sb = smb + ST0 + st * STSZ;
        const __half* kgb = Kg0 + (size_t)jb * 64 * QLD;
#pragma unroll
        for (int kc = 0; kc < 2; kc++)
            CP_ASYNC(sb + kc * CH64 + physrc, kgb + kc * 32);
        const __half* vgb = Vg0 + jb * 64;
#pragma unroll
        for (int kc = 0; kc < 2; kc++)
            CP_ASYNC(sb + VOFF + kc * CH64 + physrc, vgb + kc * 32);
        if (tid < 16)
            CP_ASYNC(sb + MOFF + tid * 16, mask + (size_t)b * SEQ + jb * 64 + tid * 4);
    };

#pragma unroll
    for (int kc = 0; kc < 2; kc++)
#pragma unroll
        for (int it = 0; it < 2; it++)
            CP_ASYNC(smb + QOFF + kc * CH128 + physrc + it * 32 * 128,
                     Qg + (size_t)it * 64 * QLD + kc * 32);
    issue_stage(0, 0);
    CP_COMMIT();
    issue_stage(1, 1);
    CP_COMMIT();
    CP_WAIT(1);
    __syncthreads();

    uint32_t qa[4][4];
    {
        const uint32_t qbase0 = phys(lane & 15, (lane >> 4)) + wid * 1024;
        const uint32_t qbase1 = phys(lane & 15, 2 + (lane >> 4)) + wid * 1024;
#pragma unroll
        for (int kc = 0; kc < 2; kc++) {
            LDSM_X4(qa[kc * 2][0], qa[kc * 2][1], qa[kc * 2][2], qa[kc * 2][3],
                    smb + QOFF + kc * CH128 + qbase0);
            LDSM_X4(qa[kc * 2 + 1][0], qa[kc * 2 + 1][1], qa[kc * 2 + 1][2], qa[kc * 2 + 1][3],
                    smb + QOFF + kc * CH128 + qbase1);
        }
    }

    const uint32_t bb0 = phys(((lane >> 4) << 3) + (lane & 7), ((lane >> 3) & 1));
    const uint32_t bb1 = phys(((lane >> 4) << 3) + (lane & 7), 2 + ((lane >> 3) & 1));

    float O[8][4];
#pragma unroll
    for (int i = 0; i < 8; i++)
#pragma unroll
        for (int j = 0; j < 4; j++) O[i][j] = 0.f;
    float m0 = -1e30f, m1 = -1e30f, l0 = 0.f, l1 = 0.f;

    for (int j = 0; j < NJ; j++) {
        const uint32_t sb = smb + ST0 + (j & 1) * STSZ;
        const int* msm = (const int*)(sm + ST0 + (j & 1) * STSZ + MOFF);

        float s[8][4];
#pragma unroll
        for (int i = 0; i < 8; i++)
#pragma unroll
            for (int k = 0; k < 4; k++) s[i][k] = 0.f;
#pragma unroll
        for (int kidx = 0; kidx < 4; kidx++) {
            const uint32_t cb = sb + (kidx >> 1) * CH64 + ((kidx & 1) ? bb1 : bb0);
#pragma unroll
            for (int np = 0; np < 4; np++) {
                uint32_t r0, r1, r2, r3;
                LDSM_X4(r0, r1, r2, r3, cb + np * 1024);
                uint32_t p0[2] = {r0, r1}, p1[2] = {r2, r3};
                MMA_F16(s[2 * np], qa[kidx], p0);
                MMA_F16(s[2 * np + 1], qa[kidx], p1);
            }
        }

        float mx0 = -1e30f, mx1 = -1e30f;
#pragma unroll
        for (int nt = 0; nt < 8; nt++) {
            const int c0 = nt * 8 + t4 * 2;
            const float a0 = msm[c0] ? 0.f : -1e9f;
            const float a1 = msm[c0 + 1] ? 0.f : -1e9f;
            s[nt][0] = s[nt][0] * SCL + a0;
            s[nt][1] = s[nt][1] * SCL + a1;
            s[nt][2] = s[nt][2] * SCL + a0;
            s[nt][3] = s[nt][3] * SCL + a1;
            mx0 = fmaxf(mx0, fmaxf(s[nt][0], s[nt][1]));
            mx1 = fmaxf(mx1, fmaxf(s[nt][2], s[nt][3]));
        }
        mx0 = fmaxf(mx0, __shfl_xor_sync(0xffffffffu, mx0, 1));
        mx0 = fmaxf(mx0, __shfl_xor_sync(0xffffffffu, mx0, 2));
        mx1 = fmaxf(mx1, __shfl_xor_sync(0xffffffffu, mx1, 1));
        mx1 = fmaxf(mx1, __shfl_xor_sync(0xffffffffu, mx1, 2));

        const float nm0 = fmaxf(m0, mx0), nm1 = fmaxf(m1, mx1);
        const float al0 = exp2f((m0 - nm0) * L2E), al1 = exp2f((m1 - nm1) * L2E);
        m0 = nm0; m1 = nm1;

        float sum0 = 0.f, sum1 = 0.f;
#pragma unroll
        for (int nt = 0; nt < 8; nt++) {
            s[nt][0] = exp2f((s[nt][0] - nm0) * L2E);
            s[nt][1] = exp2f((s[nt][1] - nm0) * L2E);
            s[nt][2] = exp2f((s[nt][2] - nm1) * L2E);
            s[nt][3] = exp2f((s[nt][3] - nm1) * L2E);
            sum0 += s[nt][0] + s[nt][1];
            sum1 += s[nt][2] + s[nt][3];
        }
        sum0 += __shfl_xor_sync(0xffffffffu, sum0, 1);
        sum0 += __shfl_xor_sync(0xffffffffu, sum0, 2);
        sum1 += __shfl_xor_sync(0xffffffffu, sum1, 1);
        sum1 += __shfl_xor_sync(0xffffffffu, sum1, 2);
        l0 = l0 * al0 + sum0;
        l1 = l1 * al1 + sum1;
#pragma unroll
        for (int i = 0; i < 8; i++) {
            O[i][0] *= al0; O[i][1] *= al0;
            O[i][2] *= al1; O[i][3] *= al1;
        }

#pragma unroll
        for (int kt = 0; kt < 4; kt++) {
            uint32_t pa[4];
            PACK_F16X2(pa[0], s[2 * kt][0], s[2 * kt][1]);
            PACK_F16X2(pa[1], s[2 * kt][2], s[2 * kt][3]);
            PACK_F16X2(pa[2], s[2 * kt + 1][0], s[2 * kt + 1][1]);
            PACK_F16X2(pa[3], s[2 * kt + 1][2], s[2 * kt + 1][3]);
            const uint32_t vb = sb + VOFF + (kt >> 1) * CH64 + ((kt & 1) ? bb1 : bb0);
#pragma unroll
            for (int np = 0; np < 4; np++) {
                uint32_t r0, r1, r2, r3;
                LDSM_X4(r0, r1, r2, r3, vb + np * 1024);
                uint32_t p0[2] = {r0, r1}, p1[2] = {r2, r3};
                MMA_F16(O[2 * np], pa, p0);
                MMA_F16(O[2 * np + 1], pa, p1);
            }
        }

        __syncthreads();
        if (j + 2 < NJ) { issue_stage(j + 2, j & 1); CP_COMMIT(); CP_WAIT(1); }
        else if (j + 1 < NJ) { CP_WAIT(0); }
        __syncthreads();
    }

    const float inv0 = 1.f / l0, inv1 = 1.f / l1;
    const int q0 = qb * 128 + wid * 16 + gid;
    __half* C1 = CTX + ((size_t)(b * SEQ + q0)) * DM + h * DKH;
    __half* C2 = C1 + 8 * DM;
#pragma unroll
    for (int nt = 0; nt < 8; nt++) {
        const int cc = nt * 8 + t4 * 2;
        ushort2 o1, o2;
        o1.x = hfu(O[nt][0] * inv0); o1.y = hfu(O[nt][1] * inv0);
        o2.x = hfu(O[nt][2] * inv1); o2.y = hfu(O[nt][3] * inv1);
        *(ushort2*)(C1 + cc) = o1;
        *(ushort2*)(C2 + cc) = o2;
    }
}

// ======================= prologue kernels =======================
__global__ void f32_to_half_k(const float* __restrict__ in, __half* __restrict__ out, int n4)
{
    int i = blockIdx.x * 256 + threadIdx.x;
    if (i < n4) {
        float4 v = *(const float4*)(in + (size_t)i * 4);
        ushort4 o;
        o.x = hfu(v.x); o.y = hfu(v.y); o.z = hfu(v.z); o.w = hfu(v.w);
        *(ushort4*)(out + (size_t)i * 4) = o;
    }
}

// ALL weight transposes in one launch (flat 1D grid of 32x32 tiles) + bias concat.
// blocks [0,4096): Wq/Wk/Wv/Wo (DM x DM); [4096,8192): W1 (DM x DFF); [8192,12288): W2 (DFF x DM).
__global__ void prep_w_k(const float* __restrict__ Wq, const float* __restrict__ Wk,
                         const float* __restrict__ Wv, const float* __restrict__ Wo,
                         const float* __restrict__ W1, const float* __restrict__ W2,
                         __half* __restrict__ WQKVT, __half* __restrict__ WOT,
                         __half* __restrict__ W1T, __half* __restrict__ W2T,
                         const float* __restrict__ bq, const float* __restrict__ bk,
                         const float* __restrict__ bv, float* __restrict__ BQKV)
{
    __shared__ float t[32][33];
    const int idx = blockIdx.x;
    const int tx = threadIdx.x, ty = threadIdx.y;
    const int lt = ty * 32 + tx;

    if (idx == 0) {
        for (int i = lt; i < DM; i += 256) {
            BQKV[i] = bq[i];
            BQKV[i + DM] = bk[i];
            BQKV[i + 2 * DM] = bv[i];
        }
    }

    const float* in;
    __half* out;
    int K, N, n0, k0;
    if (idx < 4096) {
        const int w = idx >> 10, tile = idx & 1023;
        in = (w == 0) ? Wq : (w == 1) ? Wk : (w == 2) ? Wv : Wo;
        out = (w == 3) ? WOT : WQKVT + (size_t)w * DM * DM;
        K = DM; N = DM;
        n0 = (tile & 31) * 32; k0 = (tile >> 5) * 32;
    } else if (idx < 8192) {
        const int tile = idx - 4096;
        in = W1; out = W1T; K = DM; N = DFF;
        n0 = (tile & 127) * 32; k0 = (tile >> 7) * 32;
    } else {
        const int tile = idx - 8192;
        in = W2; out = W2T; K = DFF; N = DM;
        n0 = (tile & 31) * 32; k0 = (tile >> 5) * 32;
    }

    for (int j = ty; j < 32; j += 8) t[j][tx] = in[(size_t)(k0 + j) * N + n0 + tx];
    __syncthreads();
    for (int j = ty; j < 32; j += 8)
        out[(size_t)(n0 + j) * K + k0 + tx] = __float2half_rn(t[tx][j]);
}

__global__ void vt_k(const __half* __restrict__ QKV, __half* __restrict__ VT)
{
    __shared__ __half t[32][33];
    int z = blockIdx.z, b = z >> 4, h = z & 15;
    int s0 = blockIdx.x * 32, d0 = blockIdx.y * 32;
    int tx = threadIdx.x, ty = threadIdx.y;
    for (int j = ty; j < 32; j += 8)
        t[j][tx] = QKV[(size_t)(b * SEQ + s0 + j) * (3 * DM) + 2 * DM + h * DKH + d0 + tx];
    __syncthreads();
    for (int j = ty; j < 32; j += 8)
        VT[((size_t)z * DKH + d0 + j) * SEQ + s0 + tx] = t[tx][j];
}

// ======================= reductions / LN =======================
__device__ __forceinline__ float blkSum(float v, float* red)
{
#pragma unroll
    for (int o = 16; o > 0; o >>= 1) v += __shfl_xor_sync(0xffffffffu, v, o);
    int w = threadIdx.x >> 5, l = threadIdx.x & 31;
    if (l == 0) red[w] = v;
    __syncthreads();
    if (threadIdx.x < 8) {
        v = red[threadIdx.x];
#pragma unroll
        for (int o = 4; o > 0; o >>= 1) v += __shfl_xor_sync(0xffu, v, o);
        if (threadIdx.x == 0) red[0] = v;
    }
    __syncthreads();
    float r = red[0];
    __syncthreads();
    return r;
}

template<bool EMIT_H>
__global__ void addln_k(const float* __restrict__ a, const float* __restrict__ bres,
                        const float* __restrict__ g, const float* __restrict__ be,
                        float* __restrict__ out, __half* __restrict__ outh)
{
    __shared__ float red[32];
    const long long row = blockIdx.x;
    const float* pa = a + row * DM;
    const float* pb = bres + row * DM;
    const int tid = threadIdx.x;
    float v[4], s = 0.f, s2 = 0.f;
#pragma unroll
    for (int j = 0; j < 4; j++) {
        int c = tid + j * 256;
        float t = pa[c] + pb[c];
        v[j] = t; s += t; s2 += t * t;
    }
    s = blkSum(s, red);
    s2 = blkSum(s2, red);
    float mu = s * (1.f / DM);
    float var = s2 * (1.f / DM) - mu * mu;
    float inv = rsqrtf(var + 1e-5f);
#pragma unroll
    for (int j = 0; j < 4; j++) {
        int c = tid + j * 256;
        float o = (v[j] - mu) * inv * g[c] + be[c];
        out[row * DM + c] = o;
        if (EMIT_H) outh[row * DM + c] = __float2half_rn(o);
    }
}

// ======================= launch =======================
extern "C" void kernel_launch(void* const* d_in, const int* in_sizes, int n_in,
                              void* d_out, int out_size)
{
    const float* x    = (const float*)d_in[0];
    const int*   mask = (const int*)  d_in[1];
    const float* Wq = (const float*)d_in[2];  const float* bq = (const float*)d_in[3];
    const float* Wk = (const float*)d_in[4];  const float* bk = (const float*)d_in[5];
    const float* Wv = (const float*)d_in[6];  const float* bv = (const float*)d_in[7];
    const float* Wo = (const float*)d_in[8];  const float* bo = (const float*)d_in[9];
    const float* W1 = (const float*)d_in[10]; const float* b1 = (const float*)d_in[11];
    const float* W2 = (const float*)d_in[12]; const float* b2 = (const float*)d_in[13];
    const float* g1 = (const float*)d_in[14]; const float* be1 = (const float*)d_in[15];
    const float* g2 = (const float*)d_in[16]; const float* be2 = (const float*)d_in[17];
    float* out = (float*)d_out;

    float *TMP, *H, *BQKV;
    __half *XH, *QKV, *VT, *CTX, *WQKVT, *WOT, *W1T, *W2T, *HH, *FF;
    cudaGetSymbolAddress((void**)&TMP, g_tmp);
    cudaGetSymbolAddress((void**)&H, g_h);
    cudaGetSymbolAddress((void**)&XH, g_xh);
    cudaGetSymbolAddress((void**)&QKV, g_qkv);
    cudaGetSymbolAddress((void**)&VT, g_VT);
    cudaGetSymbolAddress((void**)&CTX, g_ctx);
    cudaGetSymbolAddress((void**)&WQKVT, g_WqkvT);
    cudaGetSymbolAddress((void**)&WOT, g_WoT);
    cudaGetSymbolAddress((void**)&W1T, g_W1T);
    cudaGetSymbolAddress((void**)&W2T, g_W2T);
    cudaGetSymbolAddress((void**)&HH, g_hh);
    cudaGetSymbolAddress((void**)&FF, g_ff);
    cudaGetSymbolAddress((void**)&BQKV, g_bqkv);

    const int SM128 = 4 * (128 + 128) * 64;   // 65536
    const int SMFL  = 16384 + 2 * 16640;      // 49664
    cudaFuncSetAttribute(mma_gemm<128, 0>, cudaFuncAttributeMaxDynamicSharedMemorySize, SM128);
    cudaFuncSetAttribute(mma_gemm<128, 1>, cudaFuncAttributeMaxDynamicSharedMemorySize, SM128);
    cudaFuncSetAttribute(mma_gemm<128, 2>, cudaFuncAttributeMaxDynamicSharedMemorySize, SM128);
    cudaFuncSetAttribute(flash_k, cudaFuncAttributeMaxDynamicSharedMemorySize, SMFL);

    const dim3 t32(32, 8);

    // launch 1: x -> half
    f32_to_half_k<<<(NT * DM / 4 + 255) / 256, 256>>>(x, XH, NT * DM / 4);
    // launch 2: ALL weight transposes + bias concat
    prep_w_k<<<12288, t32>>>(Wq, Wk, Wv, Wo, W1, W2, WQKVT, WOT, W1T, W2T, bq, bk, bv, BQKV);

    // launch 3: fused QKV projection (ncu capture target)
    {
        dim3 g(3 * DM / 128, NT / 128, 1);
        mma_gemm<128, 1><<<g, 256, SM128>>>(XH, WQKVT, BQKV, (char*)QKV, DM, DM, DM, 3 * DM,
                                            0, 0, 0, 0, 0, 0, 1, 1.f);
    }
    // launch 4: V transpose per head
    vt_k<<<dim3(SEQ / 32, DKH / 32, 64), t32>>>(QKV, VT);
    // launch 5: flash attention
    flash_k<<<dim3(SEQ / 128, 64), 256, SMFL>>>(QKV, VT, mask, CTX);
    // launch 6: attn_out = ctx @ Wo + bo
    {
        dim3 g(DM / 128, NT / 128, 1);
        mma_gemm<128, 0><<<g, 256, SM128>>>(CTX, WOT, bo, (char*)TMP, DM, DM, DM, DM,
                                            0, 0, 0, 0, 0, 0, 1, 1.f);
    }
    // launch 7: LN1
    addln_k<true><<<NT, 256>>>(x, TMP, g1, be1, H, HH);
    // launch 8: FFN1
    {
        dim3 g(DFF / 128, NT / 128, 1);
        mma_gemm<128, 2><<<g, 256, SM128>>>(HH, W1T, b1, (char*)FF, DM, DM, DM, DFF,
                                            0, 0, 0, 0, 0, 0, 1, 1.f);
    }
    // launch 9: FFN2
    {
        dim3 g(DM / 128, NT / 128, 1);
        mma_gemm<128, 0><<<g, 256, SM128>>>(FF, W2T, b2, (char*)TMP, DFF, DFF, DFF, DM,
                                            0, 0, 0, 0, 0, 0, 1, 1.f);
    }
    // launch 10: LN2
    addln_k<false><<<NT, 256>>>(H, TMP, g2, be2, out, nullptr);
}

// round 9
// speedup vs baseline: 6.6392x; 1.0185x over previous
#include <cuda_runtime.h>
#include <cuda_fp16.h>
#include <cstdint>

#define BATCH 4
#define SEQ   1024
#define NT    4096
#define DM    1024
#define NH    16
#define DKH   64
#define DFF   4096

// ======================= device scratch =======================
__device__ __align__(16) float g_tmp[(size_t)NT * DM];
__device__ __align__(16) float g_h[(size_t)NT * DM];
__device__ __align__(16) __half g_xh [(size_t)NT * DM];
__device__ __align__(16) __half g_qkv[(size_t)NT * 3 * DM];
__device__ __align__(16) __half g_ctx[(size_t)NT * DM];
__device__ __align__(16) __half g_WqkvT[(size_t)3 * DM * DM];
__device__ __align__(16) __half g_WoT[(size_t)DM * DM];
__device__ __align__(16) __half g_W1T[(size_t)DFF * DM];
__device__ __align__(16) __half g_W2T[(size_t)DM * DFF];
__device__ __align__(16) __half g_hh [(size_t)NT * DM];
__device__ __align__(16) __half g_ff [(size_t)NT * DFF];
__device__ __align__(16) float  g_bqkv[3 * DM];

// ======================= asm helpers (compute_80-level only) =======================
__device__ __forceinline__ uint32_t smem_u32(const void* p) {
    uint32_t a;
    asm("{ .reg .u64 t; cvta.to.shared.u64 t, %1; cvt.u32.u64 %0, t; }" : "=r"(a) : "l"(p));
    return a;
}
#define CP_ASYNC(s, g) \
    asm volatile("cp.async.cg.shared.global [%0], [%1], 16;" :: "r"(s), "l"(g) : "memory")
#define CP_COMMIT() asm volatile("cp.async.commit_group;" ::: "memory")
#define CP_WAIT(n)  asm volatile("cp.async.wait_group %0;" :: "n"(n) : "memory")

#define LDSM_X4(r0, r1, r2, r3, a) \
    asm volatile("ldmatrix.sync.aligned.m8n8.x4.shared.b16 {%0,%1,%2,%3}, [%4];" \
        : "=r"(r0), "=r"(r1), "=r"(r2), "=r"(r3) : "r"(a))

#define LDSM_X4_T(r0, r1, r2, r3, a) \
    asm volatile("ldmatrix.sync.aligned.m8n8.x4.trans.shared.b16 {%0,%1,%2,%3}, [%4];" \
        : "=r"(r0), "=r"(r1), "=r"(r2), "=r"(r3) : "r"(a))

#define MMA_F16(d, a, b) \
    asm volatile("mma.sync.aligned.m16n8k16.row.col.f32.f16.f16.f32 " \
        "{%0,%1,%2,%3}, {%4,%5,%6,%7}, {%8,%9}, {%0,%1,%2,%3};" \
        : "+f"((d)[0]), "+f"((d)[1]), "+f"((d)[2]), "+f"((d)[3]) \
        : "r"((a)[0]), "r"((a)[1]), "r"((a)[2]), "r"((a)[3]), "r"((b)[0]), "r"((b)[1]))

#define PACK_F16X2(r, flo, fhi) \
    asm("cvt.rn.f16x2.f32 %0, %1, %2;" : "=r"(r) : "f"(fhi), "f"(flo))

// swizzled smem layout for 32-element (64B) k-chunks. phys(r+16,c)==phys(r,c)+1024.
__device__ __forceinline__ uint32_t phys(uint32_t r, uint32_t c) {
    return (r >> 1) * 128 + ((((r & 1) << 2) | c) ^ ((r >> 1) & 7)) * 16;
}
__device__ __forceinline__ unsigned short hfu(float v) {
    return __half_as_ushort(__float2half_rn(v));
}

// ======================= mma.sync batched GEMM (fp16 in, f32 acc) =======================
template<int BN, int OUT>
__global__ __launch_bounds__(256, 2)
void mma_gemm(const __half* __restrict__ A, const __half* __restrict__ B,
              const float* __restrict__ bias, char* __restrict__ Cptr,
              int K, int lda, int ldb, int ldc,
              long long sAb, long long sAh, long long sBb, long long sBh,
              long long sCb, long long sCh, int nH, float alpha)
{
    constexpr int DEPTH  = 4;
    constexpr int ABYTES = 128 * 64;
    constexpr int BBYTES = BN * 64;
    constexpr int STAGE  = ABYTES + BBYTES;
    constexpr int WN     = BN / 2;
    constexpr int NTL    = WN / 8;
    constexpr int NPAIR  = NTL / 2;
    constexpr int AIT    = 2;
    constexpr int BIT    = (BN * 4) / 256;

    extern __shared__ char sm[];
    const uint32_t smb = smem_u32(sm);

    const int tid = threadIdx.x;
    const int wid = tid >> 5, lane = tid & 31;
    const int wRow = (wid & 3) * 32;
    const int wCol = (wid >> 2) * WN;
    const int z = blockIdx.z, zb = z / nH, zh = z - zb * nH;
    A += zb * sAb + zh * sAh;
    B += zb * sBb + zh * sBh;
    const long long coff = zb * sCb + zh * sCh;
    const int row0 = blockIdx.y * 128;
    const int col0 = blockIdx.x * BN;

    const __half* Ag[AIT]; uint32_t Asm[AIT];
#pragma unroll
    for (int i = 0; i < AIT; i++) {
        int r = (tid >> 2) + i * 64, c = tid & 3;
        Ag[i]  = A + (size_t)(row0 + r) * lda + c * 8;
        Asm[i] = phys(r, c);
    }
    const __half* Bg[BIT]; uint32_t Bsm[BIT];
#pragma unroll
    for (int i = 0; i < BIT; i++) {
        int r = (tid >> 2) + i * 64, c = tid & 3;
        Bg[i]  = B + (size_t)(col0 + r) * ldb + c * 8;
        Bsm[i] = ABYTES + phys(r, c);
    }
    uint32_t ldAo[2][2], ldBo[NPAIR][2];
#pragma unroll
    for (int mt = 0; mt < 2; mt++)
#pragma unroll
        for (int kk = 0; kk < 2; kk++)
            ldAo[mt][kk] = phys(wRow + mt * 16 + (lane & 15), kk * 2 + (lane >> 4));
#pragma unroll
    for (int np = 0; np < NPAIR; np++)
#pragma unroll
        for (int kk = 0; kk < 2; kk++)
            ldBo[np][kk] = ABYTES + phys(wCol + np * 16 + ((lane >> 4) << 3) + (lane & 7),
                                         kk * 2 + ((lane >> 3) & 1));

    float acc[2][NTL][4];
#pragma unroll
    for (int i = 0; i < 2; i++)
#pragma unroll
        for (int j = 0; j < NTL; j++)
#pragma unroll
            for (int k = 0; k < 4; k++) acc[i][j][k] = 0.f;

    const int NC = K / 32;
    const int PRE = NC < (DEPTH - 1) ? NC : (DEPTH - 1);
    for (int s = 0; s < PRE; s++) {
#pragma unroll
        for (int i = 0; i < AIT; i++) CP_ASYNC(smb + s * STAGE + Asm[i], Ag[i] + s * 32);
#pragma unroll
        for (int i = 0; i < BIT; i++) CP_ASYNC(smb + s * STAGE + Bsm[i], Bg[i] + s * 32);
        CP_COMMIT();
    }
    int idx = PRE;
    for (int cch = 0; cch < NC; cch++) {
        const int rem = NC - 1 - cch;
        if (rem >= 2) { CP_WAIT(2); } else if (rem == 1) { CP_WAIT(1); } else { CP_WAIT(0); }
        __syncthreads();
        if (idx < NC) {
            const int s = idx & (DEPTH - 1);
#pragma unroll
            for (int i = 0; i < AIT; i++) CP_ASYNC(smb + s * STAGE + Asm[i], Ag[i] + idx * 32);
#pragma unroll
            for (int i = 0; i < BIT; i++) CP_ASYNC(smb + s * STAGE + Bsm[i], Bg[i] + idx * 32);
            CP_COMMIT();
            idx++;
        }
        const uint32_t sb = smb + (cch & (DEPTH - 1)) * STAGE;
#pragma unroll
        for (int kk = 0; kk < 2; kk++) {
            uint32_t a[2][4], b[NTL][2];
#pragma unroll
            for (int mt = 0; mt < 2; mt++)
                LDSM_X4(a[mt][0], a[mt][1], a[mt][2], a[mt][3], sb + ldAo[mt][kk]);
#pragma unroll
            for (int np = 0; np < NPAIR; np++)
                LDSM_X4(b[2 * np][0], b[2 * np][1], b[2 * np + 1][0], b[2 * np + 1][1],
                        sb + ldBo[np][kk]);
#pragma unroll
            for (int mt = 0; mt < 2; mt++)
#pragma unroll
                for (int nt = 0; nt < NTL; nt++)
                    MMA_F16(acc[mt][nt], a[mt], b[nt]);
        }
    }

    const int gid = lane >> 2, t4 = lane & 3;
#pragma unroll
    for (int mt = 0; mt < 2; mt++) {
        const int r1 = row0 + wRow + mt * 16 + gid;
        const long long ro1 = coff + (long long)r1 * ldc;
        const long long ro2 = ro1 + 8LL * ldc;
#pragma unroll
        for (int nt = 0; nt < NTL; nt++) {
            const int cc = col0 + wCol + nt * 8 + t4 * 2;
            const float b0 = bias ? bias[cc] : 0.f;
            const float b1 = bias ? bias[cc + 1] : 0.f;
            float v0 = acc[mt][nt][0] * alpha + b0;
            float v1 = acc[mt][nt][1] * alpha + b1;
            float v2 = acc[mt][nt][2] * alpha + b0;
            float v3 = acc[mt][nt][3] * alpha + b1;
            if constexpr (OUT == 0) {
                float* C = (float*)Cptr;
                *(float2*)(C + ro1 + cc) = make_float2(v0, v1);
                *(float2*)(C + ro2 + cc) = make_float2(v2, v3);
            } else {
                if constexpr (OUT == 2) {
                    v0 = fmaxf(v0, 0.f); v1 = fmaxf(v1, 0.f);
                    v2 = fmaxf(v2, 0.f); v3 = fmaxf(v3, 0.f);
                }
                __half* C = (__half*)Cptr;
                ushort2 o1, o2;
                o1.x = hfu(v0); o1.y = hfu(v1);
                o2.x = hfu(v2); o2.y = hfu(v3);
                *(ushort2*)(C + ro1 + cc) = o1;
                *(ushort2*)(C + ro2 + cc) = o2;
            }
        }
    }
}

// ======================= flash attention: KV-block 64, V via ldmatrix.trans =======================
// grid (SEQ/128, BATCH*NH), 256 threads (8 warps x 16 q-rows). K and V both from fused QKV.
__global__ __launch_bounds__(256, 2)
void flash_k(const __half* __restrict__ QKV, const int* __restrict__ mask,
             __half* __restrict__ CTX)
{
    constexpr int QLD   = 3 * DM;
    constexpr int CH128 = 8192;
    constexpr int CH64  = 4096;
    constexpr int QOFF  = 0;
    constexpr int ST0   = 16384;
    constexpr int VOFF  = 8192;
    constexpr int MOFF  = 16384;
    constexpr int STSZ  = 16640;
    constexpr int NJ    = SEQ / 64;
    constexpr float SCL = 0.125f;
    constexpr float L2E = 1.44269504f;

    extern __shared__ char sm[];
    const uint32_t smb = smem_u32(sm);

    const int tid = threadIdx.x;
    const int wid = tid >> 5, lane = tid & 31;
    const int gid = lane >> 2, t4 = lane & 3;
    const int qb = blockIdx.x, z = blockIdx.y;
    const int b = z >> 4, h = z & 15;

    const int rr = tid >> 2, cc4 = tid & 3;
    const size_t qrow0 = (size_t)(b * SEQ + qb * 128);
    const __half* Qg  = QKV + (qrow0 + rr) * QLD + h * DKH + cc4 * 8;
    const __half* Kg0 = QKV + ((size_t)b * SEQ + rr) * QLD + DM + h * DKH + cc4 * 8;
    const __half* Vg0 = QKV + ((size_t)b * SEQ + rr) * QLD + 2 * DM + h * DKH + cc4 * 8;
    const uint32_t physrc = phys(rr, cc4);

    auto issue_stage = [&](int jb, int st) {
        const uint32_t sb = smb + ST0 + st * STSZ;
        const __half* kgb = Kg0 + (size_t)jb * 64 * QLD;
#pragma unroll
        for (int kc = 0; kc < 2; kc++)
            CP_ASYNC(sb + kc * CH64 + physrc, kgb + kc * 32);
        const __half* vgb = Vg0 + (size_t)jb * 64 * QLD;
#pragma unroll
        for (int kc = 0; kc < 2; kc++)
            CP_ASYNC(sb + VOFF + kc * CH64 + physrc, vgb + kc * 32);
        if (tid < 16)
            CP_ASYNC(sb + MOFF + tid * 16, mask + (size_t)b * SEQ + jb * 64 + tid * 4);
    };

#pragma unroll
    for (int kc = 0; kc < 2; kc++)
#pragma unroll
        for (int it = 0; it < 2; it++)
            CP_ASYNC(smb + QOFF + kc * CH128 + physrc + it * 32 * 128,
                     Qg + (size_t)it * 64 * QLD + kc * 32);
    issue_stage(0, 0);
    CP_COMMIT();
    issue_stage(1, 1);
    CP_COMMIT();
    CP_WAIT(1);
    __syncthreads();

    uint32_t qa[4][4];
    {
        const uint32_t qbase0 = phys(lane & 15, (lane >> 4)) + wid * 1024;
        const uint32_t qbase1 = phys(lane & 15, 2 + (lane >> 4)) + wid * 1024;
#pragma unroll
        for (int kc = 0; kc < 2; kc++) {
            LDSM_X4(qa[kc * 2][0], qa[kc * 2][1], qa[kc * 2][2], qa[kc * 2][3],
                    smb + QOFF + kc * CH128 + qbase0);
            LDSM_X4(qa[kc * 2 + 1][0], qa[kc * 2 + 1][1], qa[kc * 2 + 1][2], qa[kc * 2 + 1][3],
                    smb + QOFF + kc * CH128 + qbase1);
        }
    }

    // K B-fragment bases (non-trans, K stored [s][d], fragment rows = s via col-pattern)
    const uint32_t bb0 = phys(((lane >> 4) << 3) + (lane & 7), ((lane >> 3) & 1));
    const uint32_t bb1 = phys(((lane >> 4) << 3) + (lane & 7), 2 + ((lane >> 3) & 1));
    // V B-fragment bases (trans: lane l -> s row (l&15), d block (l>>4)*8)
    const uint32_t vtb0 = phys(lane & 15, (lane >> 4));
    const uint32_t vtb1 = phys(lane & 15, 2 + (lane >> 4));

    float O[8][4];
#pragma unroll
    for (int i = 0; i < 8; i++)
#pragma unroll
        for (int j = 0; j < 4; j++) O[i][j] = 0.f;
    float m0 = -1e30f, m1 = -1e30f, l0 = 0.f, l1 = 0.f;

    for (int j = 0; j < NJ; j++) {
        const uint32_t sb = smb + ST0 + (j & 1) * STSZ;
        const int* msm = (const int*)(sm + ST0 + (j & 1) * STSZ + MOFF);

        // ---- S = Q @ K^T (128 x 64) ----
        float s[8][4];
#pragma unroll
        for (int i = 0; i < 8; i++)
#pragma unroll
            for (int k = 0; k < 4; k++) s[i][k] = 0.f;
#pragma unroll
        for (int kidx = 0; kidx < 4; kidx++) {
            const uint32_t cb = sb + (kidx >> 1) * CH64 + ((kidx & 1) ? bb1 : bb0);
#pragma unroll
            for (int np = 0; np < 4; np++) {
                uint32_t r0, r1, r2, r3;
                LDSM_X4(r0, r1, r2, r3, cb + np * 1024);
                uint32_t p0[2] = {r0, r1}, p1[2] = {r2, r3};
                MMA_F16(s[2 * np], qa[kidx], p0);
                MMA_F16(s[2 * np + 1], qa[kidx], p1);
            }
        }

        // ---- mask + scale, row max ----
        float mx0 = -1e30f, mx1 = -1e30f;
#pragma unroll
        for (int nt = 0; nt < 8; nt++) {
            const int c0 = nt * 8 + t4 * 2;
            const float a0 = msm[c0] ? 0.f : -1e9f;
            const float a1 = msm[c0 + 1] ? 0.f : -1e9f;
            s[nt][0] = s[nt][0] * SCL + a0;
            s[nt][1] = s[nt][1] * SCL + a1;
            s[nt][2] = s[nt][2] * SCL + a0;
            s[nt][3] = s[nt][3] * SCL + a1;
            mx0 = fmaxf(mx0, fmaxf(s[nt][0], s[nt][1]));
            mx1 = fmaxf(mx1, fmaxf(s[nt][2], s[nt][3]));
        }
        mx0 = fmaxf(mx0, __shfl_xor_sync(0xffffffffu, mx0, 1));
        mx0 = fmaxf(mx0, __shfl_xor_sync(0xffffffffu, mx0, 2));
        mx1 = fmaxf(mx1, __shfl_xor_sync(0xffffffffu, mx1, 1));
        mx1 = fmaxf(mx1, __shfl_xor_sync(0xffffffffu, mx1, 2));

        const float nm0 = fmaxf(m0, mx0), nm1 = fmaxf(m1, mx1);
        const float al0 = exp2f((m0 - nm0) * L2E), al1 = exp2f((m1 - nm1) * L2E);
        m0 = nm0; m1 = nm1;

        float sum0 = 0.f, sum1 = 0.f;
#pragma unroll
        for (int nt = 0; nt < 8; nt++) {
            s[nt][0] = exp2f((s[nt][0] - nm0) * L2E);
            s[nt][1] = exp2f((s[nt][1] - nm0) * L2E);
            s[nt][2] = exp2f((s[nt][2] - nm1) * L2E);
            s[nt][3] = exp2f((s[nt][3] - nm1) * L2E);
            sum0 += s[nt][0] + s[nt][1];
            sum1 += s[nt][2] + s[nt][3];
        }
        sum0 += __shfl_xor_sync(0xffffffffu, sum0, 1);
        sum0 += __shfl_xor_sync(0xffffffffu, sum0, 2);
        sum1 += __shfl_xor_sync(0xffffffffu, sum1, 1);
        sum1 += __shfl_xor_sync(0xffffffffu, sum1, 2);
        l0 = l0 * al0 + sum0;
        l1 = l1 * al1 + sum1;
#pragma unroll
        for (int i = 0; i < 8; i++) {
            O[i][0] *= al0; O[i][1] *= al0;
            O[i][2] *= al1; O[i][3] *= al1;
        }

        // ---- O += P @ V (V row-major [s][d], B-fragments via ldmatrix.trans) ----
#pragma unroll
        for (int kt = 0; kt < 4; kt++) {
            uint32_t pa[4];
            PACK_F16X2(pa[0], s[2 * kt][0], s[2 * kt][1]);
            PACK_F16X2(pa[1], s[2 * kt][2], s[2 * kt][3]);
            PACK_F16X2(pa[2], s[2 * kt + 1][0], s[2 * kt + 1][1]);
            PACK_F16X2(pa[3], s[2 * kt + 1][2], s[2 * kt + 1][3]);
#pragma unroll
            for (int np = 0; np < 4; np++) {
                uint32_t r0, r1, r2, r3;
                LDSM_X4_T(r0, r1, r2, r3,
                          sb + VOFF + (np >> 1) * CH64 + ((np & 1) ? vtb1 : vtb0) + kt * 1024);
                uint32_t p0[2] = {r0, r1}, p1[2] = {r2, r3};
                MMA_F16(O[2 * np], pa, p0);
                MMA_F16(O[2 * np + 1], pa, p1);
            }
        }

        __syncthreads();
        if (j + 2 < NJ) { issue_stage(j + 2, j & 1); CP_COMMIT(); CP_WAIT(1); }
        else if (j + 1 < NJ) { CP_WAIT(0); }
        __syncthreads();
    }

    const float inv0 = 1.f / l0, inv1 = 1.f / l1;
    const int q0 = qb * 128 + wid * 16 + gid;
    __half* C1 = CTX + ((size_t)(b * SEQ + q0)) * DM + h * DKH;
    __half* C2 = C1 + 8 * DM;
#pragma unroll
    for (int nt = 0; nt < 8; nt++) {
        const int cc = nt * 8 + t4 * 2;
        ushort2 o1, o2;
        o1.x = hfu(O[nt][0] * inv0); o1.y = hfu(O[nt][1] * inv0);
        o2.x = hfu(O[nt][2] * inv1); o2.y = hfu(O[nt][3] * inv1);
        *(ushort2*)(C1 + cc) = o1;
        *(ushort2*)(C2 + cc) = o2;
    }
}

// ======================= prologue kernels =======================
__global__ void f32_to_half_k(const float* __restrict__ in, __half* __restrict__ out, int n4)
{
    int i = blockIdx.x * 256 + threadIdx.x;
    if (i < n4) {
        float4 v = *(const float4*)(in + (size_t)i * 4);
        ushort4 o;
        o.x = hfu(v.x); o.y = hfu(v.y); o.z = hfu(v.z); o.w = hfu(v.w);
        *(ushort4*)(out + (size_t)i * 4) = o;
    }
}

// ALL weight transposes in one launch + bias concat.
__global__ void prep_w_k(const float* __restrict__ Wq, const float* __restrict__ Wk,
                         const float* __restrict__ Wv, const float* __restrict__ Wo,
                         const float* __restrict__ W1, const float* __restrict__ W2,
                         __half* __restrict__ WQKVT, __half* __restrict__ WOT,
                         __half* __restrict__ W1T, __half* __restrict__ W2T,
                         const float* __restrict__ bq, const float* __restrict__ bk,
                         const float* __restrict__ bv, float* __restrict__ BQKV)
{
    __shared__ float t[32][33];
    const int idx = blockIdx.x;
    const int tx = threadIdx.x, ty = threadIdx.y;
    const int lt = ty * 32 + tx;

    if (idx == 0) {
        for (int i = lt; i < DM; i += 256) {
            BQKV[i] = bq[i];
            BQKV[i + DM] = bk[i];
            BQKV[i + 2 * DM] = bv[i];
        }
    }

    const float* in;
    __half* out;
    int K, N, n0, k0;
    if (idx < 4096) {
        const int w = idx >> 10, tile = idx & 1023;
        in = (w == 0) ? Wq : (w == 1) ? Wk : (w == 2) ? Wv : Wo;
        out = (w == 3) ? WOT : WQKVT + (size_t)w * DM * DM;
        K = DM; N = DM;
        n0 = (tile & 31) * 32; k0 = (tile >> 5) * 32;
    } else if (idx < 8192) {
        const int tile = idx - 4096;
        in = W1; out = W1T; K = DM; N = DFF;
        n0 = (tile & 127) * 32; k0 = (tile >> 7) * 32;
    } else {
        const int tile = idx - 8192;
        in = W2; out = W2T; K = DFF; N = DM;
        n0 = (tile & 31) * 32; k0 = (tile >> 5) * 32;
    }

    for (int j = ty; j < 32; j += 8) t[j][tx] = in[(size_t)(k0 + j) * N + n0 + tx];
    __syncthreads();
    for (int j = ty; j < 32; j += 8)
        out[(size_t)(n0 + j) * K + k0 + tx] = __float2half_rn(t[tx][j]);
}

// ======================= reductions / LN =======================
__device__ __forceinline__ float blkSum(float v, float* red)
{
#pragma unroll
    for (int o = 16; o > 0; o >>= 1) v += __shfl_xor_sync(0xffffffffu, v, o);
    int w = threadIdx.x >> 5, l = threadIdx.x & 31;
    if (l == 0) red[w] = v;
    __syncthreads();
    if (threadIdx.x < 8) {
        v = red[threadIdx.x];
#pragma unroll
        for (int o = 4; o > 0; o >>= 1) v += __shfl_xor_sync(0xffu, v, o);
        if (threadIdx.x == 0) red[0] = v;
    }
    __syncthreads();
    float r = red[0];
    __syncthreads();
    return r;
}

template<bool EMIT_H>
__global__ void addln_k(const float* __restrict__ a, const float* __restrict__ bres,
                        const float* __restrict__ g, const float* __restrict__ be,
                        float* __restrict__ out, __half* __restrict__ outh)
{
    __shared__ float red[32];
    const long long row = blockIdx.x;
    const float* pa = a + row * DM;
    const float* pb = bres + row * DM;
    const int tid = threadIdx.x;
    float v[4], s = 0.f, s2 = 0.f;
#pragma unroll
    for (int j = 0; j < 4; j++) {
        int c = tid + j * 256;
        float t = pa[c] + pb[c];
        v[j] = t; s += t; s2 += t * t;
    }
    s = blkSum(s, red);
    s2 = blkSum(s2, red);
    float mu = s * (1.f / DM);
    float var = s2 * (1.f / DM) - mu * mu;
    float inv = rsqrtf(var + 1e-5f);
#pragma unroll
    for (int j = 0; j < 4; j++) {
        int c = tid + j * 256;
        float o = (v[j] - mu) * inv * g[c] + be[c];
        out[row * DM + c] = o;
        if (EMIT_H) outh[row * DM + c] = __float2half_rn(o);
    }
}

// ======================= launch =======================
extern "C" void kernel_launch(void* const* d_in, const int* in_sizes, int n_in,
                              void* d_out, int out_size)
{
    const float* x    = (const float*)d_in[0];
    const int*   mask = (const int*)  d_in[1];
    const float* Wq = (const float*)d_in[2];  const float* bq = (const float*)d_in[3];
    const float* Wk = (const float*)d_in[4];  const float* bk = (const float*)d_in[5];
    const float* Wv = (const float*)d_in[6];  const float* bv = (const float*)d_in[7];
    const float* Wo = (const float*)d_in[8];  const float* bo = (const float*)d_in[9];
    const float* W1 = (const float*)d_in[10]; const float* b1 = (const float*)d_in[11];
    const float* W2 = (const float*)d_in[12]; const float* b2 = (const float*)d_in[13];
    const float* g1 = (const float*)d_in[14]; const float* be1 = (const float*)d_in[15];
    const float* g2 = (const float*)d_in[16]; const float* be2 = (const float*)d_in[17];
    float* out = (float*)d_out;

    float *TMP, *H, *BQKV;
    __half *XH, *QKV, *CTX, *WQKVT, *WOT, *W1T, *W2T, *HH, *FF;
    cudaGetSymbolAddress((void**)&TMP, g_tmp);
    cudaGetSymbolAddress((void**)&H, g_h);
    cudaGetSymbolAddress((void**)&XH, g_xh);
    cudaGetSymbolAddress((void**)&QKV, g_qkv);
    cudaGetSymbolAddress((void**)&CTX, g_ctx);
    cudaGetSymbolAddress((void**)&WQKVT, g_WqkvT);
    cudaGetSymbolAddress((void**)&WOT, g_WoT);
    cudaGetSymbolAddress((void**)&W1T, g_W1T);
    cudaGetSymbolAddress((void**)&W2T, g_W2T);
    cudaGetSymbolAddress((void**)&HH, g_hh);
    cudaGetSymbolAddress((void**)&FF, g_ff);
    cudaGetSymbolAddress((void**)&BQKV, g_bqkv);

    const int SM128 = 4 * (128 + 128) * 64;   // 65536
    const int SMFL  = 16384 + 2 * 16640;      // 49664
    cudaFuncSetAttribute(mma_gemm<128, 0>, cudaFuncAttributeMaxDynamicSharedMemorySize, SM128);
    cudaFuncSetAttribute(mma_gemm<128, 1>, cudaFuncAttributeMaxDynamicSharedMemorySize, SM128);
    cudaFuncSetAttribute(mma_gemm<128, 2>, cudaFuncAttributeMaxDynamicSharedMemorySize, SM128);
    cudaFuncSetAttribute(flash_k, cudaFuncAttributeMaxDynamicSharedMemorySize, SMFL);

    const dim3 t32(32, 8);

    // launch 1: x -> half
    f32_to_half_k<<<(NT * DM / 4 + 255) / 256, 256>>>(x, XH, NT * DM / 4);
    // launch 2: all weight transposes + bias concat
    prep_w_k<<<12288, t32>>>(Wq, Wk, Wv, Wo, W1, W2, WQKVT, WOT, W1T, W2T, bq, bk, bv, BQKV);
    // launch 3: fused QKV projection
    {
        dim3 g(3 * DM / 128, NT / 128, 1);
        mma_gemm<128, 1><<<g, 256, SM128>>>(XH, WQKVT, BQKV, (char*)QKV, DM, DM, DM, 3 * DM,
                                            0, 0, 0, 0, 0, 0, 1, 1.f);
    }
    // launch 4: flash attention (ncu capture target)
    flash_k<<<dim3(SEQ / 128, 64), 256, SMFL>>>(QKV, mask, CTX);
    // launch 5: attn_out = ctx @ Wo + bo
    {
        dim3 g(DM / 128, NT / 128, 1);
        mma_gemm<128, 0><<<g, 256, SM128>>>(CTX, WOT, bo, (char*)TMP, DM, DM, DM, DM,
                                            0, 0, 0, 0, 0, 0, 1, 1.f);
    }
    // launch 6: LN1
    addln_k<true><<<NT, 256>>>(x, TMP, g1, be1, H, HH);
    // launch 7: FFN1
    {
        dim3 g(DFF / 128, NT / 128, 1);
        mma_gemm<128, 2><<<g, 256, SM128>>>(HH, W1T, b1, (char*)FF, DM, DM, DM, DFF,
                                            0, 0, 0, 0, 0, 0, 1, 1.f);
    }
    // launch 8: FFN2
    {
        dim3 g(DM / 128, NT / 128, 1);
        mma_gemm<128, 0><<<g, 256, SM128>>>(FF, W2T, b2, (char*)TMP, DFF, DFF, DFF, DM,
                                            0, 0, 0, 0, 0, 0, 1, 1.f);
    }
    // launch 9: LN2
    addln_k<false><<<NT, 256>>>(H, TMP, g2, be2, out, nullptr);
}

// round 10
// speedup vs baseline: 7.1661x; 1.0794x over previous
#include <cuda_runtime.h>
#include <cuda_fp16.h>
#include <cstdint>

#define BATCH 4
#define SEQ   1024
#define NT    4096
#define DM    1024
#define NH    16
#define DKH   64
#define DFF   4096

// ======================= device scratch =======================
__device__ __align__(16) float g_tmp[(size_t)NT * DM];
__device__ __align__(16) float g_h[(size_t)NT * DM];
__device__ __align__(16) __half g_xh [(size_t)NT * DM];
__device__ __align__(16) __half g_qkv[(size_t)NT * 3 * DM];
__device__ __align__(16) __half g_ctx[(size_t)NT * DM];
__device__ __align__(16) __half g_WqkvT[(size_t)3 * DM * DM];
__device__ __align__(16) __half g_WoT[(size_t)DM * DM];
__device__ __align__(16) __half g_W1T[(size_t)DFF * DM];
__device__ __align__(16) __half g_W2T[(size_t)DM * DFF];
__device__ __align__(16) __half g_hh [(size_t)NT * DM];
__device__ __align__(16) __half g_ff [(size_t)NT * DFF];
__device__ __align__(16) float  g_bqkv[3 * DM];

// ======================= asm helpers (compute_80-level only) =======================
__device__ __forceinline__ uint32_t smem_u32(const void* p) {
    uint32_t a;
    asm("{ .reg .u64 t; cvta.to.shared.u64 t, %1; cvt.u32.u64 %0, t; }" : "=r"(a) : "l"(p));
    return a;
}
#define CP_ASYNC(s, g) \
    asm volatile("cp.async.cg.shared.global [%0], [%1], 16;" :: "r"(s), "l"(g) : "memory")
#define CP_COMMIT() asm volatile("cp.async.commit_group;" ::: "memory")
#define CP_WAIT(n)  asm volatile("cp.async.wait_group %0;" :: "n"(n) : "memory")

#define LDSM_X4(r0, r1, r2, r3, a) \
    asm volatile("ldmatrix.sync.aligned.m8n8.x4.shared.b16 {%0,%1,%2,%3}, [%4];" \
        : "=r"(r0), "=r"(r1), "=r"(r2), "=r"(r3) : "r"(a))

#define LDSM_X4_T(r0, r1, r2, r3, a) \
    asm volatile("ldmatrix.sync.aligned.m8n8.x4.trans.shared.b16 {%0,%1,%2,%3}, [%4];" \
        : "=r"(r0), "=r"(r1), "=r"(r2), "=r"(r3) : "r"(a))

#define MMA_F16(d, a, b) \
    asm volatile("mma.sync.aligned.m16n8k16.row.col.f32.f16.f16.f32 " \
        "{%0,%1,%2,%3}, {%4,%5,%6,%7}, {%8,%9}, {%0,%1,%2,%3};" \
        : "+f"((d)[0]), "+f"((d)[1]), "+f"((d)[2]), "+f"((d)[3]) \
        : "r"((a)[0]), "r"((a)[1]), "r"((a)[2]), "r"((a)[3]), "r"((b)[0]), "r"((b)[1]))

#define PACK_F16X2(r, flo, fhi) \
    asm("cvt.rn.f16x2.f32 %0, %1, %2;" : "=r"(r) : "f"(fhi), "f"(flo))

// 64B-row swizzle (flash kernel): phys(r+16,c)==phys(r,c)+1024.
__device__ __forceinline__ uint32_t phys(uint32_t r, uint32_t c) {
    return (r >> 1) * 128 + ((((r & 1) << 2) | c) ^ ((r >> 1) & 7)) * 16;
}
// 128B-row swizzle (GEMM): tile row r (128B), 16B-chunk c in [0,8).
__device__ __forceinline__ uint32_t phys128(uint32_t r, uint32_t c) {
    return r * 128 + ((c ^ (r & 7)) * 16);
}
__device__ __forceinline__ unsigned short hfu(float v) {
    return __half_as_ushort(__float2half_rn(v));
}

// ======================= mma.sync batched GEMM: BM=128, BN=128, BK=64, DEPTH=3 =======================
// C[M,N] = alpha*(A @ B^T) + bias. A:[M,K] half, B:[N,K] half row-major. K%64==0.
// OUT: 0=f32, 1=half, 2=relu half.
template<int OUT>
__global__ __launch_bounds__(256, 2)
void mma_gemm(const __half* __restrict__ A, const __half* __restrict__ B,
              const float* __restrict__ bias, char* __restrict__ Cptr,
              int K, int lda, int ldb, int ldc, float alpha)
{
    constexpr int DEPTH  = 3;
    constexpr int ABYTES = 128 * 128;       // 16 KB
    constexpr int STAGE  = 2 * ABYTES;      // 32 KB
    constexpr int NTL    = 8;               // warp: 32 rows x 64 cols

    extern __shared__ char sm[];
    const uint32_t smb = smem_u32(sm);

    const int tid = threadIdx.x;
    const int wid = tid >> 5, lane = tid & 31;
    const int wRow = (wid & 3) * 32;
    const int wCol = (wid >> 2) * 64;
    const int row0 = blockIdx.y * 128;
    const int col0 = blockIdx.x * 128;

    // ---- cp.async src/dst (4 iters per operand: 128 rows x 8 chunks / 256 thr) ----
    const __half* Ag[4]; const __half* Bg[4]; uint32_t Asm[4], Bsm[4];
#pragma unroll
    for (int i = 0; i < 4; i++) {
        int idx = tid + i * 256;
        int r = idx >> 3, c = idx & 7;
        Ag[i]  = A + (size_t)(row0 + r) * lda + c * 8;
        Bg[i]  = B + (size_t)(col0 + r) * ldb + c * 8;
        Asm[i] = phys128(r, c);
        Bsm[i] = ABYTES + phys128(r, c);
    }

    // ---- ldmatrix address bases ----
    const uint32_t ra0 = (uint32_t)(wRow + (lane & 15)) * 128;       // A row base (mt adds 2048)
    const uint32_t rmA = (uint32_t)(lane & 15) & 7;
    const uint32_t sA  = lane >> 4;
    const uint32_t rb0 = (uint32_t)(wCol + ((lane >> 4) << 3) + (lane & 7)) * 128;  // B (np adds 2048)
    const uint32_t rmB = (uint32_t)lane & 7;
    const uint32_t sB  = (lane >> 3) & 1;

    float acc[2][NTL][4];
#pragma unroll
    for (int i = 0; i < 2; i++)
#pragma unroll
        for (int j = 0; j < NTL; j++)
#pragma unroll
            for (int k = 0; k < 4; k++) acc[i][j][k] = 0.f;

    const int NC = K / 64;
    const int PRE = NC < (DEPTH - 1) ? NC : (DEPTH - 1);
    for (int s = 0; s < PRE; s++) {
#pragma unroll
        for (int i = 0; i < 4; i++) {
            CP_ASYNC(smb + s * STAGE + Asm[i], Ag[i] + s * 64);
            CP_ASYNC(smb + s * STAGE + Bsm[i], Bg[i] + s * 64);
        }
        CP_COMMIT();
    }
    int idx = PRE;
    // modulo-3 stage tracker
    int stC = 0, stL = PRE % DEPTH;
    for (int cch = 0; cch < NC; cch++) {
        const int rem = NC - 1 - cch;
        if (rem >= 1) { CP_WAIT(1); } else { CP_WAIT(0); }
        __syncthreads();
        if (idx < NC) {
#pragma unroll
            for (int i = 0; i < 4; i++) {
                CP_ASYNC(smb + stL * STAGE + Asm[i], Ag[i] + idx * 64);
                CP_ASYNC(smb + stL * STAGE + Bsm[i], Bg[i] + idx * 64);
            }
            CP_COMMIT();
            idx++;
            stL = (stL + 1 == DEPTH) ? 0 : stL + 1;
        }
        const uint32_t sb = smb + stC * STAGE;
        stC = (stC + 1 == DEPTH) ? 0 : stC + 1;
#pragma unroll
        for (int kk = 0; kk < 4; kk++) {
            const uint32_t cA = ((2 * kk + sA) ^ rmA) * 16;
            const uint32_t cB = ((2 * kk + sB) ^ rmB) * 16;
            uint32_t a[2][4], b[NTL][2];
#pragma unroll
            for (int mt = 0; mt < 2; mt++)
                LDSM_X4(a[mt][0], a[mt][1], a[mt][2], a[mt][3],
                        sb + ra0 + mt * 2048 + cA);
#pragma unroll
            for (int np = 0; np < 4; np++)
                LDSM_X4(b[2 * np][0], b[2 * np][1], b[2 * np + 1][0], b[2 * np + 1][1],
                        sb + ABYTES + rb0 + np * 2048 + cB);
#pragma unroll
            for (int mt = 0; mt < 2; mt++)
#pragma unroll
                for (int nt = 0; nt < NTL; nt++)
                    MMA_F16(acc[mt][nt], a[mt], b[nt]);
        }
    }

    const int gid = lane >> 2, t4 = lane & 3;
#pragma unroll
    for (int mt = 0; mt < 2; mt++) {
        const int r1 = row0 + wRow + mt * 16 + gid;
        const long long ro1 = (long long)r1 * ldc;
        const long long ro2 = ro1 + 8LL * ldc;
#pragma unroll
        for (int nt = 0; nt < NTL; nt++) {
            const int cc = col0 + wCol + nt * 8 + t4 * 2;
            const float b0 = bias ? bias[cc] : 0.f;
            const float b1 = bias ? bias[cc + 1] : 0.f;
            float v0 = acc[mt][nt][0] * alpha + b0;
            float v1 = acc[mt][nt][1] * alpha + b1;
            float v2 = acc[mt][nt][2] * alpha + b0;
            float v3 = acc[mt][nt][3] * alpha + b1;
            if constexpr (OUT == 0) {
                float* C = (float*)Cptr;
                *(float2*)(C + ro1 + cc) = make_float2(v0, v1);
                *(float2*)(C + ro2 + cc) = make_float2(v2, v3);
            } else {
                if constexpr (OUT == 2) {
                    v0 = fmaxf(v0, 0.f); v1 = fmaxf(v1, 0.f);
                    v2 = fmaxf(v2, 0.f); v3 = fmaxf(v3, 0.f);
                }
                __half* C = (__half*)Cptr;
                ushort2 o1, o2;
                o1.x = hfu(v0); o1.y = hfu(v1);
                o2.x = hfu(v2); o2.y = hfu(v3);
                *(ushort2*)(C + ro1 + cc) = o1;
                *(ushort2*)(C + ro2 + cc) = o2;
            }
        }
    }
}

// ======================= flash attention (unchanged from R9) =======================
__global__ __launch_bounds__(256, 2)
void flash_k(const __half* __restrict__ QKV, const int* __restrict__ mask,
             __half* __restrict__ CTX)
{
    constexpr int QLD   = 3 * DM;
    constexpr int CH128 = 8192;
    constexpr int CH64  = 4096;
    constexpr int QOFF  = 0;
    constexpr int ST0   = 16384;
    constexpr int VOFF  = 8192;
    constexpr int MOFF  = 16384;
    constexpr int STSZ  = 16640;
    constexpr int NJ    = SEQ / 64;
    constexpr float SCL = 0.125f;
    constexpr float L2E = 1.44269504f;

    extern __shared__ char sm[];
    const uint32_t smb = smem_u32(sm);

    const int tid = threadIdx.x;
    const int wid = tid >> 5, lane = tid & 31;
    const int gid = lane >> 2, t4 = lane & 3;
    const int qb = blockIdx.x, z = blockIdx.y;
    const int b = z >> 4, h = z & 15;

    const int rr = tid >> 2, cc4 = tid & 3;
    const size_t qrow0 = (size_t)(b * SEQ + qb * 128);
    const __half* Qg  = QKV + (qrow0 + rr) * QLD + h * DKH + cc4 * 8;
    const __half* Kg0 = QKV + ((size_t)b * SEQ + rr) * QLD + DM + h * DKH + cc4 * 8;
    const __half* Vg0 = QKV + ((size_t)b * SEQ + rr) * QLD + 2 * DM + h * DKH + cc4 * 8;
    const uint32_t physrc = phys(rr, cc4);

    auto issue_stage = [&](int jb, int st) {
        const uint32_t sb = smb + ST0 + st * STSZ;
        const __half* kgb = Kg0 + (size_t)jb * 64 * QLD;
#pragma unroll
        for (int kc = 0; kc < 2; kc++)
            CP_ASYNC(sb + kc * CH64 + physrc, kgb + kc * 32);
        const __half* vgb = Vg0 + (size_t)jb * 64 * QLD;
#pragma unroll
        for (int kc = 0; kc < 2; kc++)
            CP_ASYNC(sb + VOFF + kc * CH64 + physrc, vgb + kc * 32);
        if (tid < 16)
            CP_ASYNC(sb + MOFF + tid * 16, mask + (size_t)b * SEQ + jb * 64 + tid * 4);
    };

#pragma unroll
    for (int kc = 0; kc < 2; kc++)
#pragma unroll
        for (int it = 0; it < 2; it++)
            CP_ASYNC(smb + QOFF + kc * CH128 + physrc + it * 32 * 128,
                     Qg + (size_t)it * 64 * QLD + kc * 32);
    issue_stage(0, 0);
    CP_COMMIT();
    issue_stage(1, 1);
    CP_COMMIT();
    CP_WAIT(1);
    __syncthreads();

    uint32_t qa[4][4];
    {
        const uint32_t qbase0 = phys(lane & 15, (lane >> 4)) + wid * 1024;
        const uint32_t qbase1 = phys(lane & 15, 2 + (lane >> 4)) + wid * 1024;
#pragma unroll
        for (int kc = 0; kc < 2; kc++) {
            LDSM_X4(qa[kc * 2][0], qa[kc * 2][1], qa[kc * 2][2], qa[kc * 2][3],
                    smb + QOFF + kc * CH128 + qbase0);
            LDSM_X4(qa[kc * 2 + 1][0], qa[kc * 2 + 1][1], qa[kc * 2 + 1][2], qa[kc * 2 + 1][3],
                    smb + QOFF + kc * CH128 + qbase1);
        }
    }

    const uint32_t bb0 = phys(((lane >> 4) << 3) + (lane & 7), ((lane >> 3) & 1));
    const uint32_t bb1 = phys(((lane >> 4) << 3) + (lane & 7), 2 + ((lane >> 3) & 1));
    const uint32_t vtb0 = phys(lane & 15, (lane >> 4));
    const uint32_t vtb1 = phys(lane & 15, 2 + (lane >> 4));

    float O[8][4];
#pragma unroll
    for (int i = 0; i < 8; i++)
#pragma unroll
        for (int j = 0; j < 4; j++) O[i][j] = 0.f;
    float m0 = -1e30f, m1 = -1e30f, l0 = 0.f, l1 = 0.f;

    for (int j = 0; j < NJ; j++) {
        const uint32_t sb = smb + ST0 + (j & 1) * STSZ;
        const int* msm = (const int*)(sm + ST0 + (j & 1) * STSZ + MOFF);

        float s[8][4];
#pragma unroll
        for (int i = 0; i < 8; i++)
#pragma unroll
            for (int k = 0; k < 4; k++) s[i][k] = 0.f;
#pragma unroll
        for (int kidx = 0; kidx < 4; kidx++) {
            const uint32_t cb = sb + (kidx >> 1) * CH64 + ((kidx & 1) ? bb1 : bb0);
#pragma unroll
            for (int np = 0; np < 4; np++) {
                uint32_t r0, r1, r2, r3;
                LDSM_X4(r0, r1, r2, r3, cb + np * 1024);
                uint32_t p0[2] = {r0, r1}, p1[2] = {r2, r3};
                MMA_F16(s[2 * np], qa[kidx], p0);
                MMA_F16(s[2 * np + 1], qa[kidx], p1);
            }
        }

        float mx0 = -1e30f, mx1 = -1e30f;
#pragma unroll
        for (int nt = 0; nt < 8; nt++) {
            const int c0 = nt * 8 + t4 * 2;
            const float a0 = msm[c0] ? 0.f : -1e9f;
            const float a1 = msm[c0 + 1] ? 0.f : -1e9f;
            s[nt][0] = s[nt][0] * SCL + a0;
            s[nt][1] = s[nt][1] * SCL + a1;
            s[nt][2] = s[nt][2] * SCL + a0;
            s[nt][3] = s[nt][3] * SCL + a1;
            mx0 = fmaxf(mx0, fmaxf(s[nt][0], s[nt][1]));
            mx1 = fmaxf(mx1, fmaxf(s[nt][2], s[nt][3]));
        }
        mx0 = fmaxf(mx0, __shfl_xor_sync(0xffffffffu, mx0, 1));
        mx0 = fmaxf(mx0, __shfl_xor_sync(0xffffffffu, mx0, 2));
        mx1 = fmaxf(mx1, __shfl_xor_sync(0xffffffffu, mx1, 1));
        mx1 = fmaxf(mx1, __shfl_xor_sync(0xffffffffu, mx1, 2));

        const float nm0 = fmaxf(m0, mx0), nm1 = fmaxf(m1, mx1);
        const float al0 = exp2f((m0 - nm0) * L2E), al1 = exp2f((m1 - nm1) * L2E);
        m0 = nm0; m1 = nm1;

        float sum0 = 0.f, sum1 = 0.f;
#pragma unroll
        for (int nt = 0; nt < 8; nt++) {
            s[nt][0] = exp2f((s[nt][0] - nm0) * L2E);
            s[nt][1] = exp2f((s[nt][1] - nm0) * L2E);
            s[nt][2] = exp2f((s[nt][2] - nm1) * L2E);
            s[nt][3] = exp2f((s[nt][3] - nm1) * L2E);
            sum0 += s[nt][0] + s[nt][1];
            sum1 += s[nt][2] + s[nt][3];
        }
        sum0 += __shfl_xor_sync(0xffffffffu, sum0, 1);
        sum0 += __shfl_xor_sync(0xffffffffu, sum0, 2);
        sum1 += __shfl_xor_sync(0xffffffffu, sum1, 1);
        sum1 += __shfl_xor_sync(0xffffffffu, sum1, 2);
        l0 = l0 * al0 + sum0;
        l1 = l1 * al1 + sum1;
#pragma unroll
        for (int i = 0; i < 8; i++) {
            O[i][0] *= al0; O[i][1] *= al0;
            O[i][2] *= al1; O[i][3] *= al1;
        }

#pragma unroll
        for (int kt = 0; kt < 4; kt++) {
            uint32_t pa[4];
            PACK_F16X2(pa[0], s[2 * kt][0], s[2 * kt][1]);
            PACK_F16X2(pa[1], s[2 * kt][2], s[2 * kt][3]);
            PACK_F16X2(pa[2], s[2 * kt + 1][0], s[2 * kt + 1][1]);
            PACK_F16X2(pa[3], s[2 * kt + 1][2], s[2 * kt + 1][3]);
#pragma unroll
            for (int np = 0; np < 4; np++) {
                uint32_t r0, r1, r2, r3;
                LDSM_X4_T(r0, r1, r2, r3,
                          sb + VOFF + (np >> 1) * CH64 + ((np & 1) ? vtb1 : vtb0) + kt * 1024);
                uint32_t p0[2] = {r0, r1}, p1[2] = {r2, r3};
                MMA_F16(O[2 * np], pa, p0);
                MMA_F16(O[2 * np + 1], pa, p1);
            }
        }

        __syncthreads();
        if (j + 2 < NJ) { issue_stage(j + 2, j & 1); CP_COMMIT(); CP_WAIT(1); }
        else if (j + 1 < NJ) { CP_WAIT(0); }
        __syncthreads();
    }

    const float inv0 = 1.f / l0, inv1 = 1.f / l1;
    const int q0 = qb * 128 + wid * 16 + gid;
    __half* C1 = CTX + ((size_t)(b * SEQ + q0)) * DM + h * DKH;
    __half* C2 = C1 + 8 * DM;
#pragma unroll
    for (int nt = 0; nt < 8; nt++) {
        const int cc = nt * 8 + t4 * 2;
        ushort2 o1, o2;
        o1.x = hfu(O[nt][0] * inv0); o1.y = hfu(O[nt][1] * inv0);
        o2.x = hfu(O[nt][2] * inv1); o2.y = hfu(O[nt][3] * inv1);
        *(ushort2*)(C1 + cc) = o1;
        *(ushort2*)(C2 + cc) = o2;
    }
}

// ======================= prologue kernels =======================
__global__ void f32_to_half_k(const float* __restrict__ in, __half* __restrict__ out, int n4)
{
    int i = blockIdx.x * 256 + threadIdx.x;
    if (i < n4) {
        float4 v = *(const float4*)(in + (size_t)i * 4);
        ushort4 o;
        o.x = hfu(v.x); o.y = hfu(v.y); o.z = hfu(v.z); o.w = hfu(v.w);
        *(ushort4*)(out + (size_t)i * 4) = o;
    }
}

// Weight transposes; base selects subrange so the launch can be split.
// global tile ids: [0,3072) Wq/Wk/Wv; [3072,4096) Wo; [4096,8192) W1; [8192,12288) W2.
__global__ void prep_w_k(const float* __restrict__ Wq, const float* __restrict__ Wk,
                         const float* __restrict__ Wv, const float* __restrict__ Wo,
                         const float* __restrict__ W1, const float* __restrict__ W2,
                         __half* __restrict__ WQKVT, __half* __restrict__ WOT,
                         __half* __restrict__ W1T, __half* __restrict__ W2T,
                         const float* __restrict__ bq, const float* __restrict__ bk,
                         const float* __restrict__ bv, float* __restrict__ BQKV, int base)
{
    __shared__ float t[32][33];
    const int idx = base + blockIdx.x;
    const int tx = threadIdx.x, ty = threadIdx.y;
    const int lt = ty * 32 + tx;

    if (idx == 0) {
        for (int i = lt; i < DM; i += 256) {
            BQKV[i] = bq[i];
            BQKV[i + DM] = bk[i];
            BQKV[i + 2 * DM] = bv[i];
        }
    }

    const float* in;
    __half* out;
    int K, N, n0, k0;
    if (idx < 4096) {
        const int w = idx >> 10, tile = idx & 1023;
        in = (w == 0) ? Wq : (w == 1) ? Wk : (w == 2) ? Wv : Wo;
        out = (w == 3) ? WOT : WQKVT + (size_t)w * DM * DM;
        K = DM; N = DM;
        n0 = (tile & 31) * 32; k0 = (tile >> 5) * 32;
    } else if (idx < 8192) {
        const int tile = idx - 4096;
        in = W1; out = W1T; K = DM; N = DFF;
        n0 = (tile & 127) * 32; k0 = (tile >> 7) * 32;
    } else {
        const int tile = idx - 8192;
        in = W2; out = W2T; K = DFF; N = DM;
        n0 = (tile & 31) * 32; k0 = (tile >> 5) * 32;
    }

    for (int j = ty; j < 32; j += 8) t[j][tx] = in[(size_t)(k0 + j) * N + n0 + tx];
    __syncthreads();
    for (int j = ty; j < 32; j += 8)
        out[(size_t)(n0 + j) * K + k0 + tx] = __float2half_rn(t[tx][j]);
}

// ======================= reductions / LN =======================
__device__ __forceinline__ float blkSum(float v, float* red)
{
#pragma unroll
    for (int o = 16; o > 0; o >>= 1) v += __shfl_xor_sync(0xffffffffu, v, o);
    int w = threadIdx.x >> 5, l = threadIdx.x & 31;
    if (l == 0) red[w] = v;
    __syncthreads();
    if (threadIdx.x < 8) {
        v = red[threadIdx.x];
#pragma unroll
        for (int o = 4; o > 0; o >>= 1) v += __shfl_xor_sync(0xffu, v, o);
        if (threadIdx.x == 0) red[0] = v;
    }
    __syncthreads();
    float r = red[0];
    __syncthreads();
    return r;
}

template<bool EMIT_H>
__global__ void addln_k(const float* __restrict__ a, const float* __restrict__ bres,
                        const float* __restrict__ g, const float* __restrict__ be,
                        float* __restrict__ out, __half* __restrict__ outh)
{
    __shared__ float red[32];
    const long long row = blockIdx.x;
    const float* pa = a + row * DM;
    const float* pb = bres + row * DM;
    const int tid = threadIdx.x;
    float v[4], s = 0.f, s2 = 0.f;
#pragma unroll
    for (int j = 0; j < 4; j++) {
        int c = tid + j * 256;
        float t = pa[c] + pb[c];
        v[j] = t; s += t; s2 += t * t;
    }
    s = blkSum(s, red);
    s2 = blkSum(s2, red);
    float mu = s * (1.f / DM);
    float var = s2 * (1.f / DM) - mu * mu;
    float inv = rsqrtf(var + 1e-5f);
#pragma unroll
    for (int j = 0; j < 4; j++) {
        int c = tid + j * 256;
        float o = (v[j] - mu) * inv * g[c] + be[c];
        out[row * DM + c] = o;
        if (EMIT_H) outh[row * DM + c] = __float2half_rn(o);
    }
}

// ======================= launch =======================
extern "C" void kernel_launch(void* const* d_in, const int* in_sizes, int n_in,
                              void* d_out, int out_size)
{
    const float* x    = (const float*)d_in[0];
    const int*   mask = (const int*)  d_in[1];
    const float* Wq = (const float*)d_in[2];  const float* bq = (const float*)d_in[3];
    const float* Wk = (const float*)d_in[4];  const float* bk = (const float*)d_in[5];
    const float* Wv = (const float*)d_in[6];  const float* bv = (const float*)d_in[7];
    const float* Wo = (const float*)d_in[8];  const float* bo = (const float*)d_in[9];
    const float* W1 = (const float*)d_in[10]; const float* b1 = (const float*)d_in[11];
    const float* W2 = (const float*)d_in[12]; const float* b2 = (const float*)d_in[13];
    const float* g1 = (const float*)d_in[14]; const float* be1 = (const float*)d_in[15];
    const float* g2 = (const float*)d_in[16]; const float* be2 = (const float*)d_in[17];
    float* out = (float*)d_out;

    float *TMP, *H, *BQKV;
    __half *XH, *QKV, *CTX, *WQKVT, *WOT, *W1T, *W2T, *HH, *FF;
    cudaGetSymbolAddress((void**)&TMP, g_tmp);
    cudaGetSymbolAddress((void**)&H, g_h);
    cudaGetSymbolAddress((void**)&XH, g_xh);
    cudaGetSymbolAddress((void**)&QKV, g_qkv);
    cudaGetSymbolAddress((void**)&CTX, g_ctx);
    cudaGetSymbolAddress((void**)&WQKVT, g_WqkvT);
    cudaGetSymbolAddress((void**)&WOT, g_WoT);
    cudaGetSymbolAddress((void**)&W1T, g_W1T);
    cudaGetSymbolAddress((void**)&W2T, g_W2T);
    cudaGetSymbolAddress((void**)&HH, g_hh);
    cudaGetSymbolAddress((void**)&FF, g_ff);
    cudaGetSymbolAddress((void**)&BQKV, g_bqkv);

    const int SMGM = 3 * 32 * 1024;           // 98304
    const int SMFL = 16384 + 2 * 16640;       // 49664
    cudaFuncSetAttribute(mma_gemm<0>, cudaFuncAttributeMaxDynamicSharedMemorySize, SMGM);
    cudaFuncSetAttribute(mma_gemm<1>, cudaFuncAttributeMaxDynamicSharedMemorySize, SMGM);
    cudaFuncSetAttribute(mma_gemm<2>, cudaFuncAttributeMaxDynamicSharedMemorySize, SMGM);
    cudaFuncSetAttribute(flash_k, cudaFuncAttributeMaxDynamicSharedMemorySize, SMFL);

    const dim3 t32(32, 8);

    // launch 1: x -> half
    f32_to_half_k<<<(NT * DM / 4 + 255) / 256, 256>>>(x, XH, NT * DM / 4);
    // launch 2: Wq/Wk/Wv transposes + bias concat (tiles [0,3072))
    prep_w_k<<<3072, t32>>>(Wq, Wk, Wv, Wo, W1, W2, WQKVT, WOT, W1T, W2T, bq, bk, bv, BQKV, 0);
    // launch 3: Wo/W1/W2 transposes (tiles [3072,12288))
    prep_w_k<<<9216, t32>>>(Wq, Wk, Wv, Wo, W1, W2, WQKVT, WOT, W1T, W2T, bq, bk, bv, BQKV, 3072);
    // launch 4: fused QKV projection (ncu capture target)
    {
        dim3 g(3 * DM / 128, NT / 128, 1);
        mma_gemm<1><<<g, 256, SMGM>>>(XH, WQKVT, BQKV, (char*)QKV, DM, DM, DM, 3 * DM, 1.f);
    }
    // launch 5: flash attention
    flash_k<<<dim3(SEQ / 128, 64), 256, SMFL>>>(QKV, mask, CTX);
    // launch 6: attn_out = ctx @ Wo + bo
    {
        dim3 g(DM / 128, NT / 128, 1);
        mma_gemm<0><<<g, 256, SMGM>>>(CTX, WOT, bo, (char*)TMP, DM, DM, DM, DM, 1.f);
    }
    // launch 7: LN1
    addln_k<true><<<NT, 256>>>(x, TMP, g1, be1, H, HH);
    // launch 8: FFN1
    {
        dim3 g(DFF / 128, NT / 128, 1);
        mma_gemm<2><<<g, 256, SMGM>>>(HH, W1T, b1, (char*)FF, DM, DM, DM, DFF, 1.f);
    }
    // launch 9: FFN2
    {
        dim3 g(DM / 128, NT / 128, 1);
        mma_gemm<0><<<g, 256, SMGM>>>(FF, W2T, b2, (char*)TMP, DFF, DFF, DFF, DM, 1.f);
    }
    // launch 10: LN2
    addln_k<false><<<NT, 256>>>(H, TMP, g2, be2, out, nullptr);
}